// round 4
// baseline (speedup 1.0000x reference)
#include <cuda_runtime.h>
#include <cuda_bf16.h>
#include <cstdint>

#define NB 8
#define NL 2048
#define NE 256
#define NH 4
#define ND 64

// ---------------- scratch (device globals; no allocation allowed) -----------
__device__ float g_QK [(size_t)NB * NL * 2 * NE];   // [16384, 512]  (q | k)
__device__ float g_Bm [(size_t)NB * NL * NL];       // [8, 2048, 2048]
__device__ float g_AG [(size_t)NB * NL * NE];       // [16384, 256]
__device__ float g_xT [(size_t)NB * NE * NL];       // [8][256][2048]
__device__ float g_WgT[(size_t)NE * NE];            // [256, 256]
__device__ float g_xr [(size_t)NB * NL * NE];       // tf32-rounded x
__device__ float g_wr [(size_t)2 * NE * NE];        // tf32-rounded w[0:512]
__device__ float g_inv[(size_t)NB * NH * NL];       // 0.25 / rowsum  [32][2048]

// ------------------------------- helpers ------------------------------------
__device__ __forceinline__ uint32_t smem_u32(const void* p) {
    uint32_t a;
    asm("{ .reg .u64 t; cvta.to.shared.u64 t, %1; cvt.u32.u64 %0, t; }"
        : "=r"(a) : "l"(p));
    return a;
}

__device__ __forceinline__ float rtf32(float x) {
    uint32_t u;
    asm("cvt.rna.tf32.f32 %0, %1;" : "=r"(u) : "f"(x));
    return __uint_as_float(u);
}

#define CP_ASYNC16(dst, src) \
    asm volatile("cp.async.cg.shared.global [%0], [%1], 16;" \
                 :: "r"(dst), "l"(src) : "memory")
#define CP_COMMIT() asm volatile("cp.async.commit_group;" ::: "memory")
#define CP_WAIT(n)  asm volatile("cp.async.wait_group %0;" :: "n"(n) : "memory")

#define MMA_TF32(d, a, b)                                                      \
    asm volatile("mma.sync.aligned.m16n8k8.row.col.f32.tf32.tf32.f32 "         \
        "{%0,%1,%2,%3}, {%4,%5,%6,%7}, {%8,%9}, {%0,%1,%2,%3};"                \
        : "+f"((d)[0]), "+f"((d)[1]), "+f"((d)[2]), "+f"((d)[3])               \
        : "r"((a)[0]), "r"((a)[1]), "r"((a)[2]), "r"((a)[3]),                  \
          "r"((b)[0]), "r"((b)[1]))

// ------------------------------- mma GEMM -----------------------------------
// C[z] = alpha * A_z * B_z^T (+ bias[col]).  A [M,K], B [N,K], both K-major,
// tf32-rounded fp32.  CTA tile 128x128, K chunk 32, 8 warps, warp tile 64x32.
#define STG_FLOATS 9216
#define STG_BYTES  36864
#define GEMM_SMEM  (2 * STG_BYTES)

template <bool ROUND_OUT, bool HAS_BIAS>
__global__ __launch_bounds__(256, 2)
void mma_gemm(const float* __restrict__ A, int lda, int a_zo_row, int a_zi_col, int a_col_base,
              const float* __restrict__ Bp, int ldb, int b_zo_row, int b_zi_col, int b_col_base,
              float* __restrict__ C, int ldc, long sC,
              int inner, int nk, float alpha, const float* __restrict__ bias)
{
    extern __shared__ __align__(16) float smem[];
    const int tid    = threadIdx.x;
    const int warpId = tid >> 5;
    const int lane   = tid & 31;
    const int g  = lane >> 2;
    const int tg = lane & 3;
    const int wr = (warpId & 1) * 64;
    const int wc = (warpId >> 1) * 32;

    const int z  = blockIdx.z;
    const int zo = z / inner;
    const int zi = z - zo * inner;

    const float* Ag = A  + ((long)zo * a_zo_row + (long)blockIdx.y * 128) * lda
                         + a_col_base + zi * a_zi_col;
    const float* Bg = Bp + ((long)zo * b_zo_row + (long)blockIdx.x * 128) * ldb
                         + b_col_base + zi * b_zi_col;

    const uint32_t sbase = smem_u32(smem);

    auto load_stage = [&](int st, int kc) {
        const uint32_t da = sbase + st * STG_BYTES;
        const float* a = Ag + kc * 32;
        const float* b = Bg + kc * 32;
#pragma unroll
        for (int i = 0; i < 4; i++) {
            const int idx = tid + 256 * i;
            const int row = idx >> 3, c4 = idx & 7;
            CP_ASYNC16(da + row * 144 + c4 * 16, a + (long)row * lda + c4 * 4);
        }
#pragma unroll
        for (int i = 0; i < 4; i++) {
            const int idx = tid + 256 * i;
            const int row = idx >> 3, c4 = idx & 7;
            CP_ASYNC16(da + 18432 + row * 144 + c4 * 16, b + (long)row * ldb + c4 * 4);
        }
    };

    float acc[4][4][4];
#pragma unroll
    for (int m = 0; m < 4; m++)
#pragma unroll
        for (int n = 0; n < 4; n++)
#pragma unroll
            for (int c = 0; c < 4; c++) acc[m][n][c] = 0.f;

    load_stage(0, 0);
    CP_COMMIT();

    for (int i = 0; i < nk; i++) {
        if (i + 1 < nk) {
            load_stage((i + 1) & 1, i + 1);
            CP_COMMIT();
            CP_WAIT(1);
        } else {
            CP_WAIT(0);
        }
        __syncthreads();

        const uint32_t* As = (const uint32_t*)(smem + (i & 1) * STG_FLOATS);
        const uint32_t* Bs = As + 4608;

#pragma unroll
        for (int j = 0; j < 4; j++) {
            uint32_t af[4][4], bf[4][2];
#pragma unroll
            for (int mt = 0; mt < 4; mt++) {
                const int r0 = wr + mt * 16 + g;
                af[mt][0] = As[ r0      * 36 + j * 8 + tg    ];
                af[mt][1] = As[(r0 + 8) * 36 + j * 8 + tg    ];
                af[mt][2] = As[ r0      * 36 + j * 8 + tg + 4];
                af[mt][3] = As[(r0 + 8) * 36 + j * 8 + tg + 4];
            }
#pragma unroll
            for (int nt = 0; nt < 4; nt++) {
                const int r0 = wc + nt * 8 + g;
                bf[nt][0] = Bs[r0 * 36 + j * 8 + tg    ];
                bf[nt][1] = Bs[r0 * 36 + j * 8 + tg + 4];
            }
#pragma unroll
            for (int mt = 0; mt < 4; mt++)
#pragma unroll
                for (int nt = 0; nt < 4; nt++)
                    MMA_TF32(acc[mt][nt], af[mt], bf[nt]);
        }
        __syncthreads();
    }

    float* Cz = C + (long)z * sC;
    const long crow0 = (long)blockIdx.y * 128;
    const int  ccol0 = blockIdx.x * 128;

#pragma unroll
    for (int mt = 0; mt < 4; mt++) {
#pragma unroll
        for (int nt = 0; nt < 4; nt++) {
            const long r = crow0 + wr + mt * 16 + g;
            const int  c = ccol0 + wc + nt * 8 + tg * 2;
            float b0 = 0.f, b1 = 0.f;
            if (HAS_BIAS) { b0 = bias[c]; b1 = bias[c + 1]; }
            float v00 = acc[mt][nt][0] * alpha + b0;
            float v01 = acc[mt][nt][1] * alpha + b1;
            float v10 = acc[mt][nt][2] * alpha + b0;
            float v11 = acc[mt][nt][3] * alpha + b1;
            if (ROUND_OUT) {
                v00 = rtf32(v00); v01 = rtf32(v01);
                v10 = rtf32(v10); v11 = rtf32(v11);
            }
            *(float2*)(Cz +  r      * ldc + c) = make_float2(v00, v01);
            *(float2*)(Cz + (r + 8) * ldc + c) = make_float2(v10, v11);
        }
    }
}

// ---------------------------------------------------------------------------
// rowsum kernel: inv[b,h,i] = 0.25 / sum_j exp(0.125 * q_h[i] . k_h[j])
// One CTA per (i-tile, b*h). Q tile persistent in smem; K tiles double-buffered.
// Tile layout: 128 rows x 64 K floats, row stride 68 (bank-conflict-free frags).
#define RS_TILE_F   (128 * 68)
#define RS_SMEM     ((3 * RS_TILE_F + 128) * 4)

__global__ __launch_bounds__(256, 2)
void rowsum_kernel(const float* __restrict__ QK, float* __restrict__ inv)
{
    extern __shared__ __align__(16) float sm[];
    float* Qs   = sm;
    float* Ks   = sm + RS_TILE_F;          // [2][RS_TILE_F]
    float* srow = sm + 3 * RS_TILE_F;      // [128]

    const int tid  = threadIdx.x;
    const int bh   = blockIdx.y;
    const int b    = bh >> 2, h = bh & 3;
    const int i0   = blockIdx.x * 128;
    const int warpId = tid >> 5;
    const int lane   = tid & 31;
    const int g  = lane >> 2;
    const int tg = lane & 3;
    const int wr = (warpId & 1) * 64;
    const int wc = (warpId >> 1) * 32;

    const float* Qg = QK + ((long)b * NL + i0) * 512 + h * 64;
    const float* Kg = QK + ((long)b * NL) * 512 + 256 + h * 64;
    const uint32_t sQ = smem_u32(Qs);
    const uint32_t sK = smem_u32(Ks);

    if (tid < 128) srow[tid] = 0.f;

    // Q tile + K tile 0 (one cp.async group)
#pragma unroll
    for (int i = 0; i < 8; i++) {
        const int idx = tid + 256 * i;
        const int row = idx >> 4, c4 = idx & 15;
        CP_ASYNC16(sQ + row * 272 + c4 * 16, Qg + (long)row * 512 + c4 * 4);
    }
    {
#pragma unroll
        for (int i = 0; i < 8; i++) {
            const int idx = tid + 256 * i;
            const int row = idx >> 4, c4 = idx & 15;
            CP_ASYNC16(sK + row * 272 + c4 * 16, Kg + (long)row * 512 + c4 * 4);
        }
    }
    CP_COMMIT();

    float partial[4][2] = {{0,0},{0,0},{0,0},{0,0}};

    for (int jt = 0; jt < 16; jt++) {
        if (jt + 1 < 16) {
            const uint32_t dst = sK + ((jt + 1) & 1) * (RS_TILE_F * 4);
            const float* kg = Kg + (long)((jt + 1) * 128) * 512;
#pragma unroll
            for (int i = 0; i < 8; i++) {
                const int idx = tid + 256 * i;
                const int row = idx >> 4, c4 = idx & 15;
                CP_ASYNC16(dst + row * 272 + c4 * 16, kg + (long)row * 512 + c4 * 4);
            }
            CP_COMMIT();
            CP_WAIT(1);
        } else {
            CP_WAIT(0);
        }
        __syncthreads();

        const uint32_t* As = (const uint32_t*)Qs;
        const uint32_t* Bs = (const uint32_t*)(Ks + (jt & 1) * RS_TILE_F);

        float acc[4][4][4];
#pragma unroll
        for (int m = 0; m < 4; m++)
#pragma unroll
            for (int n = 0; n < 4; n++)
#pragma unroll
                for (int c = 0; c < 4; c++) acc[m][n][c] = 0.f;

#pragma unroll
        for (int cchunk = 0; cchunk < 2; cchunk++) {
#pragma unroll
            for (int j = 0; j < 4; j++) {
                const int off = cchunk * 32 + j * 8;
                uint32_t af[4][4], bf[4][2];
#pragma unroll
                for (int mt = 0; mt < 4; mt++) {
                    const int r0 = wr + mt * 16 + g;
                    af[mt][0] = As[ r0      * 68 + off + tg    ];
                    af[mt][1] = As[(r0 + 8) * 68 + off + tg    ];
                    af[mt][2] = As[ r0      * 68 + off + tg + 4];
                    af[mt][3] = As[(r0 + 8) * 68 + off + tg + 4];
                }
#pragma unroll
                for (int nt = 0; nt < 4; nt++) {
                    const int r0 = wc + nt * 8 + g;
                    bf[nt][0] = Bs[r0 * 68 + off + tg    ];
                    bf[nt][1] = Bs[r0 * 68 + off + tg + 4];
                }
#pragma unroll
                for (int mt = 0; mt < 4; mt++)
#pragma unroll
                    for (int nt = 0; nt < 4; nt++)
                        MMA_TF32(acc[mt][nt], af[mt], bf[nt]);
            }
        }

#pragma unroll
        for (int mt = 0; mt < 4; mt++)
#pragma unroll
            for (int nt = 0; nt < 4; nt++) {
                partial[mt][0] += __expf(acc[mt][nt][0] * 0.125f)
                                + __expf(acc[mt][nt][1] * 0.125f);
                partial[mt][1] += __expf(acc[mt][nt][2] * 0.125f)
                                + __expf(acc[mt][nt][3] * 0.125f);
            }
        __syncthreads();
    }

    // reduce over quad (tg), then across warps via smem atomics
#pragma unroll
    for (int mt = 0; mt < 4; mt++)
#pragma unroll
        for (int hh = 0; hh < 2; hh++) {
            float v = partial[mt][hh];
            v += __shfl_xor_sync(0xffffffffu, v, 1);
            v += __shfl_xor_sync(0xffffffffu, v, 2);
            partial[mt][hh] = v;
        }
    if (tg == 0) {
#pragma unroll
        for (int mt = 0; mt < 4; mt++) {
            atomicAdd(&srow[wr + mt * 16 + g],     partial[mt][0]);
            atomicAdd(&srow[wr + mt * 16 + g + 8], partial[mt][1]);
        }
    }
    __syncthreads();
    if (tid < 128)
        inv[((long)bh << 11) + i0 + tid] = 0.25f / srow[tid];
}

// ---------------------------------------------------------------------------
// bm kernel: Bm[b, i, j] = sum_h exp(0.125 * q_h[i].k_h[j]) * inv[b,h,i]
// One CTA per (j-tile, i-tile, b). Heads looped; Q/K tiles double-buffered
// per head; head-sum kept in a second register accumulator set.
#define BM_SMEM (4 * RS_TILE_F * 4)

__global__ __launch_bounds__(256, 1)
void bm_kernel(const float* __restrict__ QK, const float* __restrict__ inv,
               float* __restrict__ Bm)
{
    extern __shared__ __align__(16) float sm[];
    const int tid = threadIdx.x;
    const int b  = blockIdx.z;
    const int i0 = blockIdx.y * 128;
    const int j0 = blockIdx.x * 128;
    const int warpId = tid >> 5;
    const int lane   = tid & 31;
    const int g  = lane >> 2;
    const int tg = lane & 3;
    const int wr = (warpId & 1) * 64;
    const int wc = (warpId >> 1) * 32;

    const uint32_t sbase = smem_u32(sm);

    auto loadH = [&](int h) {
        const uint32_t dst = sbase + (h & 1) * (2 * RS_TILE_F * 4);
        const float* qg = QK + ((long)b * NL + i0) * 512 + h * 64;
        const float* kg = QK + ((long)b * NL + j0) * 512 + 256 + h * 64;
#pragma unroll
        for (int i = 0; i < 8; i++) {
            const int idx = tid + 256 * i;
            const int row = idx >> 4, c4 = idx & 15;
            CP_ASYNC16(dst + row * 272 + c4 * 16, qg + (long)row * 512 + c4 * 4);
        }
#pragma unroll
        for (int i = 0; i < 8; i++) {
            const int idx = tid + 256 * i;
            const int row = idx >> 4, c4 = idx & 15;
            CP_ASYNC16(dst + RS_TILE_F * 4 + row * 272 + c4 * 16,
                       kg + (long)row * 512 + c4 * 4);
        }
    };

    loadH(0);
    CP_COMMIT();

    float Psum[4][4][4];
#pragma unroll
    for (int m = 0; m < 4; m++)
#pragma unroll
        for (int n = 0; n < 4; n++)
#pragma unroll
            for (int c = 0; c < 4; c++) Psum[m][n][c] = 0.f;

    for (int h = 0; h < NH; h++) {
        if (h + 1 < NH) {
            loadH(h + 1);
            CP_COMMIT();
            CP_WAIT(1);
        } else {
            CP_WAIT(0);
        }
        __syncthreads();

        const uint32_t* As = (const uint32_t*)(sm + (h & 1) * 2 * RS_TILE_F);
        const uint32_t* Bs = As + RS_TILE_F;

        float acc[4][4][4];
#pragma unroll
        for (int m = 0; m < 4; m++)
#pragma unroll
            for (int n = 0; n < 4; n++)
#pragma unroll
                for (int c = 0; c < 4; c++) acc[m][n][c] = 0.f;

#pragma unroll
        for (int cchunk = 0; cchunk < 2; cchunk++) {
#pragma unroll
            for (int j = 0; j < 4; j++) {
                const int off = cchunk * 32 + j * 8;
                uint32_t af[4][4], bf[4][2];
#pragma unroll
                for (int mt = 0; mt < 4; mt++) {
                    const int r0 = wr + mt * 16 + g;
                    af[mt][0] = As[ r0      * 68 + off + tg    ];
                    af[mt][1] = As[(r0 + 8) * 68 + off + tg    ];
                    af[mt][2] = As[ r0      * 68 + off + tg + 4];
                    af[mt][3] = As[(r0 + 8) * 68 + off + tg + 4];
                }
#pragma unroll
                for (int nt = 0; nt < 4; nt++) {
                    const int r0 = wc + nt * 8 + g;
                    bf[nt][0] = Bs[r0 * 68 + off + tg    ];
                    bf[nt][1] = Bs[r0 * 68 + off + tg + 4];
                }
#pragma unroll
                for (int mt = 0; mt < 4; mt++)
#pragma unroll
                    for (int nt = 0; nt < 4; nt++)
                        MMA_TF32(acc[mt][nt], af[mt], bf[nt]);
            }
        }

        const float* invh = inv + (((long)(b * NH + h)) << 11) + i0;
        float inva[4], invb[4];
#pragma unroll
        for (int mt = 0; mt < 4; mt++) {
            inva[mt] = __ldg(&invh[wr + mt * 16 + g]);
            invb[mt] = __ldg(&invh[wr + mt * 16 + g + 8]);
        }
#pragma unroll
        for (int mt = 0; mt < 4; mt++)
#pragma unroll
            for (int nt = 0; nt < 4; nt++) {
                Psum[mt][nt][0] += __expf(acc[mt][nt][0] * 0.125f) * inva[mt];
                Psum[mt][nt][1] += __expf(acc[mt][nt][1] * 0.125f) * inva[mt];
                Psum[mt][nt][2] += __expf(acc[mt][nt][2] * 0.125f) * invb[mt];
                Psum[mt][nt][3] += __expf(acc[mt][nt][3] * 0.125f) * invb[mt];
            }
        __syncthreads();
    }

    float* Cz = Bm + (long)b * NL * NL;
#pragma unroll
    for (int mt = 0; mt < 4; mt++) {
#pragma unroll
        for (int nt = 0; nt < 4; nt++) {
            const long r = i0 + wr + mt * 16 + g;
            const int  c = j0 + wc + nt * 8 + tg * 2;
            float2 v0 = make_float2(rtf32(Psum[mt][nt][0]), rtf32(Psum[mt][nt][1]));
            float2 v1 = make_float2(rtf32(Psum[mt][nt][2]), rtf32(Psum[mt][nt][3]));
            *(float2*)(Cz +  r      * NL + c) = v0;
            *(float2*)(Cz + (r + 8) * NL + c) = v1;
        }
    }
}

// ---------------------------------------------------------------------------
__global__ void round_copy(const float4* __restrict__ in, float4* __restrict__ out, int n4)
{
    const int i = blockIdx.x * blockDim.x + threadIdx.x;
    if (i < n4) {
        float4 v = in[i];
        v.x = rtf32(v.x); v.y = rtf32(v.y); v.z = rtf32(v.z); v.w = rtf32(v.w);
        out[i] = v;
    }
}

__global__ void transpose_round(const float* __restrict__ in, float* __restrict__ out,
                                int R, int Cn)
{
    __shared__ float t[32][33];
    in  += (size_t)blockIdx.z * R * Cn;
    out += (size_t)blockIdx.z * R * Cn;
    const int r0 = blockIdx.y * 32, c0 = blockIdx.x * 32;
    const int x = threadIdx.x, y = threadIdx.y;
#pragma unroll
    for (int i = 0; i < 32; i += 8)
        t[y + i][x] = in[(long)(r0 + y + i) * Cn + c0 + x];
    __syncthreads();
#pragma unroll
    for (int i = 0; i < 32; i += 8)
        out[(long)(c0 + y + i) * R + r0 + x] = rtf32(t[x][y + i]);
}

// ---------------------------------------------------------------------------
extern "C" void kernel_launch(void* const* d_in, const int* in_sizes, int n_in,
                              void* d_out, int out_size)
{
    (void)in_sizes; (void)n_in; (void)out_size;
    const float* x   = (const float*)d_in[0];
    const float* w   = (const float*)d_in[1];
    const float* bia = (const float*)d_in[2];
    const float* Wg  = (const float*)d_in[3];
    const float* Bg  = (const float*)d_in[4];
    float* out = (float*)d_out;

    float *QK, *Bm, *AG, *xT, *WgT, *xr, *wr, *inv;
    cudaGetSymbolAddress((void**)&QK,  g_QK);
    cudaGetSymbolAddress((void**)&Bm,  g_Bm);
    cudaGetSymbolAddress((void**)&AG,  g_AG);
    cudaGetSymbolAddress((void**)&xT,  g_xT);
    cudaGetSymbolAddress((void**)&WgT, g_WgT);
    cudaGetSymbolAddress((void**)&xr,  g_xr);
    cudaGetSymbolAddress((void**)&wr,  g_wr);
    cudaGetSymbolAddress((void**)&inv, g_inv);

    cudaFuncSetAttribute(mma_gemm<true,  true >, cudaFuncAttributeMaxDynamicSharedMemorySize, GEMM_SMEM);
    cudaFuncSetAttribute(mma_gemm<true,  false>, cudaFuncAttributeMaxDynamicSharedMemorySize, GEMM_SMEM);
    cudaFuncSetAttribute(mma_gemm<false, true >, cudaFuncAttributeMaxDynamicSharedMemorySize, GEMM_SMEM);
    cudaFuncSetAttribute(rowsum_kernel, cudaFuncAttributeMaxDynamicSharedMemorySize, RS_SMEM);
    cudaFuncSetAttribute(bm_kernel,     cudaFuncAttributeMaxDynamicSharedMemorySize, BM_SMEM);

    // 0) tf32-rounded operand prep
    {
        const int n4x = (NB * NL * NE) / 4;
        round_copy<<<(n4x + 255) / 256, 256>>>((const float4*)x, (float4*)xr, n4x);
        const int n4w = (2 * NE * NE) / 4;
        round_copy<<<(n4w + 255) / 256, 256>>>((const float4*)w, (float4*)wr, n4w);
        transpose_round<<<dim3(NE / 32, NL / 32, NB), dim3(32, 8)>>>(x, xT, NL, NE);
        transpose_round<<<dim3(NE / 32, NE / 32, 1), dim3(32, 8)>>>(Wg, WgT, NE, NE);
    }

    // 1) QK = xr @ wr^T + bias      [16384 x 512], K=256   (tf32-rounded out)
    mma_gemm<true, true><<<dim3(4, 128, 1), 256, GEMM_SMEM>>>(
        xr, NE, 0, 0, 0,
        wr, NE, 0, 0, 0,
        QK, 2 * NE, 0,
        1, NE / 32, 1.f, bia);

    // 2) inv[b,h,i] = 0.25 / rowsum of exp-scores
    rowsum_kernel<<<dim3(16, NB * NH), 256, RS_SMEM>>>(QK, inv);

    // 3) Bm tiles: head-mean softmax, written once (tf32-rounded)
    bm_kernel<<<dim3(16, 16, NB), 256, BM_SMEM>>>(QK, inv, Bm);

    // 4) AG[b] = Bm[b] @ xT[b]^T    [2048 x 256] x8, K=2048  (tf32-rounded out)
    mma_gemm<true, false><<<dim3(2, 16, NB), 256, GEMM_SMEM>>>(
        Bm, NL, NL, 0, 0,
        xT, NL, NE, 0, 0,
        AG, NE, (long)NL * NE,
        1, NL / 32, 1.f, nullptr);

    // 5) out = AG @ WgT^T + Bg      [16384 x 256], K=256
    mma_gemm<false, true><<<dim3(2, 128, 1), 256, GEMM_SMEM>>>(
        AG, NE, 0, 0, 0,
        WgT, NE, 0, 0, 0,
        out, NE, 0,
        1, NE / 32, 1.f, Bg);
}

// round 5
// speedup vs baseline: 1.4436x; 1.4436x over previous
#include <cuda_runtime.h>
#include <cuda_bf16.h>
#include <cstdint>

#define NB 8
#define NL 2048
#define NE 256
#define NH 4
#define ND 64

// ---------------- scratch (device globals; no allocation allowed) -----------
__device__ __nv_bfloat16 g_xb  [(size_t)NB * NL * NE];        // bf16 x
__device__ __nv_bfloat16 g_wb  [(size_t)2 * NE * NE];         // bf16 w[0:512]
__device__ __nv_bfloat16 g_xTb [(size_t)NB * NE * NL];        // bf16 x^T per b
__device__ __nv_bfloat16 g_WgTb[(size_t)NE * NE];             // bf16 Wg^T
__device__ __nv_bfloat16 g_QKb [(size_t)NB * NL * 2 * NE];    // [16384, 512]
__device__ __nv_bfloat16 g_P   [(size_t)NB * NH * NL * NL];   // exp-scores, 268MB
__device__ __nv_bfloat16 g_Bmb [(size_t)NB * NL * NL];        // head-mean probs
__device__ __nv_bfloat16 g_AGb [(size_t)NB * NL * NE];        // Bm @ x

// ------------------------------- helpers ------------------------------------
__device__ __forceinline__ uint32_t smem_u32(const void* p) {
    uint32_t a;
    asm("{ .reg .u64 t; cvta.to.shared.u64 t, %1; cvt.u32.u64 %0, t; }"
        : "=r"(a) : "l"(p));
    return a;
}

#define CP_ASYNC16(dst, src) \
    asm volatile("cp.async.cg.shared.global [%0], [%1], 16;" \
                 :: "r"(dst), "l"(src) : "memory")
#define CP_COMMIT() asm volatile("cp.async.commit_group;" ::: "memory")
#define CP_WAIT(n)  asm volatile("cp.async.wait_group %0;" :: "n"(n) : "memory")

#define MMA_BF16(d, a, b)                                                      \
    asm volatile("mma.sync.aligned.m16n8k16.row.col.f32.bf16.bf16.f32 "       \
        "{%0,%1,%2,%3}, {%4,%5,%6,%7}, {%8,%9}, {%0,%1,%2,%3};"                \
        : "+f"((d)[0]), "+f"((d)[1]), "+f"((d)[2]), "+f"((d)[3])               \
        : "r"((a)[0]), "r"((a)[1]), "r"((a)[2]), "r"((a)[3]),                  \
          "r"((b)[0]), "r"((b)[1]))

__device__ __forceinline__ void store2(float* p, float a, float b) {
    *(float2*)p = make_float2(a, b);
}
__device__ __forceinline__ void store2(__nv_bfloat16* p, float a, float b) {
    *(__nv_bfloat162*)p = __floats2bfloat162_rn(a, b);
}

// ------------------------------- bf16 GEMM ----------------------------------
// C[z] = f(alpha * A_z * B_z^T + bias[col]) ; A [M,K], B [N,K] bf16 K-major.
// CTA tile 128x128, K chunk 64 elems, 8 warps (2x4), warp tile 64x32,
// cp.async double buffer. smem rows: 32 words (64 bf16) + 4 pad = 36 words.
// Word-level fragment indexing identical to the proven tf32 scheme.
#define STG_BYTES  36864
#define GEMM_SMEM  (2 * STG_BYTES)

template <typename OutT, bool EXP_OUT, bool HAS_BIAS>
__global__ __launch_bounds__(256, 2)
void bgemm(const __nv_bfloat16* __restrict__ A, int lda, int a_zo_row, int a_zi_col, int a_col_base,
           const __nv_bfloat16* __restrict__ Bp, int ldb, int b_zo_row, int b_zi_col, int b_col_base,
           OutT* __restrict__ C, int ldc, long sC,
           int inner, int nk, float alpha, const float* __restrict__ bias)
{
    extern __shared__ __align__(16) char smem[];
    const int tid    = threadIdx.x;
    const int warpId = tid >> 5;
    const int lane   = tid & 31;
    const int g  = lane >> 2;
    const int tg = lane & 3;
    const int wr = (warpId & 1) * 64;
    const int wc = (warpId >> 1) * 32;

    const int z  = blockIdx.z;
    const int zo = z / inner;
    const int zi = z - zo * inner;

    const __nv_bfloat16* Ag = A  + ((long)zo * a_zo_row + (long)blockIdx.y * 128) * lda
                                 + a_col_base + zi * a_zi_col;
    const __nv_bfloat16* Bg = Bp + ((long)zo * b_zo_row + (long)blockIdx.x * 128) * ldb
                                 + b_col_base + zi * b_zi_col;

    const uint32_t sbase = smem_u32(smem);

    // stage: A tile [128 x 64 bf16] + B tile [128 x 64 bf16]; rows 144B (pad)
    auto load_stage = [&](int st, int kc) {
        const uint32_t da = sbase + st * STG_BYTES;
        const __nv_bfloat16* a = Ag + kc * 64;
        const __nv_bfloat16* b = Bg + kc * 64;
#pragma unroll
        for (int i = 0; i < 4; i++) {
            const int idx = tid + 256 * i;
            const int row = idx >> 3, c4 = idx & 7;
            CP_ASYNC16(da + row * 144 + c4 * 16, a + (long)row * lda + c4 * 8);
        }
#pragma unroll
        for (int i = 0; i < 4; i++) {
            const int idx = tid + 256 * i;
            const int row = idx >> 3, c4 = idx & 7;
            CP_ASYNC16(da + 18432 + row * 144 + c4 * 16, b + (long)row * ldb + c4 * 8);
        }
    };

    float acc[4][4][4];
#pragma unroll
    for (int m = 0; m < 4; m++)
#pragma unroll
        for (int n = 0; n < 4; n++)
#pragma unroll
            for (int c = 0; c < 4; c++) acc[m][n][c] = 0.f;

    load_stage(0, 0);
    CP_COMMIT();

    for (int i = 0; i < nk; i++) {
        if (i + 1 < nk) {
            load_stage((i + 1) & 1, i + 1);
            CP_COMMIT();
            CP_WAIT(1);
        } else {
            CP_WAIT(0);
        }
        __syncthreads();

        const uint32_t* As = (const uint32_t*)(smem + (i & 1) * STG_BYTES);
        const uint32_t* Bs = As + 4608;

#pragma unroll
        for (int j = 0; j < 4; j++) {           // 4 x k16 steps
            uint32_t af[4][4], bf[4][2];
#pragma unroll
            for (int mt = 0; mt < 4; mt++) {
                const int r0 = wr + mt * 16 + g;
                af[mt][0] = As[ r0      * 36 + j * 8 + tg    ];
                af[mt][1] = As[(r0 + 8) * 36 + j * 8 + tg    ];
                af[mt][2] = As[ r0      * 36 + j * 8 + tg + 4];
                af[mt][3] = As[(r0 + 8) * 36 + j * 8 + tg + 4];
            }
#pragma unroll
            for (int nt = 0; nt < 4; nt++) {
                const int r0 = wc + nt * 8 + g;
                bf[nt][0] = Bs[r0 * 36 + j * 8 + tg    ];
                bf[nt][1] = Bs[r0 * 36 + j * 8 + tg + 4];
            }
#pragma unroll
            for (int mt = 0; mt < 4; mt++)
#pragma unroll
                for (int nt = 0; nt < 4; nt++)
                    MMA_BF16(acc[mt][nt], af[mt], bf[nt]);
        }
        __syncthreads();
    }

    // ---- epilogue ----
    OutT* Cz = C + (long)z * sC;
    const long crow0 = (long)blockIdx.y * 128;
    const int  ccol0 = blockIdx.x * 128;

#pragma unroll
    for (int mt = 0; mt < 4; mt++) {
#pragma unroll
        for (int nt = 0; nt < 4; nt++) {
            const long r = crow0 + wr + mt * 16 + g;
            const int  c = ccol0 + wc + nt * 8 + tg * 2;
            float b0 = 0.f, b1 = 0.f;
            if (HAS_BIAS) { b0 = bias[c]; b1 = bias[c + 1]; }
            float v00 = acc[mt][nt][0] * alpha + b0;
            float v01 = acc[mt][nt][1] * alpha + b1;
            float v10 = acc[mt][nt][2] * alpha + b0;
            float v11 = acc[mt][nt][3] * alpha + b1;
            if (EXP_OUT) {
                v00 = __expf(v00); v01 = __expf(v01);
                v10 = __expf(v10); v11 = __expf(v11);
            }
            store2(Cz +  r      * ldc + c, v00, v01);
            store2(Cz + (r + 8) * ldc + c, v10, v11);
        }
    }
}

// ---------------------------------------------------------------------------
// head-mean of normalized exp-scores:
// Bm[b,i,j] = sum_h P[b,h,i,j] / (4 * sum_j' P[b,h,i,j'])
// One CTA per (b,i); each thread owns 8 contiguous columns (16B load/store).
__device__ __forceinline__ float warp_sum(float v) {
#pragma unroll
    for (int o = 16; o; o >>= 1) v += __shfl_xor_sync(0xffffffffu, v, o);
    return v;
}

__global__ __launch_bounds__(256)
void pmean_kernel(const __nv_bfloat16* __restrict__ P, __nv_bfloat16* __restrict__ Bm)
{
    __shared__ float red[8];
    const int bi   = blockIdx.x;
    const int b    = bi >> 11;
    const int i    = bi & 2047;
    const int tid  = threadIdx.x;
    const int wid  = tid >> 5;
    const int lane = tid & 31;

    float acc[8] = {0, 0, 0, 0, 0, 0, 0, 0};

    for (int h = 0; h < NH; h++) {
        const __nv_bfloat16* row = P + (((long)(b * NH + h)) * NL + i) * NL;
        union { float4 f; __nv_bfloat162 hh[4]; } u;
        u.f = *(const float4*)(row + tid * 8);
        float v[8];
#pragma unroll
        for (int j = 0; j < 4; j++) {
            float2 p = __bfloat1622float2(u.hh[j]);
            v[2 * j] = p.x; v[2 * j + 1] = p.y;
        }
        float s = 0.f;
#pragma unroll
        for (int j = 0; j < 8; j++) s += v[j];
        s = warp_sum(s);
        if (lane == 0) red[wid] = s;
        __syncthreads();
        float st = red[0];
#pragma unroll
        for (int w = 1; w < 8; w++) st += red[w];

        const float inv = 0.25f / st;
#pragma unroll
        for (int j = 0; j < 8; j++) acc[j] += v[j] * inv;
        __syncthreads();
    }

    union { float4 f; __nv_bfloat162 hh[4]; } o;
#pragma unroll
    for (int j = 0; j < 4; j++)
        o.hh[j] = __floats2bfloat162_rn(acc[2 * j], acc[2 * j + 1]);
    *(float4*)(Bm + (long)bi * NL + tid * 8) = o.f;
}

// ---------------------------------------------------------------------------
// fp32 -> bf16 convert / transposed convert prepasses
__global__ void cvt_bf16_kernel(const float* __restrict__ in,
                                __nv_bfloat16* __restrict__ out, long n)
{
    const long i = ((long)blockIdx.x * blockDim.x + threadIdx.x) * 4;
    if (i < n) {
        float4 v = *(const float4*)(in + i);
        union { uint2 u; __nv_bfloat162 h[2]; } p;
        p.h[0] = __floats2bfloat162_rn(v.x, v.y);
        p.h[1] = __floats2bfloat162_rn(v.z, v.w);
        *(uint2*)(out + i) = p.u;
    }
}

__global__ void transpose_cvt_kernel(const float* __restrict__ in,
                                     __nv_bfloat16* __restrict__ out, int R, int Cn)
{
    __shared__ float t[32][33];
    in  += (size_t)blockIdx.z * R * Cn;
    out += (size_t)blockIdx.z * R * Cn;
    const int r0 = blockIdx.y * 32, c0 = blockIdx.x * 32;
    const int x = threadIdx.x, y = threadIdx.y;
#pragma unroll
    for (int i = 0; i < 32; i += 8)
        t[y + i][x] = in[(long)(r0 + y + i) * Cn + c0 + x];
    __syncthreads();
#pragma unroll
    for (int i = 0; i < 32; i += 8)
        out[(long)(c0 + y + i) * R + r0 + x] = __float2bfloat16_rn(t[x][y + i]);
}

// ---------------------------------------------------------------------------
extern "C" void kernel_launch(void* const* d_in, const int* in_sizes, int n_in,
                              void* d_out, int out_size)
{
    (void)in_sizes; (void)n_in; (void)out_size;
    const float* x   = (const float*)d_in[0];
    const float* w   = (const float*)d_in[1];
    const float* bia = (const float*)d_in[2];
    const float* Wg  = (const float*)d_in[3];
    const float* Bg  = (const float*)d_in[4];
    float* out = (float*)d_out;

    __nv_bfloat16 *xb, *wb, *xTb, *WgTb, *QKb, *P, *Bmb, *AGb;
    cudaGetSymbolAddress((void**)&xb,   g_xb);
    cudaGetSymbolAddress((void**)&wb,   g_wb);
    cudaGetSymbolAddress((void**)&xTb,  g_xTb);
    cudaGetSymbolAddress((void**)&WgTb, g_WgTb);
    cudaGetSymbolAddress((void**)&QKb,  g_QKb);
    cudaGetSymbolAddress((void**)&P,    g_P);
    cudaGetSymbolAddress((void**)&Bmb,  g_Bmb);
    cudaGetSymbolAddress((void**)&AGb,  g_AGb);

    cudaFuncSetAttribute((const void*)bgemm<__nv_bfloat16, false, true >,
                         cudaFuncAttributeMaxDynamicSharedMemorySize, GEMM_SMEM);
    cudaFuncSetAttribute((const void*)bgemm<__nv_bfloat16, true,  false>,
                         cudaFuncAttributeMaxDynamicSharedMemorySize, GEMM_SMEM);
    cudaFuncSetAttribute((const void*)bgemm<__nv_bfloat16, false, false>,
                         cudaFuncAttributeMaxDynamicSharedMemorySize, GEMM_SMEM);
    cudaFuncSetAttribute((const void*)bgemm<float, false, true>,
                         cudaFuncAttributeMaxDynamicSharedMemorySize, GEMM_SMEM);

    // 0) bf16 operand prep
    {
        const long nx = (long)NB * NL * NE;
        cvt_bf16_kernel<<<(int)(nx / 4 / 256), 256>>>(x, xb, nx);
        const long nw = (long)2 * NE * NE;
        cvt_bf16_kernel<<<(int)((nw / 4 + 255) / 256), 256>>>(w, wb, nw);
        transpose_cvt_kernel<<<dim3(NE / 32, NL / 32, NB), dim3(32, 8)>>>(x, xTb, NL, NE);
        transpose_cvt_kernel<<<dim3(NE / 32, NE / 32, 1), dim3(32, 8)>>>(Wg, WgTb, NE, NE);
    }

    // 1) QK = xb @ wb^T + bias   [16384 x 512], K=256 (nk=4)
    bgemm<__nv_bfloat16, false, true><<<dim3(4, 128, 1), 256, GEMM_SMEM>>>(
        xb, NE, 0, 0, 0,
        wb, NE, 0, 0, 0,
        QKb, 2 * NE, 0,
        1, NE / 64, 1.f, bia);

    // 2) P[b*4+h] = exp(0.125 * q_h @ k_h^T)   [2048 x 2048] x32, K=64 (nk=1)
    bgemm<__nv_bfloat16, true, false><<<dim3(16, 16, NB * NH), 256, GEMM_SMEM>>>(
        QKb, 2 * NE, NL, ND, 0,
        QKb, 2 * NE, NL, ND, NE,
        P, NL, (long)NL * NL,
        NH, 1, 0.125f, nullptr);

    // 3) Bm[b,i,:] = mean_h P[b,h,i,:] / rowsum
    pmean_kernel<<<NB * NL, 256>>>(P, Bmb);

    // 4) AG[b] = Bm[b] @ xTb[b]^T   [2048 x 256] x8, K=2048 (nk=32)
    bgemm<__nv_bfloat16, false, false><<<dim3(2, 16, NB), 256, GEMM_SMEM>>>(
        Bmb, NL, NL, 0, 0,
        xTb, NL, NE, 0, 0,
        AGb, NE, (long)NL * NE,
        1, NL / 64, 1.f, nullptr);

    // 5) out = AG @ WgTb^T + Bg    [16384 x 256], K=256 (nk=4)
    bgemm<float, false, true><<<dim3(2, 128, 1), 256, GEMM_SMEM>>>(
        AGb, NE, 0, 0, 0,
        WgTb, NE, 0, 0, 0,
        out, NE, 0,
        1, NE / 64, 1.f, Bg);
}

// round 6
// speedup vs baseline: 1.5012x; 1.0399x over previous
#include <cuda_runtime.h>
#include <cuda_bf16.h>
#include <cstdint>

#define NB 8
#define NL 2048
#define NE 256
#define NH 4
#define ND 64

// ---------------- scratch (device globals; no allocation allowed) -----------
__device__ __nv_bfloat16 g_xb  [(size_t)NB * NL * NE];        // bf16 x
__device__ __nv_bfloat16 g_wb  [(size_t)2 * NE * NE];         // bf16 w[0:512]
__device__ __nv_bfloat16 g_xTb [(size_t)NB * NE * NL];        // bf16 x^T per b
__device__ __nv_bfloat16 g_WgTb[(size_t)NE * NE];             // bf16 Wg^T
__device__ __nv_bfloat16 g_QKb [(size_t)NB * NL * 2 * NE];    // [16384, 512]
__device__ __nv_bfloat16 g_P   [(size_t)NB * NH * NL * NL];   // exp-scores
__device__ __nv_bfloat16 g_Bmb [(size_t)NB * NL * NL];        // head-mean probs
__device__ __nv_bfloat16 g_AGb [(size_t)NB * NL * NE];        // Bm @ x

// ------------------------------- helpers ------------------------------------
__device__ __forceinline__ uint32_t smem_u32(const void* p) {
    uint32_t a;
    asm("{ .reg .u64 t; cvta.to.shared.u64 t, %1; cvt.u32.u64 %0, t; }"
        : "=r"(a) : "l"(p));
    return a;
}

#define CP_ASYNC16(dst, src) \
    asm volatile("cp.async.cg.shared.global [%0], [%1], 16;" \
                 :: "r"(dst), "l"(src) : "memory")
#define CP_COMMIT() asm volatile("cp.async.commit_group;" ::: "memory")
#define CP_WAIT(n)  asm volatile("cp.async.wait_group %0;" :: "n"(n) : "memory")

#define MMA_BF16(d, a, b)                                                      \
    asm volatile("mma.sync.aligned.m16n8k16.row.col.f32.bf16.bf16.f32 "       \
        "{%0,%1,%2,%3}, {%4,%5,%6,%7}, {%8,%9}, {%0,%1,%2,%3};"                \
        : "+f"((d)[0]), "+f"((d)[1]), "+f"((d)[2]), "+f"((d)[3])               \
        : "r"((a)[0]), "r"((a)[1]), "r"((a)[2]), "r"((a)[3]),                  \
          "r"((b)[0]), "r"((b)[1]))

#define LDSM_X4(r0, r1, r2, r3, addr)                                          \
    asm volatile("ldmatrix.sync.aligned.m8n8.x4.shared.b16 {%0,%1,%2,%3}, [%4];" \
        : "=r"(r0), "=r"(r1), "=r"(r2), "=r"(r3) : "r"(addr))

__device__ __forceinline__ void store2(float* p, float a, float b) {
    *(float2*)p = make_float2(a, b);
}
__device__ __forceinline__ void store2(__nv_bfloat16* p, float a, float b) {
    *(__nv_bfloat162*)p = __floats2bfloat162_rn(a, b);
}

// ------------------------------- bf16 GEMM ----------------------------------
// C[z] = f(alpha * A_z * B_z^T + bias[col]) ; A [M,K], B [N,K] bf16 K-major.
// CTA tile 128x128, K chunk 64 elems, 8 warps (2x4), warp tile 64x32,
// cp.async double buffer, ldmatrix fragment loads.
// smem rows: 32 words (64 bf16) + 4 pad = 36 words (conflict-free for both
// cp.async stores and ldmatrix phases: row starts at bank 4r mod 32).
#define STG_BYTES  36864
#define GEMM_SMEM  (2 * STG_BYTES)

template <typename OutT, bool EXP_OUT, bool HAS_BIAS>
__global__ __launch_bounds__(256, 2)
void bgemm(const __nv_bfloat16* __restrict__ A, int lda, int a_zo_row, int a_zi_col, int a_col_base,
           const __nv_bfloat16* __restrict__ Bp, int ldb, int b_zo_row, int b_zi_col, int b_col_base,
           OutT* __restrict__ C, int ldc, long sC,
           int inner, int nk, float alpha, const float* __restrict__ bias)
{
    extern __shared__ __align__(16) char smem[];
    const int tid    = threadIdx.x;
    const int warpId = tid >> 5;
    const int lane   = tid & 31;
    const int g  = lane >> 2;
    const int tg = lane & 3;
    const int wr = (warpId & 1) * 64;
    const int wc = (warpId >> 1) * 32;

    const int z  = blockIdx.z;
    const int zo = z / inner;
    const int zi = z - zo * inner;

    const __nv_bfloat16* Ag = A  + ((long)zo * a_zo_row + (long)blockIdx.y * 128) * lda
                                 + a_col_base + zi * a_zi_col;
    const __nv_bfloat16* Bg = Bp + ((long)zo * b_zo_row + (long)blockIdx.x * 128) * ldb
                                 + b_col_base + zi * b_zi_col;

    const uint32_t sbase = smem_u32(smem);

    // per-thread ldmatrix base offsets (bytes), relative to stage A/B starts
    const uint32_t a_loff = ((wr + (lane & 15)) * 36 + ((lane >> 4) * 4)) * 4;
    const uint32_t b_loff = ((wc + (lane & 7) + ((lane >> 4) << 3)) * 36
                             + (((lane >> 3) & 1) * 4)) * 4;

    auto load_stage = [&](int st, int kc) {
        const uint32_t da = sbase + st * STG_BYTES;
        const __nv_bfloat16* a = Ag + kc * 64;
        const __nv_bfloat16* b = Bg + kc * 64;
#pragma unroll
        for (int i = 0; i < 4; i++) {
            const int idx = tid + 256 * i;
            const int row = idx >> 3, c4 = idx & 7;
            CP_ASYNC16(da + row * 144 + c4 * 16, a + (long)row * lda + c4 * 8);
        }
#pragma unroll
        for (int i = 0; i < 4; i++) {
            const int idx = tid + 256 * i;
            const int row = idx >> 3, c4 = idx & 7;
            CP_ASYNC16(da + 18432 + row * 144 + c4 * 16, b + (long)row * ldb + c4 * 8);
        }
    };

    float acc[4][4][4];
#pragma unroll
    for (int m = 0; m < 4; m++)
#pragma unroll
        for (int n = 0; n < 4; n++)
#pragma unroll
            for (int c = 0; c < 4; c++) acc[m][n][c] = 0.f;

    load_stage(0, 0);
    CP_COMMIT();

    for (int i = 0; i < nk; i++) {
        if (i + 1 < nk) {
            load_stage((i + 1) & 1, i + 1);
            CP_COMMIT();
            CP_WAIT(1);
        } else {
            CP_WAIT(0);
        }
        __syncthreads();

        const uint32_t sA = sbase + (i & 1) * STG_BYTES + a_loff;
        const uint32_t sB = sbase + (i & 1) * STG_BYTES + 18432 + b_loff;

#pragma unroll
        for (int j = 0; j < 4; j++) {           // 4 x k16 steps
            uint32_t af[4][4], bf[4][2];
#pragma unroll
            for (int mt = 0; mt < 4; mt++)
                LDSM_X4(af[mt][0], af[mt][1], af[mt][2], af[mt][3],
                        sA + mt * (16 * 36 * 4) + j * 32);
#pragma unroll
            for (int p = 0; p < 2; p++)
                LDSM_X4(bf[2 * p][0], bf[2 * p][1], bf[2 * p + 1][0], bf[2 * p + 1][1],
                        sB + p * (16 * 36 * 4) + j * 32);
#pragma unroll
            for (int mt = 0; mt < 4; mt++)
#pragma unroll
                for (int nt = 0; nt < 4; nt++)
                    MMA_BF16(acc[mt][nt], af[mt], bf[nt]);
        }
        __syncthreads();
    }

    // ---- epilogue ----
    OutT* Cz = C + (long)z * sC;
    const long crow0 = (long)blockIdx.y * 128;
    const int  ccol0 = blockIdx.x * 128;

#pragma unroll
    for (int mt = 0; mt < 4; mt++) {
#pragma unroll
        for (int nt = 0; nt < 4; nt++) {
            const long r = crow0 + wr + mt * 16 + g;
            const int  c = ccol0 + wc + nt * 8 + tg * 2;
            float b0 = 0.f, b1 = 0.f;
            if (HAS_BIAS) { b0 = bias[c]; b1 = bias[c + 1]; }
            float v00 = acc[mt][nt][0] * alpha + b0;
            float v01 = acc[mt][nt][1] * alpha + b1;
            float v10 = acc[mt][nt][2] * alpha + b0;
            float v11 = acc[mt][nt][3] * alpha + b1;
            if (EXP_OUT) {
                v00 = __expf(v00); v01 = __expf(v01);
                v10 = __expf(v10); v11 = __expf(v11);
            }
            store2(Cz +  r      * ldc + c, v00, v01);
            store2(Cz + (r + 8) * ldc + c, v10, v11);
        }
    }
}

// ---------------------------------------------------------------------------
// head-mean of normalized exp-scores:
// Bm[b,i,j] = sum_h P[b,h,i,j] / (4 * sum_j' P[b,h,i,j'])
__device__ __forceinline__ float warp_sum(float v) {
#pragma unroll
    for (int o = 16; o; o >>= 1) v += __shfl_xor_sync(0xffffffffu, v, o);
    return v;
}

__global__ __launch_bounds__(256)
void pmean_kernel(const __nv_bfloat16* __restrict__ P, __nv_bfloat16* __restrict__ Bm)
{
    __shared__ float red[8];
    const int bi   = blockIdx.x;
    const int b    = bi >> 11;
    const int i    = bi & 2047;
    const int tid  = threadIdx.x;
    const int wid  = tid >> 5;
    const int lane = tid & 31;

    float acc[8] = {0, 0, 0, 0, 0, 0, 0, 0};

    for (int h = 0; h < NH; h++) {
        const __nv_bfloat16* row = P + (((long)(b * NH + h)) * NL + i) * NL;
        union { float4 f; __nv_bfloat162 hh[4]; } u;
        u.f = *(const float4*)(row + tid * 8);
        float v[8];
#pragma unroll
        for (int j = 0; j < 4; j++) {
            float2 p = __bfloat1622float2(u.hh[j]);
            v[2 * j] = p.x; v[2 * j + 1] = p.y;
        }
        float s = 0.f;
#pragma unroll
        for (int j = 0; j < 8; j++) s += v[j];
        s = warp_sum(s);
        if (lane == 0) red[wid] = s;
        __syncthreads();
        float st = red[0];
#pragma unroll
        for (int w = 1; w < 8; w++) st += red[w];

        const float inv = 0.25f / st;
#pragma unroll
        for (int j = 0; j < 8; j++) acc[j] += v[j] * inv;
        __syncthreads();
    }

    union { float4 f; __nv_bfloat162 hh[4]; } o;
#pragma unroll
    for (int j = 0; j < 4; j++)
        o.hh[j] = __floats2bfloat162_rn(acc[2 * j], acc[2 * j + 1]);
    *(float4*)(Bm + (long)bi * NL + tid * 8) = o.f;
}

// ---------------------------------------------------------------------------
// prepasses: fp32 -> bf16 convert (and fused transpose+convert reading once)
__global__ void cvt_bf16_kernel(const float* __restrict__ in,
                                __nv_bfloat16* __restrict__ out, long n)
{
    const long i = ((long)blockIdx.x * blockDim.x + threadIdx.x) * 4;
    if (i < n) {
        float4 v = *(const float4*)(in + i);
        union { uint2 u; __nv_bfloat162 h[2]; } p;
        p.h[0] = __floats2bfloat162_rn(v.x, v.y);
        p.h[1] = __floats2bfloat162_rn(v.z, v.w);
        *(uint2*)(out + i) = p.u;
    }
}

// reads x once: writes bf16 copy (outN, may be null) and bf16 transpose (outT)
__global__ void transpose_cvt_kernel(const float* __restrict__ in,
                                     __nv_bfloat16* __restrict__ outT,
                                     __nv_bfloat16* __restrict__ outN,
                                     int R, int Cn)
{
    __shared__ float t[32][33];
    in   += (size_t)blockIdx.z * R * Cn;
    outT += (size_t)blockIdx.z * R * Cn;
    if (outN) outN += (size_t)blockIdx.z * R * Cn;
    const int r0 = blockIdx.y * 32, c0 = blockIdx.x * 32;
    const int x = threadIdx.x, y = threadIdx.y;
#pragma unroll
    for (int i = 0; i < 32; i += 8) {
        const float v = in[(long)(r0 + y + i) * Cn + c0 + x];
        t[y + i][x] = v;
        if (outN) outN[(long)(r0 + y + i) * Cn + c0 + x] = __float2bfloat16_rn(v);
    }
    __syncthreads();
#pragma unroll
    for (int i = 0; i < 32; i += 8)
        outT[(long)(c0 + y + i) * R + r0 + x] = __float2bfloat16_rn(t[x][y + i]);
}

// ---------------------------------------------------------------------------
extern "C" void kernel_launch(void* const* d_in, const int* in_sizes, int n_in,
                              void* d_out, int out_size)
{
    (void)in_sizes; (void)n_in; (void)out_size;
    const float* x   = (const float*)d_in[0];
    const float* w   = (const float*)d_in[1];
    const float* bia = (const float*)d_in[2];
    const float* Wg  = (const float*)d_in[3];
    const float* Bg  = (const float*)d_in[4];
    float* out = (float*)d_out;

    __nv_bfloat16 *xb, *wb, *xTb, *WgTb, *QKb, *P, *Bmb, *AGb;
    cudaGetSymbolAddress((void**)&xb,   g_xb);
    cudaGetSymbolAddress((void**)&wb,   g_wb);
    cudaGetSymbolAddress((void**)&xTb,  g_xTb);
    cudaGetSymbolAddress((void**)&WgTb, g_WgTb);
    cudaGetSymbolAddress((void**)&QKb,  g_QKb);
    cudaGetSymbolAddress((void**)&P,    g_P);
    cudaGetSymbolAddress((void**)&Bmb,  g_Bmb);
    cudaGetSymbolAddress((void**)&AGb,  g_AGb);

    cudaFuncSetAttribute((const void*)bgemm<__nv_bfloat16, false, true >,
                         cudaFuncAttributeMaxDynamicSharedMemorySize, GEMM_SMEM);
    cudaFuncSetAttribute((const void*)bgemm<__nv_bfloat16, true,  false>,
                         cudaFuncAttributeMaxDynamicSharedMemorySize, GEMM_SMEM);
    cudaFuncSetAttribute((const void*)bgemm<__nv_bfloat16, false, false>,
                         cudaFuncAttributeMaxDynamicSharedMemorySize, GEMM_SMEM);
    cudaFuncSetAttribute((const void*)bgemm<float, false, true>,
                         cudaFuncAttributeMaxDynamicSharedMemorySize, GEMM_SMEM);

    // 0) bf16 operand prep (x read once -> xb + xTb)
    {
        transpose_cvt_kernel<<<dim3(NE / 32, NL / 32, NB), dim3(32, 8)>>>(x, xTb, xb, NL, NE);
        const long nw = (long)2 * NE * NE;
        cvt_bf16_kernel<<<(int)((nw / 4 + 255) / 256), 256>>>(w, wb, nw);
        transpose_cvt_kernel<<<dim3(NE / 32, NE / 32, 1), dim3(32, 8)>>>(Wg, WgTb, nullptr, NE, NE);
    }

    // 1) QK = xb @ wb^T + bias   [16384 x 512], K=256 (nk=4)
    bgemm<__nv_bfloat16, false, true><<<dim3(4, 128, 1), 256, GEMM_SMEM>>>(
        xb, NE, 0, 0, 0,
        wb, NE, 0, 0, 0,
        QKb, 2 * NE, 0,
        1, NE / 64, 1.f, bia);

    // 2) P[b*4+h] = exp(0.125 * q_h @ k_h^T)   [2048 x 2048] x32, K=64 (nk=1)
    bgemm<__nv_bfloat16, true, false><<<dim3(16, 16, NB * NH), 256, GEMM_SMEM>>>(
        QKb, 2 * NE, NL, ND, 0,
        QKb, 2 * NE, NL, ND, NE,
        P, NL, (long)NL * NL,
        NH, 1, 0.125f, nullptr);

    // 3) Bm[b,i,:] = mean_h P[b,h,i,:] / rowsum
    pmean_kernel<<<NB * NL, 256>>>(P, Bmb);

    // 4) AG[b] = Bm[b] @ xTb[b]^T   [2048 x 256] x8, K=2048 (nk=32)
    bgemm<__nv_bfloat16, false, false><<<dim3(2, 16, NB), 256, GEMM_SMEM>>>(
        Bmb, NL, NL, 0, 0,
        xTb, NL, NE, 0, 0,
        AGb, NE, (long)NL * NE,
        1, NL / 64, 1.f, nullptr);

    // 5) out = AG @ WgTb^T + Bg    [16384 x 256], K=256 (nk=4)
    bgemm<float, false, true><<<dim3(2, 128, 1), 256, GEMM_SMEM>>>(
        AGb, NE, 0, 0, 0,
        WgTb, NE, 0, 0, 0,
        out, NE, 0,
        1, NE / 64, 1.f, Bg);
}

// round 7
// speedup vs baseline: 1.5282x; 1.0180x over previous
#include <cuda_runtime.h>
#include <cuda_bf16.h>
#include <cstdint>

#define NB 8
#define NL 2048
#define NE 256
#define NH 4
#define ND 64

// ---------------- scratch (device globals; no allocation allowed) -----------
__device__ __nv_bfloat16 g_xb  [(size_t)NB * NL * NE];        // bf16 x
__device__ __nv_bfloat16 g_wb  [(size_t)2 * NE * NE];         // bf16 w[0:512]
__device__ __nv_bfloat16 g_xTb [(size_t)NB * NE * NL];        // bf16 x^T per b
__device__ __nv_bfloat16 g_WgTb[(size_t)NE * NE];             // bf16 Wg^T
__device__ __nv_bfloat16 g_QKb [(size_t)NB * NL * 2 * NE];    // [16384, 512]
__device__ __nv_bfloat16 g_P   [(size_t)NB * NH * NL * NL];   // exp-scores
__device__ __nv_bfloat16 g_Bmb [(size_t)NB * NL * NL];        // head-mean probs
__device__ __nv_bfloat16 g_AGb [(size_t)NB * NL * NE];        // Bm @ x

// ------------------------------- helpers ------------------------------------
__device__ __forceinline__ uint32_t smem_u32(const void* p) {
    uint32_t a;
    asm("{ .reg .u64 t; cvta.to.shared.u64 t, %1; cvt.u32.u64 %0, t; }"
        : "=r"(a) : "l"(p));
    return a;
}

#define CP_ASYNC16(dst, src) \
    asm volatile("cp.async.cg.shared.global [%0], [%1], 16;" \
                 :: "r"(dst), "l"(src) : "memory")
#define CP_COMMIT() asm volatile("cp.async.commit_group;" ::: "memory")
#define CP_WAIT(n)  asm volatile("cp.async.wait_group %0;" :: "n"(n) : "memory")

#define MMA_BF16(d, a, b)                                                      \
    asm volatile("mma.sync.aligned.m16n8k16.row.col.f32.bf16.bf16.f32 "       \
        "{%0,%1,%2,%3}, {%4,%5,%6,%7}, {%8,%9}, {%0,%1,%2,%3};"                \
        : "+f"((d)[0]), "+f"((d)[1]), "+f"((d)[2]), "+f"((d)[3])               \
        : "r"((a)[0]), "r"((a)[1]), "r"((a)[2]), "r"((a)[3]),                  \
          "r"((b)[0]), "r"((b)[1]))

#define LDSM_X4(r0, r1, r2, r3, addr)                                          \
    asm volatile("ldmatrix.sync.aligned.m8n8.x4.shared.b16 {%0,%1,%2,%3}, [%4];" \
        : "=r"(r0), "=r"(r1), "=r"(r2), "=r"(r3) : "r"(addr))

__device__ __forceinline__ void store2(float* p, float a, float b) {
    *(float2*)p = make_float2(a, b);
}
__device__ __forceinline__ void store2(__nv_bfloat16* p, float a, float b) {
    *(__nv_bfloat162*)p = __floats2bfloat162_rn(a, b);
}

// ------------------------------- bf16 GEMM ----------------------------------
// C[z] = f(alpha * A_z * B_z^T + bias[col]) ; A [M,K], B [N,K] bf16 K-major.
// CTA tile 128x128, K chunk 64 elems, 8 warps (2x4), warp tile 64x32,
// 3-stage cp.async pipeline (2-chunk lookahead), ldmatrix fragment loads.
// smem rows: 32 words (64 bf16) + 4 pad = 36 words (conflict-free).
#define STAGES     3
#define STG_BYTES  36864
#define GEMM_SMEM  (STAGES * STG_BYTES)

template <typename OutT, bool EXP_OUT, bool HAS_BIAS>
__global__ __launch_bounds__(256, 2)
void bgemm(const __nv_bfloat16* __restrict__ A, int lda, int a_zo_row, int a_zi_col, int a_col_base,
           const __nv_bfloat16* __restrict__ Bp, int ldb, int b_zo_row, int b_zi_col, int b_col_base,
           OutT* __restrict__ C, int ldc, long sC,
           int inner, int nk, float alpha, const float* __restrict__ bias)
{
    extern __shared__ __align__(16) char smem[];
    const int tid    = threadIdx.x;
    const int warpId = tid >> 5;
    const int lane   = tid & 31;
    const int g  = lane >> 2;
    const int tg = lane & 3;
    const int wr = (warpId & 1) * 64;
    const int wc = (warpId >> 1) * 32;

    const int z  = blockIdx.z;
    const int zo = z / inner;
    const int zi = z - zo * inner;

    const __nv_bfloat16* Ag = A  + ((long)zo * a_zo_row + (long)blockIdx.y * 128) * lda
                                 + a_col_base + zi * a_zi_col;
    const __nv_bfloat16* Bg = Bp + ((long)zo * b_zo_row + (long)blockIdx.x * 128) * ldb
                                 + b_col_base + zi * b_zi_col;

    const uint32_t sbase = smem_u32(smem);

    // per-thread ldmatrix base offsets (bytes), relative to stage A/B starts
    const uint32_t a_loff = ((wr + (lane & 15)) * 36 + ((lane >> 4) * 4)) * 4;
    const uint32_t b_loff = ((wc + (lane & 7) + ((lane >> 4) << 3)) * 36
                             + (((lane >> 3) & 1) * 4)) * 4;

    auto load_stage = [&](int st, int kc) {
        const uint32_t da = sbase + st * STG_BYTES;
        const __nv_bfloat16* a = Ag + kc * 64;
        const __nv_bfloat16* b = Bg + kc * 64;
#pragma unroll
        for (int i = 0; i < 4; i++) {
            const int idx = tid + 256 * i;
            const int row = idx >> 3, c4 = idx & 7;
            CP_ASYNC16(da + row * 144 + c4 * 16, a + (long)row * lda + c4 * 8);
        }
#pragma unroll
        for (int i = 0; i < 4; i++) {
            const int idx = tid + 256 * i;
            const int row = idx >> 3, c4 = idx & 7;
            CP_ASYNC16(da + 18432 + row * 144 + c4 * 16, b + (long)row * ldb + c4 * 8);
        }
    };

    float acc[4][4][4];
#pragma unroll
    for (int m = 0; m < 4; m++)
#pragma unroll
        for (int n = 0; n < 4; n++)
#pragma unroll
            for (int c = 0; c < 4; c++) acc[m][n][c] = 0.f;

    // prologue: fill up to STAGES-1 stages
    load_stage(0, 0);
    CP_COMMIT();
    if (nk > 1) { load_stage(1, 1); CP_COMMIT(); }

    int stage = 0;
    for (int i = 0; i < nk; i++) {
        // stage i must be complete: {i, i+1} may be in flight at this point
        if (i + 1 < nk) { CP_WAIT(1); } else { CP_WAIT(0); }
        __syncthreads();

        // issue load for chunk i+2 (overwrites stage used by chunk i-1,
        // whose reads finished before the barrier above)
        if (i + 2 < nk) {
            int ns = stage + 2; if (ns >= STAGES) ns -= STAGES;
            load_stage(ns, i + 2);
            CP_COMMIT();
        }

        const uint32_t sA = sbase + stage * STG_BYTES + a_loff;
        const uint32_t sB = sbase + stage * STG_BYTES + 18432 + b_loff;

#pragma unroll
        for (int j = 0; j < 4; j++) {           // 4 x k16 steps
            uint32_t af[4][4], bf[4][2];
#pragma unroll
            for (int mt = 0; mt < 4; mt++)
                LDSM_X4(af[mt][0], af[mt][1], af[mt][2], af[mt][3],
                        sA + mt * (16 * 36 * 4) + j * 32);
#pragma unroll
            for (int p = 0; p < 2; p++)
                LDSM_X4(bf[2 * p][0], bf[2 * p][1], bf[2 * p + 1][0], bf[2 * p + 1][1],
                        sB + p * (16 * 36 * 4) + j * 32);
#pragma unroll
            for (int mt = 0; mt < 4; mt++)
#pragma unroll
                for (int nt = 0; nt < 4; nt++)
                    MMA_BF16(acc[mt][nt], af[mt], bf[nt]);
        }

        if (++stage == STAGES) stage = 0;
    }

    // ---- epilogue ----
    OutT* Cz = C + (long)z * sC;
    const long crow0 = (long)blockIdx.y * 128;
    const int  ccol0 = blockIdx.x * 128;

#pragma unroll
    for (int mt = 0; mt < 4; mt++) {
#pragma unroll
        for (int nt = 0; nt < 4; nt++) {
            const long r = crow0 + wr + mt * 16 + g;
            const int  c = ccol0 + wc + nt * 8 + tg * 2;
            float b0 = 0.f, b1 = 0.f;
            if (HAS_BIAS) { b0 = bias[c]; b1 = bias[c + 1]; }
            float v00 = acc[mt][nt][0] * alpha + b0;
            float v01 = acc[mt][nt][1] * alpha + b1;
            float v10 = acc[mt][nt][2] * alpha + b0;
            float v11 = acc[mt][nt][3] * alpha + b1;
            if (EXP_OUT) {
                v00 = __expf(v00); v01 = __expf(v01);
                v10 = __expf(v10); v11 = __expf(v11);
            }
            store2(Cz +  r      * ldc + c, v00, v01);
            store2(Cz + (r + 8) * ldc + c, v10, v11);
        }
    }
}

// ---------------------------------------------------------------------------
// head-mean of normalized exp-scores:
// Bm[b,i,j] = sum_h P[b,h,i,j] / (4 * sum_j' P[b,h,i,j'])
__device__ __forceinline__ float warp_sum(float v) {
#pragma unroll
    for (int o = 16; o; o >>= 1) v += __shfl_xor_sync(0xffffffffu, v, o);
    return v;
}

__global__ __launch_bounds__(256)
void pmean_kernel(const __nv_bfloat16* __restrict__ P, __nv_bfloat16* __restrict__ Bm)
{
    __shared__ float red[8];
    const int bi   = blockIdx.x;
    const int b    = bi >> 11;
    const int i    = bi & 2047;
    const int tid  = threadIdx.x;
    const int wid  = tid >> 5;
    const int lane = tid & 31;

    float acc[8] = {0, 0, 0, 0, 0, 0, 0, 0};

    for (int h = 0; h < NH; h++) {
        const __nv_bfloat16* row = P + (((long)(b * NH + h)) * NL + i) * NL;
        union { float4 f; __nv_bfloat162 hh[4]; } u;
        u.f = *(const float4*)(row + tid * 8);
        float v[8];
#pragma unroll
        for (int j = 0; j < 4; j++) {
            float2 p = __bfloat1622float2(u.hh[j]);
            v[2 * j] = p.x; v[2 * j + 1] = p.y;
        }
        float s = 0.f;
#pragma unroll
        for (int j = 0; j < 8; j++) s += v[j];
        s = warp_sum(s);
        if (lane == 0) red[wid] = s;
        __syncthreads();
        float st = red[0];
#pragma unroll
        for (int w = 1; w < 8; w++) st += red[w];

        const float inv = 0.25f / st;
#pragma unroll
        for (int j = 0; j < 8; j++) acc[j] += v[j] * inv;
        __syncthreads();
    }

    union { float4 f; __nv_bfloat162 hh[4]; } o;
#pragma unroll
    for (int j = 0; j < 4; j++)
        o.hh[j] = __floats2bfloat162_rn(acc[2 * j], acc[2 * j + 1]);
    *(float4*)(Bm + (long)bi * NL + tid * 8) = o.f;
}

// ---------------------------------------------------------------------------
// prepasses: fp32 -> bf16 convert (and fused transpose+convert reading once)
__global__ void cvt_bf16_kernel(const float* __restrict__ in,
                                __nv_bfloat16* __restrict__ out, long n)
{
    const long i = ((long)blockIdx.x * blockDim.x + threadIdx.x) * 4;
    if (i < n) {
        float4 v = *(const float4*)(in + i);
        union { uint2 u; __nv_bfloat162 h[2]; } p;
        p.h[0] = __floats2bfloat162_rn(v.x, v.y);
        p.h[1] = __floats2bfloat162_rn(v.z, v.w);
        *(uint2*)(out + i) = p.u;
    }
}

// reads x once: writes bf16 copy (outN, may be null) and bf16 transpose (outT)
__global__ void transpose_cvt_kernel(const float* __restrict__ in,
                                     __nv_bfloat16* __restrict__ outT,
                                     __nv_bfloat16* __restrict__ outN,
                                     int R, int Cn)
{
    __shared__ float t[32][33];
    in   += (size_t)blockIdx.z * R * Cn;
    outT += (size_t)blockIdx.z * R * Cn;
    if (outN) outN += (size_t)blockIdx.z * R * Cn;
    const int r0 = blockIdx.y * 32, c0 = blockIdx.x * 32;
    const int x = threadIdx.x, y = threadIdx.y;
#pragma unroll
    for (int i = 0; i < 32; i += 8) {
        const float v = in[(long)(r0 + y + i) * Cn + c0 + x];
        t[y + i][x] = v;
        if (outN) outN[(long)(r0 + y + i) * Cn + c0 + x] = __float2bfloat16_rn(v);
    }
    __syncthreads();
#pragma unroll
    for (int i = 0; i < 32; i += 8)
        outT[(long)(c0 + y + i) * R + r0 + x] = __float2bfloat16_rn(t[x][y + i]);
}

// ---------------------------------------------------------------------------
extern "C" void kernel_launch(void* const* d_in, const int* in_sizes, int n_in,
                              void* d_out, int out_size)
{
    (void)in_sizes; (void)n_in; (void)out_size;
    const float* x   = (const float*)d_in[0];
    const float* w   = (const float*)d_in[1];
    const float* bia = (const float*)d_in[2];
    const float* Wg  = (const float*)d_in[3];
    const float* Bg  = (const float*)d_in[4];
    float* out = (float*)d_out;

    __nv_bfloat16 *xb, *wb, *xTb, *WgTb, *QKb, *P, *Bmb, *AGb;
    cudaGetSymbolAddress((void**)&xb,   g_xb);
    cudaGetSymbolAddress((void**)&wb,   g_wb);
    cudaGetSymbolAddress((void**)&xTb,  g_xTb);
    cudaGetSymbolAddress((void**)&WgTb, g_WgTb);
    cudaGetSymbolAddress((void**)&QKb,  g_QKb);
    cudaGetSymbolAddress((void**)&P,    g_P);
    cudaGetSymbolAddress((void**)&Bmb,  g_Bmb);
    cudaGetSymbolAddress((void**)&AGb,  g_AGb);

    cudaFuncSetAttribute((const void*)bgemm<__nv_bfloat16, false, true >,
                         cudaFuncAttributeMaxDynamicSharedMemorySize, GEMM_SMEM);
    cudaFuncSetAttribute((const void*)bgemm<__nv_bfloat16, true,  false>,
                         cudaFuncAttributeMaxDynamicSharedMemorySize, GEMM_SMEM);
    cudaFuncSetAttribute((const void*)bgemm<__nv_bfloat16, false, false>,
                         cudaFuncAttributeMaxDynamicSharedMemorySize, GEMM_SMEM);
    cudaFuncSetAttribute((const void*)bgemm<float, false, true>,
                         cudaFuncAttributeMaxDynamicSharedMemorySize, GEMM_SMEM);

    // 0) bf16 operand prep (x read once -> xb + xTb)
    {
        transpose_cvt_kernel<<<dim3(NE / 32, NL / 32, NB), dim3(32, 8)>>>(x, xTb, xb, NL, NE);
        const long nw = (long)2 * NE * NE;
        cvt_bf16_kernel<<<(int)((nw / 4 + 255) / 256), 256>>>(w, wb, nw);
        transpose_cvt_kernel<<<dim3(NE / 32, NE / 32, 1), dim3(32, 8)>>>(Wg, WgTb, nullptr, NE, NE);
    }

    // 1) QK = xb @ wb^T + bias   [16384 x 512], K=256 (nk=4)
    bgemm<__nv_bfloat16, false, true><<<dim3(4, 128, 1), 256, GEMM_SMEM>>>(
        xb, NE, 0, 0, 0,
        wb, NE, 0, 0, 0,
        QKb, 2 * NE, 0,
        1, NE / 64, 1.f, bia);

    // 2) P[b*4+h] = exp(0.125 * q_h @ k_h^T)   [2048 x 2048] x32, K=64 (nk=1)
    bgemm<__nv_bfloat16, true, false><<<dim3(16, 16, NB * NH), 256, GEMM_SMEM>>>(
        QKb, 2 * NE, NL, ND, 0,
        QKb, 2 * NE, NL, ND, NE,
        P, NL, (long)NL * NL,
        NH, 1, 0.125f, nullptr);

    // 3) Bm[b,i,:] = mean_h P[b,h,i,:] / rowsum
    pmean_kernel<<<NB * NL, 256>>>(P, Bmb);

    // 4) AG[b] = Bm[b] @ xTb[b]^T   [2048 x 256] x8, K=2048 (nk=32)
    bgemm<__nv_bfloat16, false, false><<<dim3(2, 16, NB), 256, GEMM_SMEM>>>(
        Bmb, NL, NL, 0, 0,
        xTb, NL, NE, 0, 0,
        AGb, NE, (long)NL * NE,
        1, NL / 64, 1.f, nullptr);

    // 5) out = AG @ WgTb^T + Bg    [16384 x 256], K=256 (nk=4)
    bgemm<float, false, true><<<dim3(2, 128, 1), 256, GEMM_SMEM>>>(
        AGb, NE, 0, 0, 0,
        WgTb, NE, 0, 0, 0,
        out, NE, 0,
        1, NE / 64, 1.f, Bg);
}

// round 8
// speedup vs baseline: 1.6210x; 1.0607x over previous
#include <cuda_runtime.h>
#include <cuda_bf16.h>
#include <cstdint>

#define NB 8
#define NL 2048
#define NE 256
#define NH 4
#define ND 64

// ---------------- scratch (device globals; no allocation allowed) -----------
__device__ __nv_bfloat16 g_xb  [(size_t)NB * NL * NE];        // bf16 x
__device__ __nv_bfloat16 g_wb  [(size_t)2 * NE * NE];         // bf16 w[0:512]
__device__ __nv_bfloat16 g_xTb [(size_t)NB * NE * NL];        // bf16 x^T per b
__device__ __nv_bfloat16 g_WgTb[(size_t)NE * NE];             // bf16 Wg^T
__device__ __nv_bfloat16 g_QKb [(size_t)NB * NL * 2 * NE];    // [16384, 512]
__device__ __nv_bfloat16 g_P   [(size_t)NB * NH * NL * NL];   // exp-scores
__device__ __nv_bfloat16 g_Bmb [(size_t)NB * NL * NL];        // head-mean probs
__device__ __nv_bfloat16 g_AGb [(size_t)NB * NL * NE];        // Bm @ x

// ------------------------------- helpers ------------------------------------
__device__ __forceinline__ uint32_t smem_u32(const void* p) {
    uint32_t a;
    asm("{ .reg .u64 t; cvta.to.shared.u64 t, %1; cvt.u32.u64 %0, t; }"
        : "=r"(a) : "l"(p));
    return a;
}

#define CP_ASYNC16(dst, src) \
    asm volatile("cp.async.cg.shared.global [%0], [%1], 16;" \
                 :: "r"(dst), "l"(src) : "memory")
#define CP_COMMIT() asm volatile("cp.async.commit_group;" ::: "memory")
#define CP_WAIT(n)  asm volatile("cp.async.wait_group %0;" :: "n"(n) : "memory")

#define MMA_BF16(d, a, b)                                                      \
    asm volatile("mma.sync.aligned.m16n8k16.row.col.f32.bf16.bf16.f32 "       \
        "{%0,%1,%2,%3}, {%4,%5,%6,%7}, {%8,%9}, {%0,%1,%2,%3};"                \
        : "+f"((d)[0]), "+f"((d)[1]), "+f"((d)[2]), "+f"((d)[3])               \
        : "r"((a)[0]), "r"((a)[1]), "r"((a)[2]), "r"((a)[3]),                  \
          "r"((b)[0]), "r"((b)[1]))

#define LDSM_X4(r0, r1, r2, r3, addr)                                          \
    asm volatile("ldmatrix.sync.aligned.m8n8.x4.shared.b16 {%0,%1,%2,%3}, [%4];" \
        : "=r"(r0), "=r"(r1), "=r"(r2), "=r"(r3) : "r"(addr))

// ------------------------------- bf16 GEMM ----------------------------------
// C[z] = f(alpha * A_z * B_z^T + bias[col]) ; A [M,K], B [N,K] bf16 K-major.
// CTA tile 128x128, K chunk 64 elems, 8 warps (2x4), warp tile 64x32,
// 3-stage cp.async pipeline, ldmatrix fragment loads, smem-bounce coalesced
// epilogue (16B per thread per global store).
#define STAGES     3
#define STG_BYTES  36864
#define GEMM_SMEM  (STAGES * STG_BYTES)

template <typename OutT, bool EXP_OUT, bool HAS_BIAS>
__global__ __launch_bounds__(256, 2)
void bgemm(const __nv_bfloat16* __restrict__ A, int lda, int a_zo_row, int a_zi_col, int a_col_base,
           const __nv_bfloat16* __restrict__ Bp, int ldb, int b_zo_row, int b_zi_col, int b_col_base,
           OutT* __restrict__ C, int ldc, long sC,
           int inner, int nk, float alpha, const float* __restrict__ bias)
{
    extern __shared__ __align__(16) char smem[];
    const int tid    = threadIdx.x;
    const int warpId = tid >> 5;
    const int lane   = tid & 31;
    const int g  = lane >> 2;
    const int tg = lane & 3;
    const int wr = (warpId & 1) * 64;
    const int wc = (warpId >> 1) * 32;

    const int z  = blockIdx.z;
    const int zo = z / inner;
    const int zi = z - zo * inner;

    const __nv_bfloat16* Ag = A  + ((long)zo * a_zo_row + (long)blockIdx.y * 128) * lda
                                 + a_col_base + zi * a_zi_col;
    const __nv_bfloat16* Bg = Bp + ((long)zo * b_zo_row + (long)blockIdx.x * 128) * ldb
                                 + b_col_base + zi * b_zi_col;

    const uint32_t sbase = smem_u32(smem);

    // per-thread ldmatrix base offsets (bytes), relative to stage A/B starts
    const uint32_t a_loff = ((wr + (lane & 15)) * 36 + ((lane >> 4) * 4)) * 4;
    const uint32_t b_loff = ((wc + (lane & 7) + ((lane >> 4) << 3)) * 36
                             + (((lane >> 3) & 1) * 4)) * 4;

    auto load_stage = [&](int st, int kc) {
        const uint32_t da = sbase + st * STG_BYTES;
        const __nv_bfloat16* a = Ag + kc * 64;
        const __nv_bfloat16* b = Bg + kc * 64;
#pragma unroll
        for (int i = 0; i < 4; i++) {
            const int idx = tid + 256 * i;
            const int row = idx >> 3, c4 = idx & 7;
            CP_ASYNC16(da + row * 144 + c4 * 16, a + (long)row * lda + c4 * 8);
        }
#pragma unroll
        for (int i = 0; i < 4; i++) {
            const int idx = tid + 256 * i;
            const int row = idx >> 3, c4 = idx & 7;
            CP_ASYNC16(da + 18432 + row * 144 + c4 * 16, b + (long)row * ldb + c4 * 8);
        }
    };

    float acc[4][4][4];
#pragma unroll
    for (int m = 0; m < 4; m++)
#pragma unroll
        for (int n = 0; n < 4; n++)
#pragma unroll
            for (int c = 0; c < 4; c++) acc[m][n][c] = 0.f;

    load_stage(0, 0);
    CP_COMMIT();
    if (nk > 1) { load_stage(1, 1); CP_COMMIT(); }

    int stage = 0;
    for (int i = 0; i < nk; i++) {
        if (i + 1 < nk) { CP_WAIT(1); } else { CP_WAIT(0); }
        __syncthreads();

        if (i + 2 < nk) {
            int ns = stage + 2; if (ns >= STAGES) ns -= STAGES;
            load_stage(ns, i + 2);
            CP_COMMIT();
        }

        const uint32_t sA = sbase + stage * STG_BYTES + a_loff;
        const uint32_t sB = sbase + stage * STG_BYTES + 18432 + b_loff;

#pragma unroll
        for (int j = 0; j < 4; j++) {           // 4 x k16 steps
            uint32_t af[4][4], bf[4][2];
#pragma unroll
            for (int mt = 0; mt < 4; mt++)
                LDSM_X4(af[mt][0], af[mt][1], af[mt][2], af[mt][3],
                        sA + mt * (16 * 36 * 4) + j * 32);
#pragma unroll
            for (int p = 0; p < 2; p++)
                LDSM_X4(bf[2 * p][0], bf[2 * p][1], bf[2 * p + 1][0], bf[2 * p + 1][1],
                        sB + p * (16 * 36 * 4) + j * 32);
#pragma unroll
            for (int mt = 0; mt < 4; mt++)
#pragma unroll
                for (int nt = 0; nt < 4; nt++)
                    MMA_BF16(acc[mt][nt], af[mt], bf[nt]);
        }

        if (++stage == STAGES) stage = 0;
    }

    // ---- epilogue: smem bounce -> coalesced 16B stores ----
    __syncthreads();   // stage buffers now reusable as bounce buffer

    OutT* Cz = C + (long)z * sC;
    const long crow0 = (long)blockIdx.y * 128;
    const int  ccol0 = blockIdx.x * 128;

    if (sizeof(OutT) == 2) {
        // bf16 out: bounce rows 128 x 272B (136 bf16, 68-word stride)
        __nv_bfloat16* Sb = (__nv_bfloat16*)smem;
#pragma unroll
        for (int mt = 0; mt < 4; mt++) {
#pragma unroll
            for (int nt = 0; nt < 4; nt++) {
                const int r = wr + mt * 16 + g;
                const int c = wc + nt * 8 + tg * 2;
                float b0 = 0.f, b1 = 0.f;
                if (HAS_BIAS) { b0 = bias[ccol0 + c]; b1 = bias[ccol0 + c + 1]; }
                float v00 = acc[mt][nt][0] * alpha + b0;
                float v01 = acc[mt][nt][1] * alpha + b1;
                float v10 = acc[mt][nt][2] * alpha + b0;
                float v11 = acc[mt][nt][3] * alpha + b1;
                if (EXP_OUT) {
                    v00 = __expf(v00); v01 = __expf(v01);
                    v10 = __expf(v10); v11 = __expf(v11);
                }
                *(__nv_bfloat162*)(Sb + (long)r * 136 + c)       = __floats2bfloat162_rn(v00, v01);
                *(__nv_bfloat162*)(Sb + (long)(r + 8) * 136 + c) = __floats2bfloat162_rn(v10, v11);
            }
        }
        __syncthreads();
#pragma unroll
        for (int it = 0; it < 8; it++) {
            const int idx = it * 256 + tid;
            const int row = idx >> 4;
            const int c16 = idx & 15;
            float4 v = *(float4*)(Sb + (long)row * 136 + c16 * 8);
            *(float4*)((__nv_bfloat16*)Cz + (crow0 + row) * ldc + ccol0 + c16 * 8) = v;
        }
    } else {
        // fp32 out: bounce rows 128 x 528B (132-word stride)
        float* Sb = (float*)smem;
#pragma unroll
        for (int mt = 0; mt < 4; mt++) {
#pragma unroll
            for (int nt = 0; nt < 4; nt++) {
                const int r = wr + mt * 16 + g;
                const int c = wc + nt * 8 + tg * 2;
                float b0 = 0.f, b1 = 0.f;
                if (HAS_BIAS) { b0 = bias[ccol0 + c]; b1 = bias[ccol0 + c + 1]; }
                float v00 = acc[mt][nt][0] * alpha + b0;
                float v01 = acc[mt][nt][1] * alpha + b1;
                float v10 = acc[mt][nt][2] * alpha + b0;
                float v11 = acc[mt][nt][3] * alpha + b1;
                if (EXP_OUT) {
                    v00 = __expf(v00); v01 = __expf(v01);
                    v10 = __expf(v10); v11 = __expf(v11);
                }
                *(float2*)(Sb + (long)r * 132 + c)       = make_float2(v00, v01);
                *(float2*)(Sb + (long)(r + 8) * 132 + c) = make_float2(v10, v11);
            }
        }
        __syncthreads();
#pragma unroll
        for (int it = 0; it < 16; it++) {
            const int idx = it * 256 + tid;
            const int row = idx >> 5;
            const int c4  = idx & 31;
            float4 v = *(float4*)(Sb + (long)row * 132 + c4 * 4);
            *(float4*)((float*)Cz + (crow0 + row) * ldc + ccol0 + c4 * 4) = v;
        }
    }
}

// ---------------------------------------------------------------------------
// head-mean of normalized exp-scores:
// Bm[b,i,j] = sum_h P[b,h,i,j] / (4 * sum_j' P[b,h,i,j'])
__device__ __forceinline__ float warp_sum(float v) {
#pragma unroll
    for (int o = 16; o; o >>= 1) v += __shfl_xor_sync(0xffffffffu, v, o);
    return v;
}

__global__ __launch_bounds__(256)
void pmean_kernel(const __nv_bfloat16* __restrict__ P, __nv_bfloat16* __restrict__ Bm)
{
    __shared__ float red[8];
    const int bi   = blockIdx.x;
    const int b    = bi >> 11;
    const int i    = bi & 2047;
    const int tid  = threadIdx.x;
    const int wid  = tid >> 5;
    const int lane = tid & 31;

    float acc[8] = {0, 0, 0, 0, 0, 0, 0, 0};

    for (int h = 0; h < NH; h++) {
        const __nv_bfloat16* row = P + (((long)(b * NH + h)) * NL + i) * NL;
        union { float4 f; __nv_bfloat162 hh[4]; } u;
        u.f = *(const float4*)(row + tid * 8);
        float v[8];
#pragma unroll
        for (int j = 0; j < 4; j++) {
            float2 p = __bfloat1622float2(u.hh[j]);
            v[2 * j] = p.x; v[2 * j + 1] = p.y;
        }
        float s = 0.f;
#pragma unroll
        for (int j = 0; j < 8; j++) s += v[j];
        s = warp_sum(s);
        if (lane == 0) red[wid] = s;
        __syncthreads();
        float st = red[0];
#pragma unroll
        for (int w = 1; w < 8; w++) st += red[w];

        const float inv = 0.25f / st;
#pragma unroll
        for (int j = 0; j < 8; j++) acc[j] += v[j] * inv;
        __syncthreads();
    }

    union { float4 f; __nv_bfloat162 hh[4]; } o;
#pragma unroll
    for (int j = 0; j < 4; j++)
        o.hh[j] = __floats2bfloat162_rn(acc[2 * j], acc[2 * j + 1]);
    *(float4*)(Bm + (long)bi * NL + tid * 8) = o.f;
}

// ---------------------------------------------------------------------------
// prepasses: fp32 -> bf16 convert (and fused transpose+convert reading once)
__global__ void cvt_bf16_kernel(const float* __restrict__ in,
                                __nv_bfloat16* __restrict__ out, long n)
{
    const long i = ((long)blockIdx.x * blockDim.x + threadIdx.x) * 4;
    if (i < n) {
        float4 v = *(const float4*)(in + i);
        union { uint2 u; __nv_bfloat162 h[2]; } p;
        p.h[0] = __floats2bfloat162_rn(v.x, v.y);
        p.h[1] = __floats2bfloat162_rn(v.z, v.w);
        *(uint2*)(out + i) = p.u;
    }
}

// reads x once: writes bf16 copy (outN, may be null) and bf16 transpose (outT)
__global__ void transpose_cvt_kernel(const float* __restrict__ in,
                                     __nv_bfloat16* __restrict__ outT,
                                     __nv_bfloat16* __restrict__ outN,
                                     int R, int Cn)
{
    __shared__ float t[32][33];
    in   += (size_t)blockIdx.z * R * Cn;
    outT += (size_t)blockIdx.z * R * Cn;
    if (outN) outN += (size_t)blockIdx.z * R * Cn;
    const int r0 = blockIdx.y * 32, c0 = blockIdx.x * 32;
    const int x = threadIdx.x, y = threadIdx.y;
#pragma unroll
    for (int i = 0; i < 32; i += 8) {
        const float v = in[(long)(r0 + y + i) * Cn + c0 + x];
        t[y + i][x] = v;
        if (outN) outN[(long)(r0 + y + i) * Cn + c0 + x] = __float2bfloat16_rn(v);
    }
    __syncthreads();
#pragma unroll
    for (int i = 0; i < 32; i += 8)
        outT[(long)(c0 + y + i) * R + r0 + x] = __float2bfloat16_rn(t[x][y + i]);
}

// ---------------------------------------------------------------------------
extern "C" void kernel_launch(void* const* d_in, const int* in_sizes, int n_in,
                              void* d_out, int out_size)
{
    (void)in_sizes; (void)n_in; (void)out_size;
    const float* x   = (const float*)d_in[0];
    const float* w   = (const float*)d_in[1];
    const float* bia = (const float*)d_in[2];
    const float* Wg  = (const float*)d_in[3];
    const float* Bg  = (const float*)d_in[4];
    float* out = (float*)d_out;

    __nv_bfloat16 *xb, *wb, *xTb, *WgTb, *QKb, *P, *Bmb, *AGb;
    cudaGetSymbolAddress((void**)&xb,   g_xb);
    cudaGetSymbolAddress((void**)&wb,   g_wb);
    cudaGetSymbolAddress((void**)&xTb,  g_xTb);
    cudaGetSymbolAddress((void**)&WgTb, g_WgTb);
    cudaGetSymbolAddress((void**)&QKb,  g_QKb);
    cudaGetSymbolAddress((void**)&P,    g_P);
    cudaGetSymbolAddress((void**)&Bmb,  g_Bmb);
    cudaGetSymbolAddress((void**)&AGb,  g_AGb);

    cudaFuncSetAttribute((const void*)bgemm<__nv_bfloat16, false, true >,
                         cudaFuncAttributeMaxDynamicSharedMemorySize, GEMM_SMEM);
    cudaFuncSetAttribute((const void*)bgemm<__nv_bfloat16, true,  false>,
                         cudaFuncAttributeMaxDynamicSharedMemorySize, GEMM_SMEM);
    cudaFuncSetAttribute((const void*)bgemm<__nv_bfloat16, false, false>,
                         cudaFuncAttributeMaxDynamicSharedMemorySize, GEMM_SMEM);
    cudaFuncSetAttribute((const void*)bgemm<float, false, true>,
                         cudaFuncAttributeMaxDynamicSharedMemorySize, GEMM_SMEM);

    // 0) bf16 operand prep (x read once -> xb + xTb)
    {
        transpose_cvt_kernel<<<dim3(NE / 32, NL / 32, NB), dim3(32, 8)>>>(x, xTb, xb, NL, NE);
        const long nw = (long)2 * NE * NE;
        cvt_bf16_kernel<<<(int)((nw / 4 + 255) / 256), 256>>>(w, wb, nw);
        transpose_cvt_kernel<<<dim3(NE / 32, NE / 32, 1), dim3(32, 8)>>>(Wg, WgTb, nullptr, NE, NE);
    }

    // 1) QK = xb @ wb^T + bias   [16384 x 512], K=256 (nk=4)
    bgemm<__nv_bfloat16, false, true><<<dim3(4, 128, 1), 256, GEMM_SMEM>>>(
        xb, NE, 0, 0, 0,
        wb, NE, 0, 0, 0,
        QKb, 2 * NE, 0,
        1, NE / 64, 1.f, bia);

    // 2) P[b*4+h] = exp(0.125 * q_h @ k_h^T)   [2048 x 2048] x32, K=64 (nk=1)
    bgemm<__nv_bfloat16, true, false><<<dim3(16, 16, NB * NH), 256, GEMM_SMEM>>>(
        QKb, 2 * NE, NL, ND, 0,
        QKb, 2 * NE, NL, ND, NE,
        P, NL, (long)NL * NL,
        NH, 1, 0.125f, nullptr);

    // 3) Bm[b,i,:] = mean_h P[b,h,i,:] / rowsum
    pmean_kernel<<<NB * NL, 256>>>(P, Bmb);

    // 4) AG[b] = Bm[b] @ xTb[b]^T   [2048 x 256] x8, K=2048 (nk=32)
    bgemm<__nv_bfloat16, false, false><<<dim3(2, 16, NB), 256, GEMM_SMEM>>>(
        Bmb, NL, NL, 0, 0,
        xTb, NL, NE, 0, 0,
        AGb, NE, (long)NL * NE,
        1, NL / 64, 1.f, nullptr);

    // 5) out = AG @ WgTb^T + Bg    [16384 x 256], K=256 (nk=4)
    bgemm<float, false, true><<<dim3(2, 128, 1), 256, GEMM_SMEM>>>(
        AGb, NE, 0, 0, 0,
        WgTb, NE, 0, 0, 0,
        out, NE, 0,
        1, NE / 64, 1.f, Bg);
}

// round 9
// speedup vs baseline: 1.7447x; 1.0764x over previous
#include <cuda_runtime.h>
#include <cuda_bf16.h>
#include <cstdint>

#define NB 8
#define NL 2048
#define NE 256
#define NH 4
#define ND 64

// ---------------- scratch (device globals; no allocation allowed) -----------
__device__ __nv_bfloat16 g_xb  [(size_t)NB * NL * NE];        // bf16 x
__device__ __nv_bfloat16 g_wb  [(size_t)2 * NE * NE];         // bf16 w[0:512]
__device__ __nv_bfloat16 g_xTb [(size_t)NB * NE * NL];        // bf16 x^T per b
__device__ __nv_bfloat16 g_WgTb[(size_t)NE * NE];             // bf16 Wg^T
__device__ __nv_bfloat16 g_QKb [(size_t)NB * NL * 2 * NE];    // [16384, 512]
__device__ __nv_bfloat16 g_P   [(size_t)NB * NH * NL * NL];   // exp-scores
__device__ __nv_bfloat16 g_Bmb [(size_t)NB * NL * NL];        // head-mean probs
__device__ __nv_bfloat16 g_yT  [(size_t)NB * NE * NL];        // (x @ Wg)^T per b

// ------------------------------- helpers ------------------------------------
__device__ __forceinline__ uint32_t smem_u32(const void* p) {
    uint32_t a;
    asm("{ .reg .u64 t; cvta.to.shared.u64 t, %1; cvt.u32.u64 %0, t; }"
        : "=r"(a) : "l"(p));
    return a;
}

#define CP_ASYNC16(dst, src) \
    asm volatile("cp.async.cg.shared.global [%0], [%1], 16;" \
                 :: "r"(dst), "l"(src) : "memory")
#define CP_COMMIT() asm volatile("cp.async.commit_group;" ::: "memory")
#define CP_WAIT(n)  asm volatile("cp.async.wait_group %0;" :: "n"(n) : "memory")

#define MMA_BF16(d, a, b)                                                      \
    asm volatile("mma.sync.aligned.m16n8k16.row.col.f32.bf16.bf16.f32 "       \
        "{%0,%1,%2,%3}, {%4,%5,%6,%7}, {%8,%9}, {%0,%1,%2,%3};"                \
        : "+f"((d)[0]), "+f"((d)[1]), "+f"((d)[2]), "+f"((d)[3])               \
        : "r"((a)[0]), "r"((a)[1]), "r"((a)[2]), "r"((a)[3]),                  \
          "r"((b)[0]), "r"((b)[1]))

#define LDSM_X4(r0, r1, r2, r3, addr)                                          \
    asm volatile("ldmatrix.sync.aligned.m8n8.x4.shared.b16 {%0,%1,%2,%3}, [%4];" \
        : "=r"(r0), "=r"(r1), "=r"(r2), "=r"(r3) : "r"(addr))

// ------------------------------- bf16 GEMM ----------------------------------
// C[z] = f(alpha * A_z * B_z^T + bias[col]) ; A [M,K], B [N,K] bf16 K-major.
// CTA tile 128x128, K chunk 64 elems, 8 warps (2x4), warp tile 64x32,
// 3-stage cp.async pipeline, ldmatrix fragment loads, smem-bounce coalesced
// epilogue (16B per thread per global store).
#define STAGES     3
#define STG_BYTES  36864
#define GEMM_SMEM  (STAGES * STG_BYTES)

template <typename OutT, bool EXP_OUT, bool HAS_BIAS>
__global__ __launch_bounds__(256, 2)
void bgemm(const __nv_bfloat16* __restrict__ A, int lda, int a_zo_row, int a_zi_col, int a_col_base,
           const __nv_bfloat16* __restrict__ Bp, int ldb, int b_zo_row, int b_zi_col, int b_col_base,
           OutT* __restrict__ C, int ldc, long sC,
           int inner, int nk, float alpha, const float* __restrict__ bias)
{
    extern __shared__ __align__(16) char smem[];
    const int tid    = threadIdx.x;
    const int warpId = tid >> 5;
    const int lane   = tid & 31;
    const int g  = lane >> 2;
    const int tg = lane & 3;
    const int wr = (warpId & 1) * 64;
    const int wc = (warpId >> 1) * 32;

    const int z  = blockIdx.z;
    const int zo = z / inner;
    const int zi = z - zo * inner;

    const __nv_bfloat16* Ag = A  + ((long)zo * a_zo_row + (long)blockIdx.y * 128) * lda
                                 + a_col_base + zi * a_zi_col;
    const __nv_bfloat16* Bg = Bp + ((long)zo * b_zo_row + (long)blockIdx.x * 128) * ldb
                                 + b_col_base + zi * b_zi_col;

    const uint32_t sbase = smem_u32(smem);

    // per-thread ldmatrix base offsets (bytes), relative to stage A/B starts
    const uint32_t a_loff = ((wr + (lane & 15)) * 36 + ((lane >> 4) * 4)) * 4;
    const uint32_t b_loff = ((wc + (lane & 7) + ((lane >> 4) << 3)) * 36
                             + (((lane >> 3) & 1) * 4)) * 4;

    auto load_stage = [&](int st, int kc) {
        const uint32_t da = sbase + st * STG_BYTES;
        const __nv_bfloat16* a = Ag + kc * 64;
        const __nv_bfloat16* b = Bg + kc * 64;
#pragma unroll
        for (int i = 0; i < 4; i++) {
            const int idx = tid + 256 * i;
            const int row = idx >> 3, c4 = idx & 7;
            CP_ASYNC16(da + row * 144 + c4 * 16, a + (long)row * lda + c4 * 8);
        }
#pragma unroll
        for (int i = 0; i < 4; i++) {
            const int idx = tid + 256 * i;
            const int row = idx >> 3, c4 = idx & 7;
            CP_ASYNC16(da + 18432 + row * 144 + c4 * 16, b + (long)row * ldb + c4 * 8);
        }
    };

    float acc[4][4][4];
#pragma unroll
    for (int m = 0; m < 4; m++)
#pragma unroll
        for (int n = 0; n < 4; n++)
#pragma unroll
            for (int c = 0; c < 4; c++) acc[m][n][c] = 0.f;

    load_stage(0, 0);
    CP_COMMIT();
    if (nk > 1) { load_stage(1, 1); CP_COMMIT(); }

    int stage = 0;
    for (int i = 0; i < nk; i++) {
        if (i + 1 < nk) { CP_WAIT(1); } else { CP_WAIT(0); }
        __syncthreads();

        if (i + 2 < nk) {
            int ns = stage + 2; if (ns >= STAGES) ns -= STAGES;
            load_stage(ns, i + 2);
            CP_COMMIT();
        }

        const uint32_t sA = sbase + stage * STG_BYTES + a_loff;
        const uint32_t sB = sbase + stage * STG_BYTES + 18432 + b_loff;

#pragma unroll
        for (int j = 0; j < 4; j++) {           // 4 x k16 steps
            uint32_t af[4][4], bf[4][2];
#pragma unroll
            for (int mt = 0; mt < 4; mt++)
                LDSM_X4(af[mt][0], af[mt][1], af[mt][2], af[mt][3],
                        sA + mt * (16 * 36 * 4) + j * 32);
#pragma unroll
            for (int p = 0; p < 2; p++)
                LDSM_X4(bf[2 * p][0], bf[2 * p][1], bf[2 * p + 1][0], bf[2 * p + 1][1],
                        sB + p * (16 * 36 * 4) + j * 32);
#pragma unroll
            for (int mt = 0; mt < 4; mt++)
#pragma unroll
                for (int nt = 0; nt < 4; nt++)
                    MMA_BF16(acc[mt][nt], af[mt], bf[nt]);
        }

        if (++stage == STAGES) stage = 0;
    }

    // ---- epilogue: smem bounce -> coalesced 16B stores ----
    __syncthreads();   // stage buffers now reusable as bounce buffer

    OutT* Cz = C + (long)z * sC;
    const long crow0 = (long)blockIdx.y * 128;
    const int  ccol0 = blockIdx.x * 128;

    if (sizeof(OutT) == 2) {
        // bf16 out: bounce rows 128 x 272B (136 bf16 stride)
        __nv_bfloat16* Sb = (__nv_bfloat16*)smem;
#pragma unroll
        for (int mt = 0; mt < 4; mt++) {
#pragma unroll
            for (int nt = 0; nt < 4; nt++) {
                const int r = wr + mt * 16 + g;
                const int c = wc + nt * 8 + tg * 2;
                float b0 = 0.f, b1 = 0.f;
                if (HAS_BIAS) { b0 = bias[ccol0 + c]; b1 = bias[ccol0 + c + 1]; }
                float v00 = acc[mt][nt][0] * alpha + b0;
                float v01 = acc[mt][nt][1] * alpha + b1;
                float v10 = acc[mt][nt][2] * alpha + b0;
                float v11 = acc[mt][nt][3] * alpha + b1;
                if (EXP_OUT) {
                    v00 = __expf(v00); v01 = __expf(v01);
                    v10 = __expf(v10); v11 = __expf(v11);
                }
                *(__nv_bfloat162*)(Sb + (long)r * 136 + c)       = __floats2bfloat162_rn(v00, v01);
                *(__nv_bfloat162*)(Sb + (long)(r + 8) * 136 + c) = __floats2bfloat162_rn(v10, v11);
            }
        }
        __syncthreads();
#pragma unroll
        for (int it = 0; it < 8; it++) {
            const int idx = it * 256 + tid;
            const int row = idx >> 4;
            const int c16 = idx & 15;
            float4 v = *(float4*)(Sb + (long)row * 136 + c16 * 8);
            *(float4*)((__nv_bfloat16*)Cz + (crow0 + row) * ldc + ccol0 + c16 * 8) = v;
        }
    } else {
        // fp32 out: bounce rows 128 x 528B (132-word stride)
        float* Sb = (float*)smem;
#pragma unroll
        for (int mt = 0; mt < 4; mt++) {
#pragma unroll
            for (int nt = 0; nt < 4; nt++) {
                const int r = wr + mt * 16 + g;
                const int c = wc + nt * 8 + tg * 2;
                float b0 = 0.f, b1 = 0.f;
                if (HAS_BIAS) { b0 = bias[ccol0 + c]; b1 = bias[ccol0 + c + 1]; }
                float v00 = acc[mt][nt][0] * alpha + b0;
                float v01 = acc[mt][nt][1] * alpha + b1;
                float v10 = acc[mt][nt][2] * alpha + b0;
                float v11 = acc[mt][nt][3] * alpha + b1;
                if (EXP_OUT) {
                    v00 = __expf(v00); v01 = __expf(v01);
                    v10 = __expf(v10); v11 = __expf(v11);
                }
                *(float2*)(Sb + (long)r * 132 + c)       = make_float2(v00, v01);
                *(float2*)(Sb + (long)(r + 8) * 132 + c) = make_float2(v10, v11);
            }
        }
        __syncthreads();
#pragma unroll
        for (int it = 0; it < 16; it++) {
            const int idx = it * 256 + tid;
            const int row = idx >> 5;
            const int c4  = idx & 31;
            float4 v = *(float4*)(Sb + (long)row * 132 + c4 * 4);
            *(float4*)((float*)Cz + (crow0 + row) * ldc + ccol0 + c4 * 4) = v;
        }
    }
}

// ---------------------------------------------------------------------------
// head-mean of normalized exp-scores, de-serialized:
// Bm[b,i,j] = sum_h P[b,h,i,j] / (4 * sum_j' P[b,h,i,j'])
// All 4 head loads issued upfront (MLP=4); one smem round, one barrier.
__global__ __launch_bounds__(256)
void pmean_kernel(const __nv_bfloat16* __restrict__ P, __nv_bfloat16* __restrict__ Bm)
{
    __shared__ float red[8][4];
    const int bi   = blockIdx.x;
    const int b    = bi >> 11;
    const int i    = bi & 2047;
    const int tid  = threadIdx.x;
    const int wid  = tid >> 5;
    const int lane = tid & 31;

    const __nv_bfloat16* base = P + ((long)b * NH * NL + i) * NL + tid * 8;

    union { float4 f; __nv_bfloat162 hh[4]; } u[NH];
#pragma unroll
    for (int h = 0; h < NH; h++)
        u[h].f = *(const float4*)(base + (long)h * NL * NL);

    float v[NH][8], s[NH];
#pragma unroll
    for (int h = 0; h < NH; h++) {
        float sum = 0.f;
#pragma unroll
        for (int j = 0; j < 4; j++) {
            float2 p = __bfloat1622float2(u[h].hh[j]);
            v[h][2 * j] = p.x; v[h][2 * j + 1] = p.y;
            sum += p.x + p.y;
        }
#pragma unroll
        for (int o = 16; o; o >>= 1)
            sum += __shfl_xor_sync(0xffffffffu, sum, o);
        s[h] = sum;
    }
    if (lane < 4) red[wid][lane] = s[lane];
    __syncthreads();

    float inv[NH];
#pragma unroll
    for (int h = 0; h < NH; h++) {
        float st = red[0][h];
#pragma unroll
        for (int w = 1; w < 8; w++) st += red[w][h];
        inv[h] = 0.25f / st;
    }

    float acc[8];
#pragma unroll
    for (int j = 0; j < 8; j++) {
        acc[j] = v[0][j] * inv[0];
#pragma unroll
        for (int h = 1; h < NH; h++) acc[j] += v[h][j] * inv[h];
    }

    union { float4 f; __nv_bfloat162 hh[4]; } o;
#pragma unroll
    for (int j = 0; j < 4; j++)
        o.hh[j] = __floats2bfloat162_rn(acc[2 * j], acc[2 * j + 1]);
    *(float4*)(Bm + (long)bi * NL + tid * 8) = o.f;
}

// ---------------------------------------------------------------------------
// prepasses: fp32 -> bf16 convert (and fused transpose+convert reading once)
__global__ void cvt_bf16_kernel(const float* __restrict__ in,
                                __nv_bfloat16* __restrict__ out, long n)
{
    const long i = ((long)blockIdx.x * blockDim.x + threadIdx.x) * 4;
    if (i < n) {
        float4 v = *(const float4*)(in + i);
        union { uint2 u; __nv_bfloat162 h[2]; } p;
        p.h[0] = __floats2bfloat162_rn(v.x, v.y);
        p.h[1] = __floats2bfloat162_rn(v.z, v.w);
        *(uint2*)(out + i) = p.u;
    }
}

// reads x once: writes bf16 copy (outN, may be null) and bf16 transpose (outT)
__global__ void transpose_cvt_kernel(const float* __restrict__ in,
                                     __nv_bfloat16* __restrict__ outT,
                                     __nv_bfloat16* __restrict__ outN,
                                     int R, int Cn)
{
    __shared__ float t[32][33];
    in   += (size_t)blockIdx.z * R * Cn;
    outT += (size_t)blockIdx.z * R * Cn;
    if (outN) outN += (size_t)blockIdx.z * R * Cn;
    const int r0 = blockIdx.y * 32, c0 = blockIdx.x * 32;
    const int x = threadIdx.x, y = threadIdx.y;
#pragma unroll
    for (int i = 0; i < 32; i += 8) {
        const float v = in[(long)(r0 + y + i) * Cn + c0 + x];
        t[y + i][x] = v;
        if (outN) outN[(long)(r0 + y + i) * Cn + c0 + x] = __float2bfloat16_rn(v);
    }
    __syncthreads();
#pragma unroll
    for (int i = 0; i < 32; i += 8)
        outT[(long)(c0 + y + i) * R + r0 + x] = __float2bfloat16_rn(t[x][y + i]);
}

// ---------------------------------------------------------------------------
extern "C" void kernel_launch(void* const* d_in, const int* in_sizes, int n_in,
                              void* d_out, int out_size)
{
    (void)in_sizes; (void)n_in; (void)out_size;
    const float* x   = (const float*)d_in[0];
    const float* w   = (const float*)d_in[1];
    const float* bia = (const float*)d_in[2];
    const float* Wg  = (const float*)d_in[3];
    const float* Bg  = (const float*)d_in[4];
    float* out = (float*)d_out;

    __nv_bfloat16 *xb, *wb, *xTb, *WgTb, *QKb, *P, *Bmb, *yT;
    cudaGetSymbolAddress((void**)&xb,   g_xb);
    cudaGetSymbolAddress((void**)&wb,   g_wb);
    cudaGetSymbolAddress((void**)&xTb,  g_xTb);
    cudaGetSymbolAddress((void**)&WgTb, g_WgTb);
    cudaGetSymbolAddress((void**)&QKb,  g_QKb);
    cudaGetSymbolAddress((void**)&P,    g_P);
    cudaGetSymbolAddress((void**)&Bmb,  g_Bmb);
    cudaGetSymbolAddress((void**)&yT,   g_yT);

    cudaFuncSetAttribute((const void*)bgemm<__nv_bfloat16, false, true >,
                         cudaFuncAttributeMaxDynamicSharedMemorySize, GEMM_SMEM);
    cudaFuncSetAttribute((const void*)bgemm<__nv_bfloat16, true,  false>,
                         cudaFuncAttributeMaxDynamicSharedMemorySize, GEMM_SMEM);
    cudaFuncSetAttribute((const void*)bgemm<__nv_bfloat16, false, false>,
                         cudaFuncAttributeMaxDynamicSharedMemorySize, GEMM_SMEM);
    cudaFuncSetAttribute((const void*)bgemm<float, false, true>,
                         cudaFuncAttributeMaxDynamicSharedMemorySize, GEMM_SMEM);

    // 0) bf16 operand prep (x read once -> xb + xTb ; Wg -> WgTb)
    {
        transpose_cvt_kernel<<<dim3(NE / 32, NL / 32, NB), dim3(32, 8)>>>(x, xTb, xb, NL, NE);
        const long nw = (long)2 * NE * NE;
        cvt_bf16_kernel<<<(int)((nw / 4 + 255) / 256), 256>>>(w, wb, nw);
        transpose_cvt_kernel<<<dim3(NE / 32, NE / 32, 1), dim3(32, 8)>>>(Wg, WgTb, nullptr, NE, NE);
    }

    // 1) yT[b] = Wg^T @ x[b]^T  == (x[b] @ Wg)^T   [256 x 2048] x8, K=256 (nk=4)
    bgemm<__nv_bfloat16, false, false><<<dim3(16, 2, NB), 256, GEMM_SMEM>>>(
        WgTb, NE, 0, 0, 0,
        xb,   NE, NL, 0, 0,
        yT, NL, (long)NE * NL,
        1, NE / 64, 1.f, nullptr);

    // 2) QK = xb @ wb^T + bias   [16384 x 512], K=256 (nk=4)
    bgemm<__nv_bfloat16, false, true><<<dim3(4, 128, 1), 256, GEMM_SMEM>>>(
        xb, NE, 0, 0, 0,
        wb, NE, 0, 0, 0,
        QKb, 2 * NE, 0,
        1, NE / 64, 1.f, bia);

    // 3) P[b*4+h] = exp(0.125 * q_h @ k_h^T)   [2048 x 2048] x32, K=64 (nk=1)
    bgemm<__nv_bfloat16, true, false><<<dim3(16, 16, NB * NH), 256, GEMM_SMEM>>>(
        QKb, 2 * NE, NL, ND, 0,
        QKb, 2 * NE, NL, ND, NE,
        P, NL, (long)NL * NL,
        NH, 1, 0.125f, nullptr);

    // 4) Bm[b,i,:] = mean_h P[b,h,i,:] / rowsum
    pmean_kernel<<<NB * NL, 256>>>(P, Bmb);

    // 5) out[b] = Bm[b] @ yT[b]^T + Bg   [2048 x 256] x8, K=2048 (nk=32)
    bgemm<float, false, true><<<dim3(2, 16, NB), 256, GEMM_SMEM>>>(
        Bmb, NL, NL, 0, 0,
        yT,  NL, NE, 0, 0,
        out, NE, (long)NL * NE,
        1, NL / 64, 1.f, Bg);
}

// round 10
// speedup vs baseline: 1.9486x; 1.1169x over previous
#include <cuda_runtime.h>
#include <cuda.h>
#include <cuda_bf16.h>
#include <cstdint>

#define NB 8
#define NL 2048
#define NE 256
#define NH 4
#define ND 64

// ---------------- scratch (device globals; no allocation allowed) -----------
__device__ __nv_bfloat16 g_xb  [(size_t)NB * NL * NE];        // bf16 x
__device__ __nv_bfloat16 g_wb  [(size_t)2 * NE * NE];         // bf16 w[0:512]
__device__ __nv_bfloat16 g_xTb [(size_t)NB * NE * NL];        // bf16 x^T per b
__device__ __nv_bfloat16 g_WgTb[(size_t)NE * NE];             // bf16 Wg^T
__device__ __nv_bfloat16 g_QKb [(size_t)NB * NL * 2 * NE];    // [16384, 512]
__device__ __nv_bfloat16 g_P   [(size_t)NB * NH * NL * NL];   // exp-scores
__device__ __nv_bfloat16 g_Bmb [(size_t)NB * NL * NL];        // head-mean probs
__device__ __nv_bfloat16 g_yT  [(size_t)NB * NE * NL];        // (x @ Wg)^T per b

// ------------------------------- helpers ------------------------------------
__device__ __forceinline__ uint32_t smem_u32(const void* p) {
    uint32_t a;
    asm("{ .reg .u64 t; cvta.to.shared.u64 t, %1; cvt.u32.u64 %0, t; }"
        : "=r"(a) : "l"(p));
    return a;
}

#define MBARRIER_INIT(addr, cnt) \
    asm volatile("mbarrier.init.shared.b64 [%0], %1;" :: "r"(addr), "r"(cnt) : "memory")

#define MBARRIER_EXPECT_TX(addr, bytes) \
    asm volatile("mbarrier.arrive.expect_tx.shared.b64 _, [%0], %1;" \
                 :: "r"(addr), "r"(bytes) : "memory")

#define MBARRIER_WAIT_PARITY(addr, par) do {                                   \
    uint32_t _m = (addr), _p = (par), _d;                                      \
    asm volatile("{\n\t.reg .pred p;\n\t"                                      \
        "mbarrier.try_wait.parity.acquire.cta.shared::cta.b64 p, [%1], %2;\n\t"\
        "selp.b32 %0, 1, 0, p;\n\t}"                                           \
        : "=r"(_d) : "r"(_m), "r"(_p) : "memory");                             \
    if (!_d) {                                                                 \
        asm volatile("{\n\t.reg .pred P1;\n\t"                                 \
        "WL_%=:\n\t"                                                           \
        "mbarrier.try_wait.parity.acquire.cta.shared::cta.b64 P1, [%0], %1, 0x989680;\n\t" \
        "@P1 bra.uni WD_%=;\n\t"                                               \
        "bra.uni WL_%=;\n\t"                                                   \
        "WD_%=:\n\t}" :: "r"(_m), "r"(_p) : "memory");                         \
    }                                                                          \
} while (0)

#define TMA_LOAD_2D(saddr, tmap, cx, cy, mbar)                                 \
    asm volatile("cp.async.bulk.tensor.2d.shared::cta.global.tile.mbarrier::complete_tx::bytes " \
        "[%0], [%1, {%2, %3}], [%4];"                                          \
        :: "r"((uint32_t)(saddr)), "l"(tmap), "r"((int)(cx)), "r"((int)(cy)),  \
           "r"((uint32_t)(mbar)) : "memory")

#define FENCE_ASYNC_SHARED() asm volatile("fence.proxy.async.shared::cta;" ::: "memory")

#define MMA_BF16(d, a, b)                                                      \
    asm volatile("mma.sync.aligned.m16n8k16.row.col.f32.bf16.bf16.f32 "       \
        "{%0,%1,%2,%3}, {%4,%5,%6,%7}, {%8,%9}, {%0,%1,%2,%3};"                \
        : "+f"((d)[0]), "+f"((d)[1]), "+f"((d)[2]), "+f"((d)[3])               \
        : "r"((a)[0]), "r"((a)[1]), "r"((a)[2]), "r"((a)[3]),                  \
          "r"((b)[0]), "r"((b)[1]))

#define LDSM_X4(r0, r1, r2, r3, addr)                                          \
    asm volatile("ldmatrix.sync.aligned.m8n8.x4.shared.b16 {%0,%1,%2,%3}, [%4];" \
        : "=r"(r0), "=r"(r1), "=r"(r2), "=r"(r3) : "r"(addr))

// ------------------------------- bf16 GEMM ----------------------------------
// C[z] = f(alpha * A_z * B_z^T + bias[col]) ; A [M,K], B [N,K] bf16 K-major,
// loaded via 2D TMA (SW128). CTA tile 128x128, K chunk 64 elems, 8 warps
// (2x4), warp tile 64x32, 3-stage TMA+mbarrier pipeline, ldmatrix with
// closed-form SW128 swizzle, smem-bounce coalesced epilogue.
#define STAGES     3
#define STG_BYTES  32768          // A 16KB + B 16KB, dense SW128 tiles
#define GEMM_SMEM  (STAGES * STG_BYTES + 1024 + 64)

template <typename OutT, bool EXP_OUT, bool HAS_BIAS>
__global__ __launch_bounds__(256, 2)
void bgemm(const __grid_constant__ CUtensorMap tmA,
           const __grid_constant__ CUtensorMap tmB,
           int a_zo_row, int a_zi_col, int a_col_base,
           int b_zo_row, int b_zi_col, int b_col_base,
           OutT* __restrict__ C, int ldc, long sC,
           int inner, int nk, float alpha, const float* __restrict__ bias)
{
    extern __shared__ char smem[];
    const uint32_t sb0 = smem_u32(smem);
    const uint32_t sal = (sb0 + 1023) & ~1023u;   // 1KB-aligned stage base
    const uint32_t mbb = sal + STAGES * STG_BYTES;

    const int tid    = threadIdx.x;
    const int warpId = tid >> 5;
    const int lane   = tid & 31;
    const int g  = lane >> 2;
    const int tg = lane & 3;
    const int wr = (warpId & 1) * 64;
    const int wc = (warpId >> 1) * 32;

    const int z  = blockIdx.z;
    const int zo = z / inner;
    const int zi = z - zo * inner;

    const int ary = zo * a_zo_row + blockIdx.y * 128;
    const int acx = a_col_base + zi * a_zi_col;
    const int bry = zo * b_zo_row + blockIdx.x * 128;
    const int bcx = b_col_base + zi * b_zi_col;

    if (tid == 0) {
#pragma unroll
        for (int s = 0; s < STAGES; s++) MBARRIER_INIT(mbb + s * 8, 1);
        FENCE_ASYNC_SHARED();
    }
    __syncthreads();

    auto issue = [&](int chunk) {
        const int s = chunk % STAGES;
        MBARRIER_EXPECT_TX(mbb + s * 8, (uint32_t)STG_BYTES);
        TMA_LOAD_2D(sal + s * STG_BYTES,         &tmA, acx + chunk * 64, ary, mbb + s * 8);
        TMA_LOAD_2D(sal + s * STG_BYTES + 16384, &tmB, bcx + chunk * 64, bry, mbb + s * 8);
    };

    if (tid == 0) {
        issue(0);
        if (nk > 1) issue(1);
    }

    // ldmatrix swizzled addressing: byte(row, cb) at row*128 + (cb ^ ((row&7)<<4));
    // in both operand maps row ≡ lane (mod 8), so the XOR is a per-thread const.
    const uint32_t xorv  = (uint32_t)((lane & 7) << 4);
    const uint32_t aRow  = (uint32_t)(wr + (lane & 15)) * 128;
    const uint32_t aCol0 = (uint32_t)((lane >> 4) * 16);
    const uint32_t bRow  = (uint32_t)(wc + (lane & 7) + ((lane >> 4) << 3)) * 128;
    const uint32_t bCol0 = (uint32_t)(((lane >> 3) & 1) * 16);

    float acc[4][4][4];
#pragma unroll
    for (int m = 0; m < 4; m++)
#pragma unroll
        for (int n = 0; n < 4; n++)
#pragma unroll
            for (int c = 0; c < 4; c++) acc[m][n][c] = 0.f;

    for (int i = 0; i < nk; i++) {
        const int s  = i % STAGES;
        const int ph = (i / STAGES) & 1;

        __syncthreads();                 // stage (i+2)%3 reads (chunk i-1) done
        if (tid == 0 && i + 2 < nk) issue(i + 2);
        MBARRIER_WAIT_PARITY(mbb + s * 8, ph);

        const uint32_t sA = sal + s * STG_BYTES;
        const uint32_t sB = sA + 16384;

#pragma unroll
        for (int j = 0; j < 4; j++) {    // 4 x k16 steps
            uint32_t af[4][4], bf[4][2];
            const uint32_t ac = (aCol0 + j * 32) ^ xorv;
            const uint32_t bc = (bCol0 + j * 32) ^ xorv;
#pragma unroll
            for (int mt = 0; mt < 4; mt++)
                LDSM_X4(af[mt][0], af[mt][1], af[mt][2], af[mt][3],
                        sA + aRow + mt * 2048 + ac);
#pragma unroll
            for (int p = 0; p < 2; p++)
                LDSM_X4(bf[2 * p][0], bf[2 * p][1], bf[2 * p + 1][0], bf[2 * p + 1][1],
                        sB + bRow + p * 2048 + bc);
#pragma unroll
            for (int mt = 0; mt < 4; mt++)
#pragma unroll
                for (int nt = 0; nt < 4; nt++)
                    MMA_BF16(acc[mt][nt], af[mt], bf[nt]);
        }
    }

    // ---- epilogue: smem bounce -> coalesced 16B stores ----
    __syncthreads();                     // stages now reusable as bounce

    char* bounce = smem + (sal - sb0);
    OutT* Cz = C + (long)z * sC;
    const long crow0 = (long)blockIdx.y * 128;
    const int  ccol0 = blockIdx.x * 128;

    if (sizeof(OutT) == 2) {
        __nv_bfloat16* Sb = (__nv_bfloat16*)bounce;   // 128 x 136 bf16
#pragma unroll
        for (int mt = 0; mt < 4; mt++) {
#pragma unroll
            for (int nt = 0; nt < 4; nt++) {
                const int r = wr + mt * 16 + g;
                const int c = wc + nt * 8 + tg * 2;
                float b0 = 0.f, b1 = 0.f;
                if (HAS_BIAS) { b0 = bias[ccol0 + c]; b1 = bias[ccol0 + c + 1]; }
                float v00 = acc[mt][nt][0] * alpha + b0;
                float v01 = acc[mt][nt][1] * alpha + b1;
                float v10 = acc[mt][nt][2] * alpha + b0;
                float v11 = acc[mt][nt][3] * alpha + b1;
                if (EXP_OUT) {
                    v00 = __expf(v00); v01 = __expf(v01);
                    v10 = __expf(v10); v11 = __expf(v11);
                }
                *(__nv_bfloat162*)(Sb + (long)r * 136 + c)       = __floats2bfloat162_rn(v00, v01);
                *(__nv_bfloat162*)(Sb + (long)(r + 8) * 136 + c) = __floats2bfloat162_rn(v10, v11);
            }
        }
        __syncthreads();
#pragma unroll
        for (int it = 0; it < 8; it++) {
            const int idx = it * 256 + tid;
            const int row = idx >> 4;
            const int c16 = idx & 15;
            float4 v = *(float4*)(Sb + (long)row * 136 + c16 * 8);
            *(float4*)((__nv_bfloat16*)Cz + (crow0 + row) * ldc + ccol0 + c16 * 8) = v;
        }
    } else {
        float* Sb = (float*)bounce;      // 128 x 132 fp32
#pragma unroll
        for (int mt = 0; mt < 4; mt++) {
#pragma unroll
            for (int nt = 0; nt < 4; nt++) {
                const int r = wr + mt * 16 + g;
                const int c = wc + nt * 8 + tg * 2;
                float b0 = 0.f, b1 = 0.f;
                if (HAS_BIAS) { b0 = bias[ccol0 + c]; b1 = bias[ccol0 + c + 1]; }
                float v00 = acc[mt][nt][0] * alpha + b0;
                float v01 = acc[mt][nt][1] * alpha + b1;
                float v10 = acc[mt][nt][2] * alpha + b0;
                float v11 = acc[mt][nt][3] * alpha + b1;
                if (EXP_OUT) {
                    v00 = __expf(v00); v01 = __expf(v01);
                    v10 = __expf(v10); v11 = __expf(v11);
                }
                *(float2*)(Sb + (long)r * 132 + c)       = make_float2(v00, v01);
                *(float2*)(Sb + (long)(r + 8) * 132 + c) = make_float2(v10, v11);
            }
        }
        __syncthreads();
#pragma unroll
        for (int it = 0; it < 16; it++) {
            const int idx = it * 256 + tid;
            const int row = idx >> 5;
            const int c4  = idx & 31;
            float4 v = *(float4*)(Sb + (long)row * 132 + c4 * 4);
            *(float4*)((float*)Cz + (crow0 + row) * ldc + ccol0 + c4 * 4) = v;
        }
    }
}

// ---------------------------------------------------------------------------
// head-mean of normalized exp-scores, de-serialized (MLP=4, one barrier).
__global__ __launch_bounds__(256)
void pmean_kernel(const __nv_bfloat16* __restrict__ P, __nv_bfloat16* __restrict__ Bm)
{
    __shared__ float red[8][4];
    const int bi   = blockIdx.x;
    const int b    = bi >> 11;
    const int i    = bi & 2047;
    const int tid  = threadIdx.x;
    const int wid  = tid >> 5;
    const int lane = tid & 31;

    const __nv_bfloat16* base = P + ((long)b * NH * NL + i) * NL + tid * 8;

    union { float4 f; __nv_bfloat162 hh[4]; } u[NH];
#pragma unroll
    for (int h = 0; h < NH; h++)
        u[h].f = *(const float4*)(base + (long)h * NL * NL);

    float v[NH][8], s[NH];
#pragma unroll
    for (int h = 0; h < NH; h++) {
        float sum = 0.f;
#pragma unroll
        for (int j = 0; j < 4; j++) {
            float2 p = __bfloat1622float2(u[h].hh[j]);
            v[h][2 * j] = p.x; v[h][2 * j + 1] = p.y;
            sum += p.x + p.y;
        }
#pragma unroll
        for (int o = 16; o; o >>= 1)
            sum += __shfl_xor_sync(0xffffffffu, sum, o);
        s[h] = sum;
    }
    if (lane < 4) red[wid][lane] = s[lane];
    __syncthreads();

    float inv[NH];
#pragma unroll
    for (int h = 0; h < NH; h++) {
        float st = red[0][h];
#pragma unroll
        for (int w = 1; w < 8; w++) st += red[w][h];
        inv[h] = 0.25f / st;
    }

    float acc[8];
#pragma unroll
    for (int j = 0; j < 8; j++) {
        acc[j] = v[0][j] * inv[0];
#pragma unroll
        for (int h = 1; h < NH; h++) acc[j] += v[h][j] * inv[h];
    }

    union { float4 f; __nv_bfloat162 hh[4]; } o;
#pragma unroll
    for (int j = 0; j < 4; j++)
        o.hh[j] = __floats2bfloat162_rn(acc[2 * j], acc[2 * j + 1]);
    *(float4*)(Bm + (long)bi * NL + tid * 8) = o.f;
}

// ---------------------------------------------------------------------------
// prepasses
__global__ void cvt_bf16_kernel(const float* __restrict__ in,
                                __nv_bfloat16* __restrict__ out, long n)
{
    const long i = ((long)blockIdx.x * blockDim.x + threadIdx.x) * 4;
    if (i < n) {
        float4 v = *(const float4*)(in + i);
        union { uint2 u; __nv_bfloat162 h[2]; } p;
        p.h[0] = __floats2bfloat162_rn(v.x, v.y);
        p.h[1] = __floats2bfloat162_rn(v.z, v.w);
        *(uint2*)(out + i) = p.u;
    }
}

__global__ void transpose_cvt_kernel(const float* __restrict__ in,
                                     __nv_bfloat16* __restrict__ outT,
                                     __nv_bfloat16* __restrict__ outN,
                                     int R, int Cn)
{
    __shared__ float t[32][33];
    in   += (size_t)blockIdx.z * R * Cn;
    outT += (size_t)blockIdx.z * R * Cn;
    if (outN) outN += (size_t)blockIdx.z * R * Cn;
    const int r0 = blockIdx.y * 32, c0 = blockIdx.x * 32;
    const int x = threadIdx.x, y = threadIdx.y;
#pragma unroll
    for (int i = 0; i < 32; i += 8) {
        const float v = in[(long)(r0 + y + i) * Cn + c0 + x];
        t[y + i][x] = v;
        if (outN) outN[(long)(r0 + y + i) * Cn + c0 + x] = __float2bfloat16_rn(v);
    }
    __syncthreads();
#pragma unroll
    for (int i = 0; i < 32; i += 8)
        outT[(long)(c0 + y + i) * R + r0 + x] = __float2bfloat16_rn(t[x][y + i]);
}

// ---------------------------------------------------------------------------
typedef CUresult (*encode_fn_t)(
    CUtensorMap*, CUtensorMapDataType, cuuint32_t, void*,
    const cuuint64_t*, const cuuint64_t*, const cuuint32_t*, const cuuint32_t*,
    CUtensorMapInterleave, CUtensorMapSwizzle, CUtensorMapL2promotion,
    CUtensorMapFloatOOBfill);

static void make_map(encode_fn_t enc, CUtensorMap* m, void* ptr, long rows, long cols)
{
    cuuint64_t dims[2]    = {(cuuint64_t)cols, (cuuint64_t)rows};
    cuuint64_t strides[1] = {(cuuint64_t)cols * 2};
    cuuint32_t box[2]     = {64u, 128u};
    cuuint32_t es[2]      = {1u, 1u};
    enc(m, CU_TENSOR_MAP_DATA_TYPE_BFLOAT16, 2, ptr, dims, strides, box, es,
        CU_TENSOR_MAP_INTERLEAVE_NONE, CU_TENSOR_MAP_SWIZZLE_128B,
        CU_TENSOR_MAP_L2_PROMOTION_L2_128B, CU_TENSOR_MAP_FLOAT_OOB_FILL_NONE);
}

extern "C" void kernel_launch(void* const* d_in, const int* in_sizes, int n_in,
                              void* d_out, int out_size)
{
    (void)in_sizes; (void)n_in; (void)out_size;
    const float* x   = (const float*)d_in[0];
    const float* w   = (const float*)d_in[1];
    const float* bia = (const float*)d_in[2];
    const float* Wg  = (const float*)d_in[3];
    const float* Bg  = (const float*)d_in[4];
    float* out = (float*)d_out;

    __nv_bfloat16 *xb, *wb, *xTb, *WgTb, *QKb, *P, *Bmb, *yT;
    cudaGetSymbolAddress((void**)&xb,   g_xb);
    cudaGetSymbolAddress((void**)&wb,   g_wb);
    cudaGetSymbolAddress((void**)&xTb,  g_xTb);
    cudaGetSymbolAddress((void**)&WgTb, g_WgTb);
    cudaGetSymbolAddress((void**)&QKb,  g_QKb);
    cudaGetSymbolAddress((void**)&P,    g_P);
    cudaGetSymbolAddress((void**)&Bmb,  g_Bmb);
    cudaGetSymbolAddress((void**)&yT,   g_yT);

    encode_fn_t enc = nullptr;
    {
        void* p = nullptr;
        cudaDriverEntryPointQueryResult st;
        cudaGetDriverEntryPoint("cuTensorMapEncodeTiled", &p, cudaEnableDefault, &st);
        enc = (encode_fn_t)p;
    }

    CUtensorMap m_xb, m_wb, m_WgTb, m_QKb, m_Bmb, m_yT;
    make_map(enc, &m_xb,   xb,   (long)NB * NL, NE);
    make_map(enc, &m_wb,   wb,   2 * NE,        NE);
    make_map(enc, &m_WgTb, WgTb, NE,            NE);
    make_map(enc, &m_QKb,  QKb,  (long)NB * NL, 2 * NE);
    make_map(enc, &m_Bmb,  Bmb,  (long)NB * NL, NL);
    make_map(enc, &m_yT,   yT,   (long)NB * NE, NL);

    cudaFuncSetAttribute((const void*)bgemm<__nv_bfloat16, false, true >,
                         cudaFuncAttributeMaxDynamicSharedMemorySize, GEMM_SMEM);
    cudaFuncSetAttribute((const void*)bgemm<__nv_bfloat16, true,  false>,
                         cudaFuncAttributeMaxDynamicSharedMemorySize, GEMM_SMEM);
    cudaFuncSetAttribute((const void*)bgemm<__nv_bfloat16, false, false>,
                         cudaFuncAttributeMaxDynamicSharedMemorySize, GEMM_SMEM);
    cudaFuncSetAttribute((const void*)bgemm<float, false, true>,
                         cudaFuncAttributeMaxDynamicSharedMemorySize, GEMM_SMEM);

    // 0) bf16 operand prep
    {
        transpose_cvt_kernel<<<dim3(NE / 32, NL / 32, NB), dim3(32, 8)>>>(x, xTb, xb, NL, NE);
        const long nw = (long)2 * NE * NE;
        cvt_bf16_kernel<<<(int)((nw / 4 + 255) / 256), 256>>>(w, wb, nw);
        transpose_cvt_kernel<<<dim3(NE / 32, NE / 32, 1), dim3(32, 8)>>>(Wg, WgTb, nullptr, NE, NE);
    }

    // 1) yT[b] = Wg^T @ x[b]^T   [256 x 2048] x8, K=256 (nk=4)
    bgemm<__nv_bfloat16, false, false><<<dim3(16, 2, NB), 256, GEMM_SMEM>>>(
        m_WgTb, m_xb,
        0, 0, 0,   NL, 0, 0,
        yT, NL, (long)NE * NL,
        1, NE / 64, 1.f, nullptr);

    // 2) QK = xb @ wb^T + bias   [16384 x 512], K=256 (nk=4)
    bgemm<__nv_bfloat16, false, true><<<dim3(4, 128, 1), 256, GEMM_SMEM>>>(
        m_xb, m_wb,
        0, 0, 0,   0, 0, 0,
        QKb, 2 * NE, 0,
        1, NE / 64, 1.f, bia);

    // 3) P[b*4+h] = exp(0.125 * q_h @ k_h^T)   [2048 x 2048] x32, K=64 (nk=1)
    bgemm<__nv_bfloat16, true, false><<<dim3(16, 16, NB * NH), 256, GEMM_SMEM>>>(
        m_QKb, m_QKb,
        NL, ND, 0,   NL, ND, NE,
        P, NL, (long)NL * NL,
        NH, 1, 0.125f, nullptr);

    // 4) Bm[b,i,:] = mean_h P[b,h,i,:] / rowsum
    pmean_kernel<<<NB * NL, 256>>>(P, Bmb);

    // 5) out[b] = Bm[b] @ yT[b]^T + Bg   [2048 x 256] x8, K=2048 (nk=32)
    bgemm<float, false, true><<<dim3(2, 16, NB), 256, GEMM_SMEM>>>(
        m_Bmb, m_yT,
        NL, 0, 0,   NE, 0, 0,
        out, NE, (long)NL * NE,
        1, NL / 64, 1.f, Bg);
}

// round 11
// speedup vs baseline: 2.0182x; 1.0357x over previous
#include <cuda_runtime.h>
#include <cuda.h>
#include <cuda_bf16.h>
#include <cuda_fp16.h>
#include <cstdint>

#define NB 8
#define NL 2048
#define NE 256
#define NH 4
#define ND 64

// ---------------- scratch (device globals; no allocation allowed) -----------
__device__ __nv_bfloat16 g_xb  [(size_t)NB * NL * NE];        // bf16 x
__device__ __nv_bfloat16 g_wb  [(size_t)2 * NE * NE];         // bf16 w[0:512]
__device__ __nv_bfloat16 g_WgTb[(size_t)NE * NE];             // bf16 Wg^T
__device__ __nv_bfloat16 g_QKb [(size_t)NB * NL * 2 * NE];    // [16384, 512]
__device__ __half        g_S   [(size_t)NB * NH * NL * NL];   // raw scores fp16
__device__ __nv_bfloat16 g_Bmb [(size_t)NB * NL * NL];        // head-mean probs
__device__ __nv_bfloat16 g_yT  [(size_t)NB * NE * NL];        // (x @ Wg)^T per b

// ------------------------------- helpers ------------------------------------
__device__ __forceinline__ uint32_t smem_u32(const void* p) {
    uint32_t a;
    asm("{ .reg .u64 t; cvta.to.shared.u64 t, %1; cvt.u32.u64 %0, t; }"
        : "=r"(a) : "l"(p));
    return a;
}

#define MBARRIER_INIT(addr, cnt) \
    asm volatile("mbarrier.init.shared.b64 [%0], %1;" :: "r"(addr), "r"(cnt) : "memory")

#define MBARRIER_EXPECT_TX(addr, bytes) \
    asm volatile("mbarrier.arrive.expect_tx.shared.b64 _, [%0], %1;" \
                 :: "r"(addr), "r"(bytes) : "memory")

#define MBARRIER_WAIT_PARITY(addr, par) do {                                   \
    uint32_t _m = (addr), _p = (par), _d;                                      \
    asm volatile("{\n\t.reg .pred p;\n\t"                                      \
        "mbarrier.try_wait.parity.acquire.cta.shared::cta.b64 p, [%1], %2;\n\t"\
        "selp.b32 %0, 1, 0, p;\n\t}"                                           \
        : "=r"(_d) : "r"(_m), "r"(_p) : "memory");                             \
    if (!_d) {                                                                 \
        asm volatile("{\n\t.reg .pred P1;\n\t"                                 \
        "WL_%=:\n\t"                                                           \
        "mbarrier.try_wait.parity.acquire.cta.shared::cta.b64 P1, [%0], %1, 0x989680;\n\t" \
        "@P1 bra.uni WD_%=;\n\t"                                               \
        "bra.uni WL_%=;\n\t"                                                   \
        "WD_%=:\n\t}" :: "r"(_m), "r"(_p) : "memory");                         \
    }                                                                          \
} while (0)

#define TMA_LOAD_2D(saddr, tmap, cx, cy, mbar)                                 \
    asm volatile("cp.async.bulk.tensor.2d.shared::cta.global.tile.mbarrier::complete_tx::bytes " \
        "[%0], [%1, {%2, %3}], [%4];"                                          \
        :: "r"((uint32_t)(saddr)), "l"(tmap), "r"((int)(cx)), "r"((int)(cy)),  \
           "r"((uint32_t)(mbar)) : "memory")

#define FENCE_ASYNC_SHARED() asm volatile("fence.proxy.async.shared::cta;" ::: "memory")

#define MMA_BF16(d, a, b)                                                      \
    asm volatile("mma.sync.aligned.m16n8k16.row.col.f32.bf16.bf16.f32 "       \
        "{%0,%1,%2,%3}, {%4,%5,%6,%7}, {%8,%9}, {%0,%1,%2,%3};"                \
        : "+f"((d)[0]), "+f"((d)[1]), "+f"((d)[2]), "+f"((d)[3])               \
        : "r"((a)[0]), "r"((a)[1]), "r"((a)[2]), "r"((a)[3]),                  \
          "r"((b)[0]), "r"((b)[1]))

#define LDSM_X4(r0, r1, r2, r3, addr)                                          \
    asm volatile("ldmatrix.sync.aligned.m8n8.x4.shared.b16 {%0,%1,%2,%3}, [%4];" \
        : "=r"(r0), "=r"(r1), "=r"(r2), "=r"(r3) : "r"(addr))

__device__ __forceinline__ void store2(float* p, float a, float b) {
    *(float2*)p = make_float2(a, b);
}
__device__ __forceinline__ void store2(__nv_bfloat16* p, float a, float b) {
    *(__nv_bfloat162*)p = __floats2bfloat162_rn(a, b);
}
__device__ __forceinline__ void store2(__half* p, float a, float b) {
    *(__half2*)p = __floats2half2_rn(a, b);
}

// ------------------------------- bf16 GEMM ----------------------------------
// C[z] = alpha * A_z * B_z^T (+ bias[col]) ; A [M,K], B [N,K] bf16 K-major,
// loaded via 2D TMA (SW128). CTA tile 128x128, K chunk 64 elems, 8 warps
// (2x4), warp tile 64x32, 3-stage TMA+mbarrier pipeline, ldmatrix with
// closed-form SW128 swizzle, smem-bounce coalesced epilogue.
#define STAGES     3
#define STG_BYTES  32768          // A 16KB + B 16KB, dense SW128 tiles
#define GEMM_SMEM  (STAGES * STG_BYTES + 1024 + 64)

template <typename OutT, bool HAS_BIAS>
__global__ __launch_bounds__(256, 2)
void bgemm(const __grid_constant__ CUtensorMap tmA,
           const __grid_constant__ CUtensorMap tmB,
           int a_zo_row, int a_zi_col, int a_col_base,
           int b_zo_row, int b_zi_col, int b_col_base,
           OutT* __restrict__ C, int ldc, long sC,
           int inner, int nk, float alpha, const float* __restrict__ bias)
{
    extern __shared__ char smem[];
    const uint32_t sb0 = smem_u32(smem);
    const uint32_t sal = (sb0 + 1023) & ~1023u;   // 1KB-aligned stage base
    const uint32_t mbb = sal + STAGES * STG_BYTES;

    const int tid    = threadIdx.x;
    const int warpId = tid >> 5;
    const int lane   = tid & 31;
    const int g  = lane >> 2;
    const int tg = lane & 3;
    const int wr = (warpId & 1) * 64;
    const int wc = (warpId >> 1) * 32;

    const int z  = blockIdx.z;
    const int zo = z / inner;
    const int zi = z - zo * inner;

    const int ary = zo * a_zo_row + blockIdx.y * 128;
    const int acx = a_col_base + zi * a_zi_col;
    const int bry = zo * b_zo_row + blockIdx.x * 128;
    const int bcx = b_col_base + zi * b_zi_col;

    if (tid == 0) {
#pragma unroll
        for (int s = 0; s < STAGES; s++) MBARRIER_INIT(mbb + s * 8, 1);
        FENCE_ASYNC_SHARED();
    }
    __syncthreads();

    auto issue = [&](int chunk) {
        const int s = chunk % STAGES;
        MBARRIER_EXPECT_TX(mbb + s * 8, (uint32_t)STG_BYTES);
        TMA_LOAD_2D(sal + s * STG_BYTES,         &tmA, acx + chunk * 64, ary, mbb + s * 8);
        TMA_LOAD_2D(sal + s * STG_BYTES + 16384, &tmB, bcx + chunk * 64, bry, mbb + s * 8);
    };

    if (tid == 0) {
        issue(0);
        if (nk > 1) issue(1);
    }

    // ldmatrix swizzled addressing: byte(row, cb) at row*128 + (cb ^ ((row&7)<<4));
    // in both operand maps row ≡ lane (mod 8), so the XOR is a per-thread const.
    const uint32_t xorv  = (uint32_t)((lane & 7) << 4);
    const uint32_t aRow  = (uint32_t)(wr + (lane & 15)) * 128;
    const uint32_t aCol0 = (uint32_t)((lane >> 4) * 16);
    const uint32_t bRow  = (uint32_t)(wc + (lane & 7) + ((lane >> 4) << 3)) * 128;
    const uint32_t bCol0 = (uint32_t)(((lane >> 3) & 1) * 16);

    float acc[4][4][4];
#pragma unroll
    for (int m = 0; m < 4; m++)
#pragma unroll
        for (int n = 0; n < 4; n++)
#pragma unroll
            for (int c = 0; c < 4; c++) acc[m][n][c] = 0.f;

    for (int i = 0; i < nk; i++) {
        const int s  = i % STAGES;
        const int ph = (i / STAGES) & 1;

        __syncthreads();                 // stage (i+2)%3 reads (chunk i-1) done
        if (tid == 0 && i + 2 < nk) issue(i + 2);
        MBARRIER_WAIT_PARITY(mbb + s * 8, ph);

        const uint32_t sA = sal + s * STG_BYTES;
        const uint32_t sB = sA + 16384;

#pragma unroll
        for (int j = 0; j < 4; j++) {    // 4 x k16 steps
            uint32_t af[4][4], bf[4][2];
            const uint32_t ac = (aCol0 + j * 32) ^ xorv;
            const uint32_t bc = (bCol0 + j * 32) ^ xorv;
#pragma unroll
            for (int mt = 0; mt < 4; mt++)
                LDSM_X4(af[mt][0], af[mt][1], af[mt][2], af[mt][3],
                        sA + aRow + mt * 2048 + ac);
#pragma unroll
            for (int p = 0; p < 2; p++)
                LDSM_X4(bf[2 * p][0], bf[2 * p][1], bf[2 * p + 1][0], bf[2 * p + 1][1],
                        sB + bRow + p * 2048 + bc);
#pragma unroll
            for (int mt = 0; mt < 4; mt++)
#pragma unroll
                for (int nt = 0; nt < 4; nt++)
                    MMA_BF16(acc[mt][nt], af[mt], bf[nt]);
        }
    }

    // ---- epilogue: smem bounce -> coalesced 16B stores ----
    __syncthreads();                     // stages now reusable as bounce

    char* bounce = smem + (sal - sb0);
    OutT* Cz = C + (long)z * sC;
    const long crow0 = (long)blockIdx.y * 128;
    const int  ccol0 = blockIdx.x * 128;

    if (sizeof(OutT) == 2) {
        OutT* Sb = (OutT*)bounce;        // 128 x 136 halfword
#pragma unroll
        for (int mt = 0; mt < 4; mt++) {
#pragma unroll
            for (int nt = 0; nt < 4; nt++) {
                const int r = wr + mt * 16 + g;
                const int c = wc + nt * 8 + tg * 2;
                float b0 = 0.f, b1 = 0.f;
                if (HAS_BIAS) { b0 = bias[ccol0 + c]; b1 = bias[ccol0 + c + 1]; }
                store2(Sb + (long)r * 136 + c,
                       acc[mt][nt][0] * alpha + b0, acc[mt][nt][1] * alpha + b1);
                store2(Sb + (long)(r + 8) * 136 + c,
                       acc[mt][nt][2] * alpha + b0, acc[mt][nt][3] * alpha + b1);
            }
        }
        __syncthreads();
#pragma unroll
        for (int it = 0; it < 8; it++) {
            const int idx = it * 256 + tid;
            const int row = idx >> 4;
            const int c16 = idx & 15;
            float4 v = *(float4*)(Sb + (long)row * 136 + c16 * 8);
            *(float4*)(Cz + (crow0 + row) * ldc + ccol0 + c16 * 8) = v;
        }
    } else {
        float* Sb = (float*)bounce;      // 128 x 132 fp32
#pragma unroll
        for (int mt = 0; mt < 4; mt++) {
#pragma unroll
            for (int nt = 0; nt < 4; nt++) {
                const int r = wr + mt * 16 + g;
                const int c = wc + nt * 8 + tg * 2;
                float b0 = 0.f, b1 = 0.f;
                if (HAS_BIAS) { b0 = bias[ccol0 + c]; b1 = bias[ccol0 + c + 1]; }
                *(float2*)(Sb + (long)r * 132 + c) =
                    make_float2(acc[mt][nt][0] * alpha + b0, acc[mt][nt][1] * alpha + b1);
                *(float2*)(Sb + (long)(r + 8) * 132 + c) =
                    make_float2(acc[mt][nt][2] * alpha + b0, acc[mt][nt][3] * alpha + b1);
            }
        }
        __syncthreads();
#pragma unroll
        for (int it = 0; it < 16; it++) {
            const int idx = it * 256 + tid;
            const int row = idx >> 5;
            const int c4  = idx & 31;
            float4 v = *(float4*)(Sb + (long)row * 132 + c4 * 4);
            *(float4*)((float*)Cz + (crow0 + row) * ldc + ccol0 + c4 * 4) = v;
        }
    }
}

// ---------------------------------------------------------------------------
// head-mean softmax from raw fp16 scores (exp done here, overlapped with DRAM):
// Bm[b,i,j] = sum_h exp(S[b,h,i,j]) / (4 * sum_j' exp(S[b,h,i,j']))
__global__ __launch_bounds__(256)
void pmean_kernel(const __half* __restrict__ S, __nv_bfloat16* __restrict__ Bm)
{
    __shared__ float red[8][4];
    const int bi   = blockIdx.x;
    const int b    = bi >> 11;
    const int i    = bi & 2047;
    const int tid  = threadIdx.x;
    const int wid  = tid >> 5;
    const int lane = tid & 31;

    const __half* base = S + ((long)b * NH * NL + i) * NL + tid * 8;

    union { float4 f; __half2 hh[4]; } u[NH];
#pragma unroll
    for (int h = 0; h < NH; h++)
        u[h].f = *(const float4*)(base + (long)h * NL * NL);

    float v[NH][8], s[NH];
#pragma unroll
    for (int h = 0; h < NH; h++) {
        float sum = 0.f;
#pragma unroll
        for (int j = 0; j < 4; j++) {
            float2 p = __half22float2(u[h].hh[j]);
            float e0 = __expf(p.x), e1 = __expf(p.y);
            v[h][2 * j] = e0; v[h][2 * j + 1] = e1;
            sum += e0 + e1;
        }
#pragma unroll
        for (int o = 16; o; o >>= 1)
            sum += __shfl_xor_sync(0xffffffffu, sum, o);
        s[h] = sum;
    }
    if (lane < 4) red[wid][lane] = s[lane];
    __syncthreads();

    float inv[NH];
#pragma unroll
    for (int h = 0; h < NH; h++) {
        float st = red[0][h];
#pragma unroll
        for (int w = 1; w < 8; w++) st += red[w][h];
        inv[h] = 0.25f / st;
    }

    float acc[8];
#pragma unroll
    for (int j = 0; j < 8; j++) {
        acc[j] = v[0][j] * inv[0];
#pragma unroll
        for (int h = 1; h < NH; h++) acc[j] += v[h][j] * inv[h];
    }

    union { float4 f; __nv_bfloat162 hh[4]; } o;
#pragma unroll
    for (int j = 0; j < 4; j++)
        o.hh[j] = __floats2bfloat162_rn(acc[2 * j], acc[2 * j + 1]);
    *(float4*)(Bm + (long)bi * NL + tid * 8) = o.f;
}

// ---------------------------------------------------------------------------
// prepasses
__global__ void cvt_bf16_kernel(const float* __restrict__ in,
                                __nv_bfloat16* __restrict__ out, long n)
{
    const long i = ((long)blockIdx.x * blockDim.x + threadIdx.x) * 4;
    if (i < n) {
        float4 v = *(const float4*)(in + i);
        union { uint2 u; __nv_bfloat162 h[2]; } p;
        p.h[0] = __floats2bfloat162_rn(v.x, v.y);
        p.h[1] = __floats2bfloat162_rn(v.z, v.w);
        *(uint2*)(out + i) = p.u;
    }
}

__global__ void transpose_cvt_kernel(const float* __restrict__ in,
                                     __nv_bfloat16* __restrict__ outT,
                                     int R, int Cn)
{
    __shared__ float t[32][33];
    in   += (size_t)blockIdx.z * R * Cn;
    outT += (size_t)blockIdx.z * R * Cn;
    const int r0 = blockIdx.y * 32, c0 = blockIdx.x * 32;
    const int x = threadIdx.x, y = threadIdx.y;
#pragma unroll
    for (int i = 0; i < 32; i += 8)
        t[y + i][x] = in[(long)(r0 + y + i) * Cn + c0 + x];
    __syncthreads();
#pragma unroll
    for (int i = 0; i < 32; i += 8)
        outT[(long)(c0 + y + i) * R + r0 + x] = __float2bfloat16_rn(t[x][y + i]);
}

// ---------------------------------------------------------------------------
typedef CUresult (*encode_fn_t)(
    CUtensorMap*, CUtensorMapDataType, cuuint32_t, void*,
    const cuuint64_t*, const cuuint64_t*, const cuuint32_t*, const cuuint32_t*,
    CUtensorMapInterleave, CUtensorMapSwizzle, CUtensorMapL2promotion,
    CUtensorMapFloatOOBfill);

static void make_map(encode_fn_t enc, CUtensorMap* m, void* ptr, long rows, long cols)
{
    cuuint64_t dims[2]    = {(cuuint64_t)cols, (cuuint64_t)rows};
    cuuint64_t strides[1] = {(cuuint64_t)cols * 2};
    cuuint32_t box[2]     = {64u, 128u};
    cuuint32_t es[2]      = {1u, 1u};
    enc(m, CU_TENSOR_MAP_DATA_TYPE_BFLOAT16, 2, ptr, dims, strides, box, es,
        CU_TENSOR_MAP_INTERLEAVE_NONE, CU_TENSOR_MAP_SWIZZLE_128B,
        CU_TENSOR_MAP_L2_PROMOTION_L2_128B, CU_TENSOR_MAP_FLOAT_OOB_FILL_NONE);
}

extern "C" void kernel_launch(void* const* d_in, const int* in_sizes, int n_in,
                              void* d_out, int out_size)
{
    (void)in_sizes; (void)n_in; (void)out_size;
    const float* x   = (const float*)d_in[0];
    const float* w   = (const float*)d_in[1];
    const float* bia = (const float*)d_in[2];
    const float* Wg  = (const float*)d_in[3];
    const float* Bg  = (const float*)d_in[4];
    float* out = (float*)d_out;

    __nv_bfloat16 *xb, *wb, *WgTb, *QKb, *Bmb, *yT;
    __half* S;
    cudaGetSymbolAddress((void**)&xb,   g_xb);
    cudaGetSymbolAddress((void**)&wb,   g_wb);
    cudaGetSymbolAddress((void**)&WgTb, g_WgTb);
    cudaGetSymbolAddress((void**)&QKb,  g_QKb);
    cudaGetSymbolAddress((void**)&S,    g_S);
    cudaGetSymbolAddress((void**)&Bmb,  g_Bmb);
    cudaGetSymbolAddress((void**)&yT,   g_yT);

    encode_fn_t enc = nullptr;
    {
        void* p = nullptr;
        cudaDriverEntryPointQueryResult st;
        cudaGetDriverEntryPoint("cuTensorMapEncodeTiled", &p, cudaEnableDefault, &st);
        enc = (encode_fn_t)p;
    }

    CUtensorMap m_xb, m_wb, m_WgTb, m_QKb, m_Bmb, m_yT;
    make_map(enc, &m_xb,   xb,   (long)NB * NL, NE);
    make_map(enc, &m_wb,   wb,   2 * NE,        NE);
    make_map(enc, &m_WgTb, WgTb, NE,            NE);
    make_map(enc, &m_QKb,  QKb,  (long)NB * NL, 2 * NE);
    make_map(enc, &m_Bmb,  Bmb,  (long)NB * NL, NL);
    make_map(enc, &m_yT,   yT,   (long)NB * NE, NL);

    cudaFuncSetAttribute((const void*)bgemm<__nv_bfloat16, true >,
                         cudaFuncAttributeMaxDynamicSharedMemorySize, GEMM_SMEM);
    cudaFuncSetAttribute((const void*)bgemm<__nv_bfloat16, false>,
                         cudaFuncAttributeMaxDynamicSharedMemorySize, GEMM_SMEM);
    cudaFuncSetAttribute((const void*)bgemm<__half, false>,
                         cudaFuncAttributeMaxDynamicSharedMemorySize, GEMM_SMEM);
    cudaFuncSetAttribute((const void*)bgemm<float, true>,
                         cudaFuncAttributeMaxDynamicSharedMemorySize, GEMM_SMEM);

    // 0) bf16 operand prep (no transpose of x needed anymore)
    {
        const long nx = (long)NB * NL * NE;
        cvt_bf16_kernel<<<(int)(nx / 4 / 256), 256>>>(x, xb, nx);
        const long nw = (long)2 * NE * NE;
        cvt_bf16_kernel<<<(int)((nw / 4 + 255) / 256), 256>>>(w, wb, nw);
        transpose_cvt_kernel<<<dim3(NE / 32, NE / 32, 1), dim3(32, 8)>>>(Wg, WgTb, NE, NE);
    }

    // 1) yT[b] = Wg^T @ x[b]^T   [256 x 2048] x8, K=256 (nk=4)
    bgemm<__nv_bfloat16, false><<<dim3(16, 2, NB), 256, GEMM_SMEM>>>(
        m_WgTb, m_xb,
        0, 0, 0,   NL, 0, 0,
        yT, NL, (long)NE * NL,
        1, NE / 64, 1.f, nullptr);

    // 2) QK = xb @ wb^T + bias   [16384 x 512], K=256 (nk=4)
    bgemm<__nv_bfloat16, true><<<dim3(4, 128, 1), 256, GEMM_SMEM>>>(
        m_xb, m_wb,
        0, 0, 0,   0, 0, 0,
        QKb, 2 * NE, 0,
        1, NE / 64, 1.f, bia);

    // 3) S[b*4+h] = 0.125 * q_h @ k_h^T  (raw scores, fp16)  [2048x2048]x32, nk=1
    bgemm<__half, false><<<dim3(16, 16, NB * NH), 256, GEMM_SMEM>>>(
        m_QKb, m_QKb,
        NL, ND, 0,   NL, ND, NE,
        S, NL, (long)NL * NL,
        NH, 1, 0.125f, nullptr);

    // 4) Bm[b,i,:] = mean_h softmax(S[b,h,i,:])   (exp computed here)
    pmean_kernel<<<NB * NL, 256>>>(S, Bmb);

    // 5) out[b] = Bm[b] @ yT[b]^T + Bg   [2048 x 256] x8, K=2048 (nk=32)
    bgemm<float, true><<<dim3(2, 16, NB), 256, GEMM_SMEM>>>(
        m_Bmb, m_yT,
        NL, 0, 0,   NE, 0, 0,
        out, NE, (long)NL * NE,
        1, NL / 64, 1.f, Bg);
}

// round 12
// speedup vs baseline: 2.0505x; 1.0160x over previous
#include <cuda_runtime.h>
#include <cuda.h>
#include <cuda_bf16.h>
#include <cuda_fp16.h>
#include <cstdint>

#define NB 8
#define NL 2048
#define NE 256
#define NH 4
#define ND 64

// ---------------- scratch (device globals; no allocation allowed) -----------
__device__ __nv_bfloat16 g_xb  [(size_t)NB * NL * NE];        // bf16 x
__device__ __nv_bfloat16 g_wb  [(size_t)2 * NE * NE];         // bf16 w[0:512]
__device__ __nv_bfloat16 g_WgTb[(size_t)NE * NE];             // bf16 Wg^T
__device__ __nv_bfloat16 g_QKb [(size_t)NB * NL * 2 * NE];    // [16384, 512]
__device__ __half        g_S   [(size_t)NB * NH * NL * NL];   // raw scores fp16
__device__ __nv_bfloat16 g_Bmb [(size_t)NB * NL * NL];        // head-mean probs
__device__ __nv_bfloat16 g_yT  [(size_t)NB * NE * NL];        // (x @ Wg)^T per b

// ------------------------------- helpers ------------------------------------
__device__ __forceinline__ uint32_t smem_u32(const void* p) {
    uint32_t a;
    asm("{ .reg .u64 t; cvta.to.shared.u64 t, %1; cvt.u32.u64 %0, t; }"
        : "=r"(a) : "l"(p));
    return a;
}

#define MBARRIER_INIT(addr, cnt) \
    asm volatile("mbarrier.init.shared.b64 [%0], %1;" :: "r"(addr), "r"(cnt) : "memory")

#define MBARRIER_EXPECT_TX(addr, bytes) \
    asm volatile("mbarrier.arrive.expect_tx.shared.b64 _, [%0], %1;" \
                 :: "r"(addr), "r"(bytes) : "memory")

#define MBARRIER_WAIT_PARITY(addr, par) do {                                   \
    uint32_t _m = (addr), _p = (par), _d;                                      \
    asm volatile("{\n\t.reg .pred p;\n\t"                                      \
        "mbarrier.try_wait.parity.acquire.cta.shared::cta.b64 p, [%1], %2;\n\t"\
        "selp.b32 %0, 1, 0, p;\n\t}"                                           \
        : "=r"(_d) : "r"(_m), "r"(_p) : "memory");                             \
    if (!_d) {                                                                 \
        asm volatile("{\n\t.reg .pred P1;\n\t"                                 \
        "WL_%=:\n\t"                                                           \
        "mbarrier.try_wait.parity.acquire.cta.shared::cta.b64 P1, [%0], %1, 0x989680;\n\t" \
        "@P1 bra.uni WD_%=;\n\t"                                               \
        "bra.uni WL_%=;\n\t"                                                   \
        "WD_%=:\n\t}" :: "r"(_m), "r"(_p) : "memory");                         \
    }                                                                          \
} while (0)

#define TMA_LOAD_2D(saddr, tmap, cx, cy, mbar)                                 \
    asm volatile("cp.async.bulk.tensor.2d.shared::cta.global.tile.mbarrier::complete_tx::bytes " \
        "[%0], [%1, {%2, %3}], [%4];"                                          \
        :: "r"((uint32_t)(saddr)), "l"(tmap), "r"((int)(cx)), "r"((int)(cy)),  \
           "r"((uint32_t)(mbar)) : "memory")

#define FENCE_ASYNC_SHARED() asm volatile("fence.proxy.async.shared::cta;" ::: "memory")

#define MMA_BF16(d, a, b)                                                      \
    asm volatile("mma.sync.aligned.m16n8k16.row.col.f32.bf16.bf16.f32 "       \
        "{%0,%1,%2,%3}, {%4,%5,%6,%7}, {%8,%9}, {%0,%1,%2,%3};"                \
        : "+f"((d)[0]), "+f"((d)[1]), "+f"((d)[2]), "+f"((d)[3])               \
        : "r"((a)[0]), "r"((a)[1]), "r"((a)[2]), "r"((a)[3]),                  \
          "r"((b)[0]), "r"((b)[1]))

#define LDSM_X4(r0, r1, r2, r3, addr)                                          \
    asm volatile("ldmatrix.sync.aligned.m8n8.x4.shared.b16 {%0,%1,%2,%3}, [%4];" \
        : "=r"(r0), "=r"(r1), "=r"(r2), "=r"(r3) : "r"(addr))

__device__ __forceinline__ void store2(float* p, float a, float b) {
    *(float2*)p = make_float2(a, b);
}
__device__ __forceinline__ void store2(__nv_bfloat16* p, float a, float b) {
    *(__nv_bfloat162*)p = __floats2bfloat162_rn(a, b);
}
__device__ __forceinline__ void store2(__half* p, float a, float b) {
    *(__half2*)p = __floats2half2_rn(a, b);
}

#define STAGES     3
#define STG_BYTES  32768          // A 16KB + B 16KB, dense SW128 tiles
#define GEMM_SMEM  (STAGES * STG_BYTES + 1024 + 64)

// ---- shared mainloop: 128x128 tile, 64-K chunks via TMA, ldmatrix+mma ------
struct Frag { float acc[4][4][4]; };

__device__ __forceinline__ void gemm_mainloop(
    uint32_t sal, uint32_t mbb, int tid,
    const CUtensorMap* pA, const CUtensorMap* pB,
    int ary, int acx, int bry, int bcx, int nk,
    uint32_t aRow, uint32_t aCol0, uint32_t bRow, uint32_t bCol0, uint32_t xorv,
    Frag& F)
{
#pragma unroll
    for (int m = 0; m < 4; m++)
#pragma unroll
        for (int n = 0; n < 4; n++)
#pragma unroll
            for (int c = 0; c < 4; c++) F.acc[m][n][c] = 0.f;

    auto issue = [&](int chunk) {
        const int s = chunk % STAGES;
        MBARRIER_EXPECT_TX(mbb + s * 8, (uint32_t)STG_BYTES);
        TMA_LOAD_2D(sal + s * STG_BYTES,         pA, acx + chunk * 64, ary, mbb + s * 8);
        TMA_LOAD_2D(sal + s * STG_BYTES + 16384, pB, bcx + chunk * 64, bry, mbb + s * 8);
    };

    if (tid == 0) {
        issue(0);
        if (nk > 1) issue(1);
    }

    for (int i = 0; i < nk; i++) {
        const int s  = i % STAGES;
        const int ph = (i / STAGES) & 1;

        __syncthreads();
        if (tid == 0 && i + 2 < nk) issue(i + 2);
        MBARRIER_WAIT_PARITY(mbb + s * 8, ph);

        const uint32_t sA = sal + s * STG_BYTES;
        const uint32_t sB = sA + 16384;

#pragma unroll
        for (int j = 0; j < 4; j++) {
            uint32_t af[4][4], bf[4][2];
            const uint32_t ac = (aCol0 + j * 32) ^ xorv;
            const uint32_t bc = (bCol0 + j * 32) ^ xorv;
#pragma unroll
            for (int mt = 0; mt < 4; mt++)
                LDSM_X4(af[mt][0], af[mt][1], af[mt][2], af[mt][3],
                        sA + aRow + mt * 2048 + ac);
#pragma unroll
            for (int p = 0; p < 2; p++)
                LDSM_X4(bf[2 * p][0], bf[2 * p][1], bf[2 * p + 1][0], bf[2 * p + 1][1],
                        sB + bRow + p * 2048 + bc);
#pragma unroll
            for (int mt = 0; mt < 4; mt++)
#pragma unroll
                for (int nt = 0; nt < 4; nt++)
                    MMA_BF16(F.acc[mt][nt], af[mt], bf[nt]);
        }
    }
}

// 16-bit-output epilogue: smem bounce -> coalesced 16B stores
template <typename OutT>
__device__ __forceinline__ void epilogue16(
    char* bounce, int tid, int wr, int wc, int g, int tg,
    OutT* Cz, int ldc, long crow0, int ccol0,
    float alpha, const float* bias, const Frag& F)
{
    OutT* Sb = (OutT*)bounce;            // 128 x 136 halfword
#pragma unroll
    for (int mt = 0; mt < 4; mt++) {
#pragma unroll
        for (int nt = 0; nt < 4; nt++) {
            const int r = wr + mt * 16 + g;
            const int c = wc + nt * 8 + tg * 2;
            float b0 = 0.f, b1 = 0.f;
            if (bias) { b0 = bias[ccol0 + c]; b1 = bias[ccol0 + c + 1]; }
            store2(Sb + (long)r * 136 + c,
                   F.acc[mt][nt][0] * alpha + b0, F.acc[mt][nt][1] * alpha + b1);
            store2(Sb + (long)(r + 8) * 136 + c,
                   F.acc[mt][nt][2] * alpha + b0, F.acc[mt][nt][3] * alpha + b1);
        }
    }
    __syncthreads();
#pragma unroll
    for (int it = 0; it < 8; it++) {
        const int idx = it * 256 + tid;
        const int row = idx >> 4;
        const int c16 = idx & 15;
        float4 v = *(float4*)(Sb + (long)row * 136 + c16 * 8);
        *(float4*)(Cz + (crow0 + row) * ldc + ccol0 + c16 * 8) = v;
    }
}

// ------------------------- generic batched GEMM ------------------------------
template <typename OutT, bool HAS_BIAS>
__global__ __launch_bounds__(256, 2)
void bgemm(const __grid_constant__ CUtensorMap tmA,
           const __grid_constant__ CUtensorMap tmB,
           int a_zo_row, int a_zi_col, int a_col_base,
           int b_zo_row, int b_zi_col, int b_col_base,
           OutT* __restrict__ C, int ldc, long sC,
           int inner, int nk, float alpha, const float* __restrict__ bias)
{
    extern __shared__ char smem[];
    const uint32_t sb0 = smem_u32(smem);
    const uint32_t sal = (sb0 + 1023) & ~1023u;
    const uint32_t mbb = sal + STAGES * STG_BYTES;

    const int tid    = threadIdx.x;
    const int warpId = tid >> 5;
    const int lane   = tid & 31;
    const int g  = lane >> 2;
    const int tg = lane & 3;
    const int wr = (warpId & 1) * 64;
    const int wc = (warpId >> 1) * 32;

    const int z  = blockIdx.z;
    const int zo = z / inner;
    const int zi = z - zo * inner;

    const int ary = zo * a_zo_row + blockIdx.y * 128;
    const int acx = a_col_base + zi * a_zi_col;
    const int bry = zo * b_zo_row + blockIdx.x * 128;
    const int bcx = b_col_base + zi * b_zi_col;

    if (tid == 0) {
#pragma unroll
        for (int s = 0; s < STAGES; s++) MBARRIER_INIT(mbb + s * 8, 1);
        FENCE_ASYNC_SHARED();
    }
    __syncthreads();

    const uint32_t xorv  = (uint32_t)((lane & 7) << 4);
    const uint32_t aRow  = (uint32_t)(wr + (lane & 15)) * 128;
    const uint32_t aCol0 = (uint32_t)((lane >> 4) * 16);
    const uint32_t bRow  = (uint32_t)(wc + (lane & 7) + ((lane >> 4) << 3)) * 128;
    const uint32_t bCol0 = (uint32_t)(((lane >> 3) & 1) * 16);

    Frag F;
    gemm_mainloop(sal, mbb, tid, &tmA, &tmB, ary, acx, bry, bcx, nk,
                  aRow, aCol0, bRow, bCol0, xorv, F);

    __syncthreads();                     // stages reusable as bounce
    char* bounce = smem + (sal - sb0);
    OutT* Cz = C + (long)z * sC;
    const long crow0 = (long)blockIdx.y * 128;
    const int  ccol0 = blockIdx.x * 128;
    const float* bp = HAS_BIAS ? bias : nullptr;

    if (sizeof(OutT) == 2) {
        epilogue16(bounce, tid, wr, wc, g, tg, Cz, ldc, crow0, ccol0, alpha, bp, F);
    } else {
        float* Sb = (float*)bounce;      // 128 x 132 fp32
#pragma unroll
        for (int mt = 0; mt < 4; mt++) {
#pragma unroll
            for (int nt = 0; nt < 4; nt++) {
                const int r = wr + mt * 16 + g;
                const int c = wc + nt * 8 + tg * 2;
                float b0 = 0.f, b1 = 0.f;
                if (HAS_BIAS) { b0 = bias[ccol0 + c]; b1 = bias[ccol0 + c + 1]; }
                *(float2*)(Sb + (long)r * 132 + c) =
                    make_float2(F.acc[mt][nt][0] * alpha + b0, F.acc[mt][nt][1] * alpha + b1);
                *(float2*)(Sb + (long)(r + 8) * 132 + c) =
                    make_float2(F.acc[mt][nt][2] * alpha + b0, F.acc[mt][nt][3] * alpha + b1);
            }
        }
        __syncthreads();
#pragma unroll
        for (int it = 0; it < 16; it++) {
            const int idx = it * 256 + tid;
            const int row = idx >> 5;
            const int c4  = idx & 31;
            float4 v = *(float4*)(Sb + (long)row * 132 + c4 * 4);
            *(float4*)((float*)Cz + (crow0 + row) * ldc + ccol0 + c4 * 4) = v;
        }
    }
}

// ------------- merged QK + yT GEMM (both nk=4, bf16 out) --------------------
// flat grid: id < 512 -> QK tile (x=id&3, y=id>>2): QK = xb @ wb^T + bias
// id >= 512 -> yT tile: t=id-512, x=t&15, y=(t>>4)&1, b=t>>5:
//              yT[b] = WgT @ x[b]^T
__global__ __launch_bounds__(256, 2)
void bgemm_qkyt(const __grid_constant__ CUtensorMap tmXb,
                const __grid_constant__ CUtensorMap tmWb,
                const __grid_constant__ CUtensorMap tmWgT,
                __nv_bfloat16* __restrict__ QKb,
                __nv_bfloat16* __restrict__ yT,
                const float* __restrict__ bia)
{
    extern __shared__ char smem[];
    const uint32_t sb0 = smem_u32(smem);
    const uint32_t sal = (sb0 + 1023) & ~1023u;
    const uint32_t mbb = sal + STAGES * STG_BYTES;

    const int tid    = threadIdx.x;
    const int warpId = tid >> 5;
    const int lane   = tid & 31;
    const int g  = lane >> 2;
    const int tg = lane & 3;
    const int wr = (warpId & 1) * 64;
    const int wc = (warpId >> 1) * 32;

    const int id = blockIdx.x;
    const bool isQK = (id < 512);
    int xt, yt, zb;
    if (isQK) { xt = id & 3;  yt = id >> 2;        zb = 0; }
    else      { int t = id - 512; xt = t & 15; yt = (t >> 4) & 1; zb = t >> 5; }

    const CUtensorMap* pA = isQK ? &tmXb : &tmWgT;
    const CUtensorMap* pB = isQK ? &tmWb : &tmXb;
    const int ary = yt * 128;
    const int bry = (isQK ? 0 : zb * NL) + xt * 128;

    __nv_bfloat16* Cz = isQK ? QKb : (yT + (long)zb * NE * NL);
    const int   ldc   = isQK ? (2 * NE) : NL;
    const float* bias = isQK ? bia : nullptr;

    if (tid == 0) {
#pragma unroll
        for (int s = 0; s < STAGES; s++) MBARRIER_INIT(mbb + s * 8, 1);
        FENCE_ASYNC_SHARED();
    }
    __syncthreads();

    const uint32_t xorv  = (uint32_t)((lane & 7) << 4);
    const uint32_t aRow  = (uint32_t)(wr + (lane & 15)) * 128;
    const uint32_t aCol0 = (uint32_t)((lane >> 4) * 16);
    const uint32_t bRow  = (uint32_t)(wc + (lane & 7) + ((lane >> 4) << 3)) * 128;
    const uint32_t bCol0 = (uint32_t)(((lane >> 3) & 1) * 16);

    Frag F;
    gemm_mainloop(sal, mbb, tid, pA, pB, ary, 0, bry, 0, NE / 64,
                  aRow, aCol0, bRow, bCol0, xorv, F);

    __syncthreads();
    char* bounce = smem + (sal - sb0);
    epilogue16(bounce, tid, wr, wc, g, tg, Cz, ldc,
               (long)yt * 128, xt * 128, 1.f, bias, F);
}

// ---------------------------------------------------------------------------
// head-mean softmax from raw fp16 scores; streaming (__ldcs) reads.
__global__ __launch_bounds__(256)
void pmean_kernel(const __half* __restrict__ S, __nv_bfloat16* __restrict__ Bm)
{
    __shared__ float red[8][4];
    const int bi   = blockIdx.x;
    const int b    = bi >> 11;
    const int i    = bi & 2047;
    const int tid  = threadIdx.x;
    const int wid  = tid >> 5;
    const int lane = tid & 31;

    const __half* base = S + ((long)b * NH * NL + i) * NL + tid * 8;

    union F4H { float4 f; __half2 hh[4]; } u[NH];
#pragma unroll
    for (int h = 0; h < NH; h++)
        u[h].f = __ldcs((const float4*)(base + (long)h * NL * NL));

    float v[NH][8], s[NH];
#pragma unroll
    for (int h = 0; h < NH; h++) {
        float sum = 0.f;
#pragma unroll
        for (int j = 0; j < 4; j++) {
            float2 p = __half22float2(u[h].hh[j]);
            float e0 = __expf(p.x), e1 = __expf(p.y);
            v[h][2 * j] = e0; v[h][2 * j + 1] = e1;
            sum += e0 + e1;
        }
#pragma unroll
        for (int o = 16; o; o >>= 1)
            sum += __shfl_xor_sync(0xffffffffu, sum, o);
        s[h] = sum;
    }
    if (lane < 4) red[wid][lane] = s[lane];
    __syncthreads();

    float inv[NH];
#pragma unroll
    for (int h = 0; h < NH; h++) {
        float st = red[0][h];
#pragma unroll
        for (int w = 1; w < 8; w++) st += red[w][h];
        inv[h] = 0.25f / st;
    }

    float acc[8];
#pragma unroll
    for (int j = 0; j < 8; j++) {
        acc[j] = v[0][j] * inv[0];
#pragma unroll
        for (int h = 1; h < NH; h++) acc[j] += v[h][j] * inv[h];
    }

    union { float4 f; __nv_bfloat162 hh[4]; } o;
#pragma unroll
    for (int j = 0; j < 4; j++)
        o.hh[j] = __floats2bfloat162_rn(acc[2 * j], acc[2 * j + 1]);
    *(float4*)(Bm + (long)bi * NL + tid * 8) = o.f;
}

// ---------------------------------------------------------------------------
// prepasses
__global__ void cvt_bf16_kernel(const float* __restrict__ in,
                                __nv_bfloat16* __restrict__ out, long n)
{
    const long i = ((long)blockIdx.x * blockDim.x + threadIdx.x) * 4;
    if (i < n) {
        float4 v = *(const float4*)(in + i);
        union { uint2 u; __nv_bfloat162 h[2]; } p;
        p.h[0] = __floats2bfloat162_rn(v.x, v.y);
        p.h[1] = __floats2bfloat162_rn(v.z, v.w);
        *(uint2*)(out + i) = p.u;
    }
}

__global__ void transpose_cvt_kernel(const float* __restrict__ in,
                                     __nv_bfloat16* __restrict__ outT,
                                     int R, int Cn)
{
    __shared__ float t[32][33];
    in   += (size_t)blockIdx.z * R * Cn;
    outT += (size_t)blockIdx.z * R * Cn;
    const int r0 = blockIdx.y * 32, c0 = blockIdx.x * 32;
    const int x = threadIdx.x, y = threadIdx.y;
#pragma unroll
    for (int i = 0; i < 32; i += 8)
        t[y + i][x] = in[(long)(r0 + y + i) * Cn + c0 + x];
    __syncthreads();
#pragma unroll
    for (int i = 0; i < 32; i += 8)
        outT[(long)(c0 + y + i) * R + r0 + x] = __float2bfloat16_rn(t[x][y + i]);
}

// ---------------------------------------------------------------------------
typedef CUresult (*encode_fn_t)(
    CUtensorMap*, CUtensorMapDataType, cuuint32_t, void*,
    const cuuint64_t*, const cuuint64_t*, const cuuint32_t*, const cuuint32_t*,
    CUtensorMapInterleave, CUtensorMapSwizzle, CUtensorMapL2promotion,
    CUtensorMapFloatOOBfill);

static void make_map(encode_fn_t enc, CUtensorMap* m, void* ptr, long rows, long cols)
{
    cuuint64_t dims[2]    = {(cuuint64_t)cols, (cuuint64_t)rows};
    cuuint64_t strides[1] = {(cuuint64_t)cols * 2};
    cuuint32_t box[2]     = {64u, 128u};
    cuuint32_t es[2]      = {1u, 1u};
    enc(m, CU_TENSOR_MAP_DATA_TYPE_BFLOAT16, 2, ptr, dims, strides, box, es,
        CU_TENSOR_MAP_INTERLEAVE_NONE, CU_TENSOR_MAP_SWIZZLE_128B,
        CU_TENSOR_MAP_L2_PROMOTION_L2_128B, CU_TENSOR_MAP_FLOAT_OOB_FILL_NONE);
}

extern "C" void kernel_launch(void* const* d_in, const int* in_sizes, int n_in,
                              void* d_out, int out_size)
{
    (void)in_sizes; (void)n_in; (void)out_size;
    const float* x   = (const float*)d_in[0];
    const float* w   = (const float*)d_in[1];
    const float* bia = (const float*)d_in[2];
    const float* Wg  = (const float*)d_in[3];
    const float* Bg  = (const float*)d_in[4];
    float* out = (float*)d_out;

    __nv_bfloat16 *xb, *wb, *WgTb, *QKb, *Bmb, *yT;
    __half* S;
    cudaGetSymbolAddress((void**)&xb,   g_xb);
    cudaGetSymbolAddress((void**)&wb,   g_wb);
    cudaGetSymbolAddress((void**)&WgTb, g_WgTb);
    cudaGetSymbolAddress((void**)&QKb,  g_QKb);
    cudaGetSymbolAddress((void**)&S,    g_S);
    cudaGetSymbolAddress((void**)&Bmb,  g_Bmb);
    cudaGetSymbolAddress((void**)&yT,   g_yT);

    encode_fn_t enc = nullptr;
    {
        void* p = nullptr;
        cudaDriverEntryPointQueryResult st;
        cudaGetDriverEntryPoint("cuTensorMapEncodeTiled", &p, cudaEnableDefault, &st);
        enc = (encode_fn_t)p;
    }

    CUtensorMap m_xb, m_wb, m_WgTb, m_QKb, m_Bmb, m_yT;
    make_map(enc, &m_xb,   xb,   (long)NB * NL, NE);
    make_map(enc, &m_wb,   wb,   2 * NE,        NE);
    make_map(enc, &m_WgTb, WgTb, NE,            NE);
    make_map(enc, &m_QKb,  QKb,  (long)NB * NL, 2 * NE);
    make_map(enc, &m_Bmb,  Bmb,  (long)NB * NL, NL);
    make_map(enc, &m_yT,   yT,   (long)NB * NE, NL);

    cudaFuncSetAttribute((const void*)bgemm_qkyt,
                         cudaFuncAttributeMaxDynamicSharedMemorySize, GEMM_SMEM);
    cudaFuncSetAttribute((const void*)bgemm<__half, false>,
                         cudaFuncAttributeMaxDynamicSharedMemorySize, GEMM_SMEM);
    cudaFuncSetAttribute((const void*)bgemm<float, true>,
                         cudaFuncAttributeMaxDynamicSharedMemorySize, GEMM_SMEM);

    // 0) bf16 operand prep
    {
        const long nx = (long)NB * NL * NE;
        cvt_bf16_kernel<<<(int)(nx / 4 / 256), 256>>>(x, xb, nx);
        const long nw = (long)2 * NE * NE;
        cvt_bf16_kernel<<<(int)((nw / 4 + 255) / 256), 256>>>(w, wb, nw);
        transpose_cvt_kernel<<<dim3(NE / 32, NE / 32, 1), dim3(32, 8)>>>(Wg, WgTb, NE, NE);
    }

    // 1+2) merged: QK = xb @ wb^T + bias  AND  yT[b] = WgT @ x[b]^T
    bgemm_qkyt<<<768, 256, GEMM_SMEM>>>(m_xb, m_wb, m_WgTb, QKb, yT, bia);

    // 3) S[b*4+h] = 0.125 * q_h @ k_h^T  (raw scores, fp16)  [2048x2048]x32, nk=1
    bgemm<__half, false><<<dim3(16, 16, NB * NH), 256, GEMM_SMEM>>>(
        m_QKb, m_QKb,
        NL, ND, 0,   NL, ND, NE,
        S, NL, (long)NL * NL,
        NH, 1, 0.125f, nullptr);

    // 4) Bm[b,i,:] = mean_h softmax(S[b,h,i,:])
    pmean_kernel<<<NB * NL, 256>>>(S, Bmb);

    // 5) out[b] = Bm[b] @ yT[b]^T + Bg   [2048 x 256] x8, K=2048 (nk=32)
    bgemm<float, true><<<dim3(2, 16, NB), 256, GEMM_SMEM>>>(
        m_Bmb, m_yT,
        NL, 0, 0,   NE, 0, 0,
        out, NE, (long)NL * NE,
        1, NL / 64, 1.f, Bg);
}

// round 13
// speedup vs baseline: 2.1373x; 1.0423x over previous
#include <cuda_runtime.h>
#include <cuda.h>
#include <cuda_bf16.h>
#include <cuda_fp16.h>
#include <cstdint>

#define NB 8
#define NL 2048
#define NE 256
#define NH 4
#define ND 64

// ---------------- scratch (device globals; no allocation allowed) -----------
__device__ __nv_bfloat16 g_xb  [(size_t)NB * NL * NE];        // bf16 x
__device__ __nv_bfloat16 g_wb  [(size_t)2 * NE * NE];         // bf16 w[0:512]
__device__ __nv_bfloat16 g_WgTb[(size_t)NE * NE];             // bf16 Wg^T
__device__ __nv_bfloat16 g_QKb [(size_t)NB * NL * 2 * NE];    // [16384, 512]
__device__ __half        g_S   [(size_t)NB * NH * NL * NL];   // raw scores fp16
__device__ __nv_bfloat16 g_Bmb [(size_t)NB * NL * NL];        // head-mean probs
__device__ __nv_bfloat16 g_yT  [(size_t)NB * NE * NL];        // (x @ Wg)^T per b

// ------------------------------- helpers ------------------------------------
__device__ __forceinline__ uint32_t smem_u32(const void* p) {
    uint32_t a;
    asm("{ .reg .u64 t; cvta.to.shared.u64 t, %1; cvt.u32.u64 %0, t; }"
        : "=r"(a) : "l"(p));
    return a;
}

#define MBARRIER_INIT(addr, cnt) \
    asm volatile("mbarrier.init.shared.b64 [%0], %1;" :: "r"(addr), "r"(cnt) : "memory")

#define MBARRIER_EXPECT_TX(addr, bytes) \
    asm volatile("mbarrier.arrive.expect_tx.shared.b64 _, [%0], %1;" \
                 :: "r"(addr), "r"(bytes) : "memory")

#define MBARRIER_WAIT_PARITY(addr, par) do {                                   \
    uint32_t _m = (addr), _p = (par), _d;                                      \
    asm volatile("{\n\t.reg .pred p;\n\t"                                      \
        "mbarrier.try_wait.parity.acquire.cta.shared::cta.b64 p, [%1], %2;\n\t"\
        "selp.b32 %0, 1, 0, p;\n\t}"                                           \
        : "=r"(_d) : "r"(_m), "r"(_p) : "memory");                             \
    if (!_d) {                                                                 \
        asm volatile("{\n\t.reg .pred P1;\n\t"                                 \
        "WL_%=:\n\t"                                                           \
        "mbarrier.try_wait.parity.acquire.cta.shared::cta.b64 P1, [%0], %1, 0x989680;\n\t" \
        "@P1 bra.uni WD_%=;\n\t"                                               \
        "bra.uni WL_%=;\n\t"                                                   \
        "WD_%=:\n\t}" :: "r"(_m), "r"(_p) : "memory");                         \
    }                                                                          \
} while (0)

#define TMA_LOAD_2D(saddr, tmap, cx, cy, mbar)                                 \
    asm volatile("cp.async.bulk.tensor.2d.shared::cta.global.tile.mbarrier::complete_tx::bytes " \
        "[%0], [%1, {%2, %3}], [%4];"                                          \
        :: "r"((uint32_t)(saddr)), "l"(tmap), "r"((int)(cx)), "r"((int)(cy)),  \
           "r"((uint32_t)(mbar)) : "memory")

#define FENCE_ASYNC_SHARED() asm volatile("fence.proxy.async.shared::cta;" ::: "memory")

#define MMA_BF16(d, a, b)                                                      \
    asm volatile("mma.sync.aligned.m16n8k16.row.col.f32.bf16.bf16.f32 "       \
        "{%0,%1,%2,%3}, {%4,%5,%6,%7}, {%8,%9}, {%0,%1,%2,%3};"                \
        : "+f"((d)[0]), "+f"((d)[1]), "+f"((d)[2]), "+f"((d)[3])               \
        : "r"((a)[0]), "r"((a)[1]), "r"((a)[2]), "r"((a)[3]),                  \
          "r"((b)[0]), "r"((b)[1]))

#define LDSM_X4(r0, r1, r2, r3, addr)                                          \
    asm volatile("ldmatrix.sync.aligned.m8n8.x4.shared.b16 {%0,%1,%2,%3}, [%4];" \
        : "=r"(r0), "=r"(r1), "=r"(r2), "=r"(r3) : "r"(addr))

__device__ __forceinline__ void store2(float* p, float a, float b) {
    *(float2*)p = make_float2(a, b);
}
__device__ __forceinline__ void store2(__nv_bfloat16* p, float a, float b) {
    *(__nv_bfloat162*)p = __floats2bfloat162_rn(a, b);
}
__device__ __forceinline__ void store2(__half* p, float a, float b) {
    *(__half2*)p = __floats2half2_rn(a, b);
}

#define STAGES     3
#define STG_BYTES  32768          // A 16KB + B 16KB, dense SW128 tiles
#define GEMM_SMEM  (STAGES * STG_BYTES + 1024 + 64)
// scores kernel: 2 stages + dedicated fp16 bounce (128 x 136)
#define SC_STAGES  2
#define SC_BOUNCE  (128 * 136 * 2)
#define SC_SMEM    (SC_STAGES * STG_BYTES + SC_BOUNCE + 1024 + 64)

struct Frag { float acc[4][4][4]; };

// one k16 x (4x4) fragment compute step from SW128 tiles
__device__ __forceinline__ void mma_step(
    uint32_t sA, uint32_t sB, int j,
    uint32_t aRow, uint32_t aCol0, uint32_t bRow, uint32_t bCol0, uint32_t xorv,
    Frag& F)
{
    uint32_t af[4][4], bf[4][2];
    const uint32_t ac = (aCol0 + j * 32) ^ xorv;
    const uint32_t bc = (bCol0 + j * 32) ^ xorv;
#pragma unroll
    for (int mt = 0; mt < 4; mt++)
        LDSM_X4(af[mt][0], af[mt][1], af[mt][2], af[mt][3],
                sA + aRow + mt * 2048 + ac);
#pragma unroll
    for (int p = 0; p < 2; p++)
        LDSM_X4(bf[2 * p][0], bf[2 * p][1], bf[2 * p + 1][0], bf[2 * p + 1][1],
                sB + bRow + p * 2048 + bc);
#pragma unroll
    for (int mt = 0; mt < 4; mt++)
#pragma unroll
        for (int nt = 0; nt < 4; nt++)
            MMA_BF16(F.acc[mt][nt], af[mt], bf[nt]);
}

__device__ __forceinline__ void gemm_mainloop(
    uint32_t sal, uint32_t mbb, int tid,
    const CUtensorMap* pA, const CUtensorMap* pB,
    int ary, int acx, int bry, int bcx, int nk,
    uint32_t aRow, uint32_t aCol0, uint32_t bRow, uint32_t bCol0, uint32_t xorv,
    Frag& F)
{
#pragma unroll
    for (int m = 0; m < 4; m++)
#pragma unroll
        for (int n = 0; n < 4; n++)
#pragma unroll
            for (int c = 0; c < 4; c++) F.acc[m][n][c] = 0.f;

    auto issue = [&](int chunk) {
        const int s = chunk % STAGES;
        MBARRIER_EXPECT_TX(mbb + s * 8, (uint32_t)STG_BYTES);
        TMA_LOAD_2D(sal + s * STG_BYTES,         pA, acx + chunk * 64, ary, mbb + s * 8);
        TMA_LOAD_2D(sal + s * STG_BYTES + 16384, pB, bcx + chunk * 64, bry, mbb + s * 8);
    };

    if (tid == 0) {
        issue(0);
        if (nk > 1) issue(1);
    }

    for (int i = 0; i < nk; i++) {
        const int s  = i % STAGES;
        const int ph = (i / STAGES) & 1;

        __syncthreads();
        if (tid == 0 && i + 2 < nk) issue(i + 2);
        MBARRIER_WAIT_PARITY(mbb + s * 8, ph);

        const uint32_t sA = sal + s * STG_BYTES;
        const uint32_t sB = sA + 16384;
#pragma unroll
        for (int j = 0; j < 4; j++)
            mma_step(sA, sB, j, aRow, aCol0, bRow, bCol0, xorv, F);
    }
}

// 16-bit-output epilogue: smem bounce -> coalesced 16B stores
template <typename OutT>
__device__ __forceinline__ void epilogue16(
    char* bounce, int tid, int wr, int wc, int g, int tg,
    OutT* Cz, int ldc, long crow0, int ccol0,
    float alpha, const float* bias, const Frag& F)
{
    OutT* Sb = (OutT*)bounce;            // 128 x 136 halfword
#pragma unroll
    for (int mt = 0; mt < 4; mt++) {
#pragma unroll
        for (int nt = 0; nt < 4; nt++) {
            const int r = wr + mt * 16 + g;
            const int c = wc + nt * 8 + tg * 2;
            float b0 = 0.f, b1 = 0.f;
            if (bias) { b0 = bias[ccol0 + c]; b1 = bias[ccol0 + c + 1]; }
            store2(Sb + (long)r * 136 + c,
                   F.acc[mt][nt][0] * alpha + b0, F.acc[mt][nt][1] * alpha + b1);
            store2(Sb + (long)(r + 8) * 136 + c,
                   F.acc[mt][nt][2] * alpha + b0, F.acc[mt][nt][3] * alpha + b1);
        }
    }
    __syncthreads();
#pragma unroll
    for (int it = 0; it < 8; it++) {
        const int idx = it * 256 + tid;
        const int row = idx >> 4;
        const int c16 = idx & 15;
        float4 v = *(float4*)(Sb + (long)row * 136 + c16 * 8);
        *(float4*)(Cz + (crow0 + row) * ldc + ccol0 + c16 * 8) = v;
    }
}

// ------------------------- generic batched GEMM ------------------------------
template <typename OutT, bool HAS_BIAS>
__global__ __launch_bounds__(256, 2)
void bgemm(const __grid_constant__ CUtensorMap tmA,
           const __grid_constant__ CUtensorMap tmB,
           int a_zo_row, int a_zi_col, int a_col_base,
           int b_zo_row, int b_zi_col, int b_col_base,
           OutT* __restrict__ C, int ldc, long sC,
           int inner, int nk, float alpha, const float* __restrict__ bias)
{
    extern __shared__ char smem[];
    const uint32_t sb0 = smem_u32(smem);
    const uint32_t sal = (sb0 + 1023) & ~1023u;
    const uint32_t mbb = sal + STAGES * STG_BYTES;

    const int tid    = threadIdx.x;
    const int warpId = tid >> 5;
    const int lane   = tid & 31;
    const int g  = lane >> 2;
    const int tg = lane & 3;
    const int wr = (warpId & 1) * 64;
    const int wc = (warpId >> 1) * 32;

    const int z  = blockIdx.z;
    const int zo = z / inner;
    const int zi = z - zo * inner;

    const int ary = zo * a_zo_row + blockIdx.y * 128;
    const int acx = a_col_base + zi * a_zi_col;
    const int bry = zo * b_zo_row + blockIdx.x * 128;
    const int bcx = b_col_base + zi * b_zi_col;

    if (tid == 0) {
#pragma unroll
        for (int s = 0; s < STAGES; s++) MBARRIER_INIT(mbb + s * 8, 1);
        FENCE_ASYNC_SHARED();
    }
    __syncthreads();

    const uint32_t xorv  = (uint32_t)((lane & 7) << 4);
    const uint32_t aRow  = (uint32_t)(wr + (lane & 15)) * 128;
    const uint32_t aCol0 = (uint32_t)((lane >> 4) * 16);
    const uint32_t bRow  = (uint32_t)(wc + (lane & 7) + ((lane >> 4) << 3)) * 128;
    const uint32_t bCol0 = (uint32_t)(((lane >> 3) & 1) * 16);

    Frag F;
    gemm_mainloop(sal, mbb, tid, &tmA, &tmB, ary, acx, bry, bcx, nk,
                  aRow, aCol0, bRow, bCol0, xorv, F);

    __syncthreads();
    char* bounce = smem + (sal - sb0);
    OutT* Cz = C + (long)z * sC;
    const long crow0 = (long)blockIdx.y * 128;
    const int  ccol0 = blockIdx.x * 128;
    const float* bp = HAS_BIAS ? bias : nullptr;

    if (sizeof(OutT) == 2) {
        epilogue16(bounce, tid, wr, wc, g, tg, Cz, ldc, crow0, ccol0, alpha, bp, F);
    } else {
        float* Sb = (float*)bounce;      // 128 x 132 fp32
#pragma unroll
        for (int mt = 0; mt < 4; mt++) {
#pragma unroll
            for (int nt = 0; nt < 4; nt++) {
                const int r = wr + mt * 16 + g;
                const int c = wc + nt * 8 + tg * 2;
                float b0 = 0.f, b1 = 0.f;
                if (HAS_BIAS) { b0 = bias[ccol0 + c]; b1 = bias[ccol0 + c + 1]; }
                *(float2*)(Sb + (long)r * 132 + c) =
                    make_float2(F.acc[mt][nt][0] * alpha + b0, F.acc[mt][nt][1] * alpha + b1);
                *(float2*)(Sb + (long)(r + 8) * 132 + c) =
                    make_float2(F.acc[mt][nt][2] * alpha + b0, F.acc[mt][nt][3] * alpha + b1);
            }
        }
        __syncthreads();
#pragma unroll
        for (int it = 0; it < 16; it++) {
            const int idx = it * 256 + tid;
            const int row = idx >> 5;
            const int c4  = idx & 31;
            float4 v = *(float4*)(Sb + (long)row * 132 + c4 * 4);
            *(float4*)((float*)Cz + (crow0 + row) * ldc + ccol0 + c4 * 4) = v;
        }
    }
}

// ------------- merged QK + yT GEMM (both nk=4, bf16 out) --------------------
__global__ __launch_bounds__(256, 2)
void bgemm_qkyt(const __grid_constant__ CUtensorMap tmXb,
                const __grid_constant__ CUtensorMap tmWb,
                const __grid_constant__ CUtensorMap tmWgT,
                __nv_bfloat16* __restrict__ QKb,
                __nv_bfloat16* __restrict__ yT,
                const float* __restrict__ bia)
{
    extern __shared__ char smem[];
    const uint32_t sb0 = smem_u32(smem);
    const uint32_t sal = (sb0 + 1023) & ~1023u;
    const uint32_t mbb = sal + STAGES * STG_BYTES;

    const int tid    = threadIdx.x;
    const int warpId = tid >> 5;
    const int lane   = tid & 31;
    const int g  = lane >> 2;
    const int tg = lane & 3;
    const int wr = (warpId & 1) * 64;
    const int wc = (warpId >> 1) * 32;

    const int id = blockIdx.x;
    const bool isQK = (id < 512);
    int xt, yt, zb;
    if (isQK) { xt = id & 3;  yt = id >> 2;        zb = 0; }
    else      { int t = id - 512; xt = t & 15; yt = (t >> 4) & 1; zb = t >> 5; }

    const CUtensorMap* pA = isQK ? &tmXb : &tmWgT;
    const CUtensorMap* pB = isQK ? &tmWb : &tmXb;
    const int ary = yt * 128;
    const int bry = (isQK ? 0 : zb * NL) + xt * 128;

    __nv_bfloat16* Cz = isQK ? QKb : (yT + (long)zb * NE * NL);
    const int   ldc   = isQK ? (2 * NE) : NL;
    const float* bias = isQK ? bia : nullptr;

    if (tid == 0) {
#pragma unroll
        for (int s = 0; s < STAGES; s++) MBARRIER_INIT(mbb + s * 8, 1);
        FENCE_ASYNC_SHARED();
    }
    __syncthreads();

    const uint32_t xorv  = (uint32_t)((lane & 7) << 4);
    const uint32_t aRow  = (uint32_t)(wr + (lane & 15)) * 128;
    const uint32_t aCol0 = (uint32_t)((lane >> 4) * 16);
    const uint32_t bRow  = (uint32_t)(wc + (lane & 7) + ((lane >> 4) << 3)) * 128;
    const uint32_t bCol0 = (uint32_t)(((lane >> 3) & 1) * 16);

    Frag F;
    gemm_mainloop(sal, mbb, tid, pA, pB, ary, 0, bry, 0, NE / 64,
                  aRow, aCol0, bRow, bCol0, xorv, F);

    __syncthreads();
    char* bounce = smem + (sal - sb0);
    epilogue16(bounce, tid, wr, wc, g, tg, Cz, ldc,
               (long)yt * 128, xt * 128, 1.f, bias, F);
}

// ------------------ scores GEMM: heads-as-chunks (nk=4) ----------------------
// grid (16 j-tiles, 16 i-tiles, NB). Per chunk h: S[b,h] tile = 0.125*q_h@k_h^T.
// 2-stage pipeline + dedicated bounce; per-chunk epilogue overlaps next TMA.
__global__ __launch_bounds__(256, 2)
void bgemm_scores(const __grid_constant__ CUtensorMap tmQK,
                  __half* __restrict__ S)
{
    extern __shared__ char smem[];
    const uint32_t sb0 = smem_u32(smem);
    const uint32_t sal = (sb0 + 1023) & ~1023u;
    const uint32_t bnc = sal + SC_STAGES * STG_BYTES;
    const uint32_t mbb = bnc + SC_BOUNCE;
    char* bounce = smem + (bnc - sb0);

    const int tid    = threadIdx.x;
    const int warpId = tid >> 5;
    const int lane   = tid & 31;
    const int g  = lane >> 2;
    const int tg = lane & 3;
    const int wr = (warpId & 1) * 64;
    const int wc = (warpId >> 1) * 32;

    const int b  = blockIdx.z;
    const int i0 = blockIdx.y * 128;
    const int j0 = blockIdx.x * 128;
    const int ary = b * NL + i0;
    const int bry = b * NL + j0;

    if (tid == 0) {
#pragma unroll
        for (int s = 0; s < SC_STAGES; s++) MBARRIER_INIT(mbb + s * 8, 1);
        FENCE_ASYNC_SHARED();
    }
    __syncthreads();

    auto issue = [&](int h) {
        const int s = h & 1;
        MBARRIER_EXPECT_TX(mbb + s * 8, (uint32_t)STG_BYTES);
        TMA_LOAD_2D(sal + s * STG_BYTES,         &tmQK, h * 64,       ary, mbb + s * 8);
        TMA_LOAD_2D(sal + s * STG_BYTES + 16384, &tmQK, 256 + h * 64, bry, mbb + s * 8);
    };

    if (tid == 0) { issue(0); issue(1); }

    const uint32_t xorv  = (uint32_t)((lane & 7) << 4);
    const uint32_t aRow  = (uint32_t)(wr + (lane & 15)) * 128;
    const uint32_t aCol0 = (uint32_t)((lane >> 4) * 16);
    const uint32_t bRow  = (uint32_t)(wc + (lane & 7) + ((lane >> 4) << 3)) * 128;
    const uint32_t bCol0 = (uint32_t)(((lane >> 3) & 1) * 16);

    for (int h = 0; h < NH; h++) {
        const int s  = h & 1;
        const int ph = (h >> 1) & 1;
        MBARRIER_WAIT_PARITY(mbb + s * 8, ph);

        Frag F;
#pragma unroll
        for (int m = 0; m < 4; m++)
#pragma unroll
            for (int n = 0; n < 4; n++)
#pragma unroll
                for (int c = 0; c < 4; c++) F.acc[m][n][c] = 0.f;

        const uint32_t sA = sal + s * STG_BYTES;
        const uint32_t sB = sA + 16384;
#pragma unroll
        for (int j = 0; j < 4; j++)
            mma_step(sA, sB, j, aRow, aCol0, bRow, bCol0, xorv, F);

        __syncthreads();                 // all warps done reading stage s
        if (tid == 0 && h + 2 < NH) issue(h + 2);

        // per-chunk epilogue into dedicated bounce (overlaps stage refill)
        __half* Cz = S + ((long)(b * NH + h) * NL + i0) * NL;
        epilogue16(bounce, tid, wr, wc, g, tg, Cz, NL,
                   0L, j0, 0.125f, (const float*)nullptr, F);
        __syncthreads();                 // bounce reusable next chunk
    }
}

// ---------------------------------------------------------------------------
// head-mean softmax from raw fp16 scores; streaming reads.
__global__ __launch_bounds__(256)
void pmean_kernel(const __half* __restrict__ S, __nv_bfloat16* __restrict__ Bm)
{
    __shared__ float red[8][4];
    const int bi   = blockIdx.x;
    const int b    = bi >> 11;
    const int i    = bi & 2047;
    const int tid  = threadIdx.x;
    const int wid  = tid >> 5;
    const int lane = tid & 31;

    const __half* base = S + ((long)b * NH * NL + i) * NL + tid * 8;

    union F4H { float4 f; __half2 hh[4]; } u[NH];
#pragma unroll
    for (int h = 0; h < NH; h++)
        u[h].f = __ldcs((const float4*)(base + (long)h * NL * NL));

    float v[NH][8], s[NH];
#pragma unroll
    for (int h = 0; h < NH; h++) {
        float sum = 0.f;
#pragma unroll
        for (int j = 0; j < 4; j++) {
            float2 p = __half22float2(u[h].hh[j]);
            float e0 = __expf(p.x), e1 = __expf(p.y);
            v[h][2 * j] = e0; v[h][2 * j + 1] = e1;
            sum += e0 + e1;
        }
#pragma unroll
        for (int o = 16; o; o >>= 1)
            sum += __shfl_xor_sync(0xffffffffu, sum, o);
        s[h] = sum;
    }
    if (lane < 4) red[wid][lane] = s[lane];
    __syncthreads();

    float inv[NH];
#pragma unroll
    for (int h = 0; h < NH; h++) {
        float st = red[0][h];
#pragma unroll
        for (int w = 1; w < 8; w++) st += red[w][h];
        inv[h] = 0.25f / st;
    }

    float acc[8];
#pragma unroll
    for (int j = 0; j < 8; j++) {
        acc[j] = v[0][j] * inv[0];
#pragma unroll
        for (int h = 1; h < NH; h++) acc[j] += v[h][j] * inv[h];
    }

    union { float4 f; __nv_bfloat162 hh[4]; } o;
#pragma unroll
    for (int j = 0; j < 4; j++)
        o.hh[j] = __floats2bfloat162_rn(acc[2 * j], acc[2 * j + 1]);
    *(float4*)(Bm + (long)bi * NL + tid * 8) = o.f;
}

// ---------------------------------------------------------------------------
// prepasses
__global__ void cvt_bf16_kernel(const float* __restrict__ in,
                                __nv_bfloat16* __restrict__ out, long n)
{
    const long i = ((long)blockIdx.x * blockDim.x + threadIdx.x) * 4;
    if (i < n) {
        float4 v = *(const float4*)(in + i);
        union { uint2 u; __nv_bfloat162 h[2]; } p;
        p.h[0] = __floats2bfloat162_rn(v.x, v.y);
        p.h[1] = __floats2bfloat162_rn(v.z, v.w);
        *(uint2*)(out + i) = p.u;
    }
}

__global__ void transpose_cvt_kernel(const float* __restrict__ in,
                                     __nv_bfloat16* __restrict__ outT,
                                     int R, int Cn)
{
    __shared__ float t[32][33];
    in   += (size_t)blockIdx.z * R * Cn;
    outT += (size_t)blockIdx.z * R * Cn;
    const int r0 = blockIdx.y * 32, c0 = blockIdx.x * 32;
    const int x = threadIdx.x, y = threadIdx.y;
#pragma unroll
    for (int i = 0; i < 32; i += 8)
        t[y + i][x] = in[(long)(r0 + y + i) * Cn + c0 + x];
    __syncthreads();
#pragma unroll
    for (int i = 0; i < 32; i += 8)
        outT[(long)(c0 + y + i) * R + r0 + x] = __float2bfloat16_rn(t[x][y + i]);
}

// ---------------------------------------------------------------------------
typedef CUresult (*encode_fn_t)(
    CUtensorMap*, CUtensorMapDataType, cuuint32_t, void*,
    const cuuint64_t*, const cuuint64_t*, const cuuint32_t*, const cuuint32_t*,
    CUtensorMapInterleave, CUtensorMapSwizzle, CUtensorMapL2promotion,
    CUtensorMapFloatOOBfill);

static void make_map(encode_fn_t enc, CUtensorMap* m, void* ptr, long rows, long cols)
{
    cuuint64_t dims[2]    = {(cuuint64_t)cols, (cuuint64_t)rows};
    cuuint64_t strides[1] = {(cuuint64_t)cols * 2};
    cuuint32_t box[2]     = {64u, 128u};
    cuuint32_t es[2]      = {1u, 1u};
    enc(m, CU_TENSOR_MAP_DATA_TYPE_BFLOAT16, 2, ptr, dims, strides, box, es,
        CU_TENSOR_MAP_INTERLEAVE_NONE, CU_TENSOR_MAP_SWIZZLE_128B,
        CU_TENSOR_MAP_L2_PROMOTION_L2_128B, CU_TENSOR_MAP_FLOAT_OOB_FILL_NONE);
}

extern "C" void kernel_launch(void* const* d_in, const int* in_sizes, int n_in,
                              void* d_out, int out_size)
{
    (void)in_sizes; (void)n_in; (void)out_size;
    const float* x   = (const float*)d_in[0];
    const float* w   = (const float*)d_in[1];
    const float* bia = (const float*)d_in[2];
    const float* Wg  = (const float*)d_in[3];
    const float* Bg  = (const float*)d_in[4];
    float* out = (float*)d_out;

    __nv_bfloat16 *xb, *wb, *WgTb, *QKb, *Bmb, *yT;
    __half* S;
    cudaGetSymbolAddress((void**)&xb,   g_xb);
    cudaGetSymbolAddress((void**)&wb,   g_wb);
    cudaGetSymbolAddress((void**)&WgTb, g_WgTb);
    cudaGetSymbolAddress((void**)&QKb,  g_QKb);
    cudaGetSymbolAddress((void**)&S,    g_S);
    cudaGetSymbolAddress((void**)&Bmb,  g_Bmb);
    cudaGetSymbolAddress((void**)&yT,   g_yT);

    encode_fn_t enc = nullptr;
    {
        void* p = nullptr;
        cudaDriverEntryPointQueryResult st;
        cudaGetDriverEntryPoint("cuTensorMapEncodeTiled", &p, cudaEnableDefault, &st);
        enc = (encode_fn_t)p;
    }

    CUtensorMap m_xb, m_wb, m_WgTb, m_QKb, m_Bmb, m_yT;
    make_map(enc, &m_xb,   xb,   (long)NB * NL, NE);
    make_map(enc, &m_wb,   wb,   2 * NE,        NE);
    make_map(enc, &m_WgTb, WgTb, NE,            NE);
    make_map(enc, &m_QKb,  QKb,  (long)NB * NL, 2 * NE);
    make_map(enc, &m_Bmb,  Bmb,  (long)NB * NL, NL);
    make_map(enc, &m_yT,   yT,   (long)NB * NE, NL);

    cudaFuncSetAttribute((const void*)bgemm_qkyt,
                         cudaFuncAttributeMaxDynamicSharedMemorySize, GEMM_SMEM);
    cudaFuncSetAttribute((const void*)bgemm_scores,
                         cudaFuncAttributeMaxDynamicSharedMemorySize, SC_SMEM);
    cudaFuncSetAttribute((const void*)bgemm<float, true>,
                         cudaFuncAttributeMaxDynamicSharedMemorySize, GEMM_SMEM);

    // 0) bf16 operand prep
    {
        const long nx = (long)NB * NL * NE;
        cvt_bf16_kernel<<<(int)(nx / 4 / 256), 256>>>(x, xb, nx);
        const long nw = (long)2 * NE * NE;
        cvt_bf16_kernel<<<(int)((nw / 4 + 255) / 256), 256>>>(w, wb, nw);
        transpose_cvt_kernel<<<dim3(NE / 32, NE / 32, 1), dim3(32, 8)>>>(Wg, WgTb, NE, NE);
    }

    // 1+2) merged: QK = xb @ wb^T + bias  AND  yT[b] = WgT @ x[b]^T
    bgemm_qkyt<<<768, 256, GEMM_SMEM>>>(m_xb, m_wb, m_WgTb, QKb, yT, bia);

    // 3) S: heads-as-chunks pipelined scores (fp16 raw, scaled 0.125)
    bgemm_scores<<<dim3(16, 16, NB), 256, SC_SMEM>>>(m_QKb, S);

    // 4) Bm[b,i,:] = mean_h softmax(S[b,h,i,:])
    pmean_kernel<<<NB * NL, 256>>>(S, Bmb);

    // 5) out[b] = Bm[b] @ yT[b]^T + Bg   [2048 x 256] x8, K=2048 (nk=32)
    bgemm<float, true><<<dim3(2, 16, NB), 256, GEMM_SMEM>>>(
        m_Bmb, m_yT,
        NL, 0, 0,   NE, 0, 0,
        out, NE, (long)NL * NE,
        1, NL / 64, 1.f, Bg);
}